// round 11
// baseline (speedup 1.0000x reference)
#include <cuda_runtime.h>
#include <cuda_bf16.h>
#include <cstdint>
#include <math.h>

#define BATCH 16
#define SEQ   512
#define NI    32
#define NHEAD 8
#define NH    512
#define NO    64
#define MROWS (BATCH*SEQ)      // 8192
#define VDIM  (NHEAD*NI)       // 256
#define EPSV  1e-5f
#define SLOPE 0.05f
#define NPART 64

// ---------------- scratch ----------------
__device__ float    g_En  [16*8*512];
__device__ uint32_t g_Xthi[(size_t)16*256*256], g_Xtlo[(size_t)16*256*256];
__device__ uint32_t g_Ghi [(size_t)16*512*256], g_Glo [(size_t)16*512*256];
__device__ uint32_t g_Vhi [(size_t)8192*128],   g_Vlo [(size_t)8192*128];
__device__ uint32_t g_W1hi[512*128], g_W1lo[512*128];
__device__ uint32_t g_W2hi[512*256], g_W2lo[512*256];
__device__ uint32_t g_W3hi[64*256],  g_W3lo[64*256];
__device__ uint32_t g_Axhi[(size_t)8192*256],   g_Axlo[(size_t)8192*256];
__device__ float g_Y1[(size_t)MROWS * NH];
__device__ float g_Y2[(size_t)MROWS * NH];
__device__ float g_Y3[(size_t)MROWS * NO];
__device__ float g_pS [NPART * NH];
__device__ float g_pS2[NPART * NH];
__device__ float g_scale[NH];
__device__ float g_shift[NH];

// ---------------- helpers ----------------
__device__ __forceinline__ void split_pair(float v0, float v1, uint32_t& hi, uint32_t& lo) {
    __nv_bfloat16 h0 = __float2bfloat16(v0);
    __nv_bfloat16 h1 = __float2bfloat16(v1);
    float r0 = v0 - __bfloat162float(h0);
    float r1 = v1 - __bfloat162float(h1);
    __nv_bfloat16 l0 = __float2bfloat16(r0);
    __nv_bfloat16 l1 = __float2bfloat16(r1);
    hi = ((uint32_t)__bfloat16_as_ushort(h1) << 16) | __bfloat16_as_ushort(h0);
    lo = ((uint32_t)__bfloat16_as_ushort(l1) << 16) | __bfloat16_as_ushort(l0);
}

__device__ __forceinline__ void mma_bf16(float* d, const uint32_t* a, const uint32_t* b) {
    asm volatile(
        "mma.sync.aligned.m16n8k16.row.col.f32.bf16.bf16.f32 "
        "{%0,%1,%2,%3}, {%4,%5,%6,%7}, {%8,%9}, {%0,%1,%2,%3};"
        : "+f"(d[0]), "+f"(d[1]), "+f"(d[2]), "+f"(d[3])
        : "r"(a[0]), "r"(a[1]), "r"(a[2]), "r"(a[3]), "r"(b[0]), "r"(b[1]));
}

__device__ __forceinline__ void ldsm4(uint32_t* r, uint32_t addr) {
    asm volatile("ldmatrix.sync.aligned.m8n8.x4.shared.b16 {%0,%1,%2,%3}, [%4];"
        : "=r"(r[0]), "=r"(r[1]), "=r"(r[2]), "=r"(r[3]) : "r"(addr));
}

__device__ __forceinline__ uint32_t smem_u32(const void* p) {
    uint32_t a;
    asm("{ .reg .u64 t; cvta.to.shared.u64 t, %1; cvt.u32.u64 %0, t; }" : "=r"(a) : "l"(p));
    return a;
}
__device__ __forceinline__ void cp_async16(uint32_t saddr, const void* gptr) {
    asm volatile("cp.async.cg.shared.global [%0], [%1], 16;" :: "r"(saddr), "l"(gptr));
}
#define CP_COMMIT() asm volatile("cp.async.commit_group;" ::: "memory")
#define CP_WAIT0()  asm volatile("cp.async.wait_group 0;" ::: "memory")

// ---------------- prep: En tables, Xt build, W splits ----------------
__global__ void __launch_bounds__(256) prep_kernel(
    const float* __restrict__ x, const float* __restrict__ Q,
    float* __restrict__ En,
    uint32_t* __restrict__ Xthi, uint32_t* __restrict__ Xtlo,
    const float* __restrict__ W1, uint32_t* __restrict__ W1hi, uint32_t* __restrict__ W1lo,
    const float* __restrict__ W2, uint32_t* __restrict__ W2hi, uint32_t* __restrict__ W2lo,
    const float* __restrict__ W3, uint32_t* __restrict__ W3hi, uint32_t* __restrict__ W3lo)
{
    const int blk = blockIdx.x;
    const int tid = threadIdx.x;

    if (blk >= 64) {
        int widx = blk - 64;
        const float* src; uint32_t* hi; uint32_t* lo; int base;
        if (widx < 32)      { src = W1; hi = W1hi; lo = W1lo; base = widx * 2048; }
        else if (widx < 96) { src = W2; hi = W2hi; lo = W2lo; base = (widx - 32) * 2048; }
        else                { src = W3; hi = W3hi; lo = W3lo; base = (widx - 96) * 2048; }
        int p = base + tid;
        #pragma unroll
        for (int j = 0; j < 8; j++, p += 256) {
            float2 v = ((const float2*)src)[p];
            uint32_t h, l; split_pair(v.x, v.y, h, l);
            hi[p] = h; lo[p] = l;
        }
        return;
    }

    const int b = blk >> 2, chunk = blk & 3;

    __shared__ float sEm[8][128];
    __shared__ float sQ[8][4];
    __shared__ uint32_t shi[256][8], slo[256][8];

    if (tid < 8) {
        float a = Q[tid*3+0], bq = Q[tid*3+1], cq = Q[tid*3+2];
        sQ[tid][0] = a; sQ[tid][1] = bq; sQ[tid][2] = cq;
        sQ[tid][3] = a*a + bq*bq + cq*cq;
    }
    __syncthreads();

    if (tid < 128) {
        int m = chunk*128 + tid;
        const float* xp = x + ((size_t)b*512 + m)*32;
        float px = xp[0], py = xp[1], pz = xp[2];
        #pragma unroll
        for (int h = 0; h < 8; h++) {
            float dot = px*sQ[h][0] + py*sQ[h][1] + pz*sQ[h][2];
            float em = __expf(-2.f*dot);
            float en = __expf(2.f*dot - sQ[h][3]);
            sEm[h][tid] = em;
            En[((size_t)b*8 + h)*512 + m] = en;
        }
    }
    __syncthreads();

    const int c = tid, h = c >> 5, i = c & 31;
    for (int grp = 0; grp < 8; grp++) {
        #pragma unroll
        for (int j = 0; j < 8; j++) {
            int mloc = (grp*8 + j)*2;
            int m = chunk*128 + mloc;
            float v0 = sEm[h][mloc]   * x[((size_t)b*512 + m  )*32 + i];
            float v1 = sEm[h][mloc+1] * x[((size_t)b*512 + m+1)*32 + i];
            uint32_t hh, ll; split_pair(v0, v1, hh, ll);
            shi[c][j] = hh; slo[c][j] = ll;
        }
        __syncthreads();
        int cc = tid >> 3, j2 = tid & 7;
        #pragma unroll
        for (int rep = 0; rep < 8; rep++) {
            int ccc = cc + rep*32;
            size_t addr = ((size_t)b*256 + ccc)*256 + chunk*64 + grp*8 + j2;
            Xthi[addr] = shi[ccc][j2];
            Xtlo[addr] = slo[ccc][j2];
        }
        __syncthreads();
    }
}

// ---------------- buildG ----------------
__global__ void __launch_bounds__(256) buildG_kernel(
    const float* __restrict__ x, uint32_t* __restrict__ Ghi, uint32_t* __restrict__ Glo)
{
    const int b  = blockIdx.x >> 3, nt = blockIdx.x & 7;
    const int tid = threadIdx.x;
    const int n = tid & 63, mq = tid >> 6;

    __shared__ float pn3[64][5];
    __shared__ float pm3[128][4];

    if (tid < 64) {
        const float* xp = x + ((size_t)b*512 + nt*64 + tid)*32;
        pn3[tid][0] = xp[0]; pn3[tid][1] = xp[1]; pn3[tid][2] = xp[2];
    }

    for (int mc = 0; mc < 4; mc++) {
        __syncthreads();
        if (tid < 128) {
            const float* xp = x + ((size_t)b*512 + mc*128 + tid)*32;
            pm3[tid][0] = xp[0]; pm3[tid][1] = xp[1]; pm3[tid][2] = xp[2];
        }
        __syncthreads();
        float px = pn3[n][0], py = pn3[n][1], pz = pn3[n][2];
        uint32_t outh[16], outl[16];
        #pragma unroll
        for (int j = 0; j < 16; j++) {
            int ml = mq*32 + j*2;
            float dx0 = px - pm3[ml][0],   dy0 = py - pm3[ml][1],   dz0 = pz - pm3[ml][2];
            float dx1 = px - pm3[ml+1][0], dy1 = py - pm3[ml+1][1], dz1 = pz - pm3[ml+1][2];
            float e0 = __expf(-(dx0*dx0 + dy0*dy0 + dz0*dz0));
            float e1 = __expf(-(dx1*dx1 + dy1*dy1 + dz1*dz1));
            split_pair(e0, e1, outh[j], outl[j]);
        }
        size_t base = ((size_t)b*512 + nt*64 + n)*256 + mc*64 + mq*16;
        #pragma unroll
        for (int j4 = 0; j4 < 4; j4++) {
            ((uint4*)(Ghi + base))[j4] = make_uint4(outh[j4*4], outh[j4*4+1], outh[j4*4+2], outh[j4*4+3]);
            ((uint4*)(Glo + base))[j4] = make_uint4(outl[j4*4], outl[j4*4+1], outl[j4*4+2], outl[j4*4+3]);
        }
    }
}

// ================= GEMM machinery: TN=64, K32, 2-stage, ldsm, 3-pass MMA order =================
#define RSU 20
#define TN  64
#define NFRAG (TN/16)
#define ASZ (128*RSU)
#define BSZ (TN*RSU)

// shared compute body: preload all fragments, then 3 passes (hh, hl, lh)
#define COMPUTE_BODY(buf, bAh, bAl, bBh, bBl)                                         \
    _Pragma("unroll")                                                                  \
    for (int kk = 0; kk < 2; kk++) {                                                   \
        uint32_t ah[2][4], al[2][4];                                                   \
        _Pragma("unroll")                                                              \
        for (int mi = 0; mi < 2; mi++) {                                               \
            uint32_t off = (uint32_t)((buf)*ASZ + (wm + mi*16 + rowA)*RSU + kk*8 + colA) * 4; \
            ldsm4(ah[mi], (bAh) + off);                                                \
            ldsm4(al[mi], (bAl) + off);                                                \
        }                                                                              \
        uint32_t bh[NFRAG][2], bl[NFRAG][2];                                           \
        _Pragma("unroll")                                                              \
        for (int np = 0; np < NFRAG/2; np++) {                                         \
            uint32_t off = (uint32_t)((buf)*BSZ + (wn + np*16 + rowB)*RSU + kk*8 + colB) * 4; \
            uint32_t th[4], tl[4];                                                     \
            ldsm4(th, (bBh) + off);                                                    \
            ldsm4(tl, (bBl) + off);                                                    \
            bh[np*2][0] = th[0]; bh[np*2][1] = th[1];                                  \
            bh[np*2+1][0] = th[2]; bh[np*2+1][1] = th[3];                              \
            bl[np*2][0] = tl[0]; bl[np*2][1] = tl[1];                                  \
            bl[np*2+1][0] = tl[2]; bl[np*2+1][1] = tl[3];                              \
        }                                                                              \
        _Pragma("unroll")                                                              \
        for (int ni = 0; ni < NFRAG; ni++)                                             \
            _Pragma("unroll")                                                          \
            for (int mi = 0; mi < 2; mi++)                                             \
                mma_bf16(acc[mi][ni], ah[mi], bh[ni]);                                 \
        _Pragma("unroll")                                                              \
        for (int ni = 0; ni < NFRAG; ni++)                                             \
            _Pragma("unroll")                                                          \
            for (int mi = 0; mi < 2; mi++)                                             \
                mma_bf16(acc[mi][ni], ah[mi], bl[ni]);                                 \
        _Pragma("unroll")                                                              \
        for (int ni = 0; ni < NFRAG; ni++)                                             \
            _Pragma("unroll")                                                          \
            for (int mi = 0; mi < 2; mi++)                                             \
                mma_bf16(acc[mi][ni], al[mi], bh[ni]);                                 \
    }

// ---------------- vgemm: V = En .* (G @ Xt^T) - pos ----------------
__global__ void __launch_bounds__(256, 3) vgemm_kernel(
    const uint32_t* __restrict__ Ghi, const uint32_t* __restrict__ Glo,
    const uint32_t* __restrict__ Bhi_g, const uint32_t* __restrict__ Blo_g,
    const float* __restrict__ En, const float* __restrict__ x,
    uint32_t* __restrict__ Vhi, uint32_t* __restrict__ Vlo)
{
    constexpr int KE = 512, K2 = KE/2;
    extern __shared__ uint32_t smem_u[];
    const uint32_t sbase = smem_u32(smem_u);
    const uint32_t bAh = sbase;
    const uint32_t bAl = sbase + 2*ASZ*4;
    const uint32_t bBh = sbase + 4*ASZ*4;
    const uint32_t bBl = sbase + (4*ASZ + 2*BSZ)*4;

    const int tid = threadIdx.x, wid = tid >> 5, lane = tid & 31;
    const int wm = (wid >> 1) * 32, wn = (wid & 1) * (TN/2);
    const int l4 = lane >> 2, lk = lane & 3;
    const int rowA = lane & 15, colA = (lane >> 4) * 4;
    const int rowB = ((lane >> 4) & 1) * 8 + (lane & 7);
    const int colB = ((lane >> 3) & 1) * 4;
    const int b = blockIdx.z;
    const int m0 = blockIdx.y * 128, c0 = blockIdx.x * TN;

    const uint32_t* Ah_g = Ghi + (size_t)b*512*K2;
    const uint32_t* Al_g = Glo + (size_t)b*512*K2;
    const uint32_t* Bh_g = Bhi_g + (size_t)b*256*K2;
    const uint32_t* Bl_g = Blo_g + (size_t)b*256*K2;

    float acc[2][NFRAG][4];
    #pragma unroll
    for (int a = 0; a < 2; a++)
        #pragma unroll
        for (int q = 0; q < NFRAG; q++)
            { acc[a][q][0]=0.f; acc[a][q][1]=0.f; acc[a][q][2]=0.f; acc[a][q][3]=0.f; }

    auto issue = [&](int t) {
        int buf = t & 1;
        #pragma unroll
        for (int j = 0; j < 2; j++) {
            int lin = tid + j*256; int r = lin >> 2, q = lin & 3;
            uint32_t off = (uint32_t)(buf*ASZ + r*RSU + q*4) * 4;
            size_t ao = (size_t)(m0 + r)*K2 + t*16 + q*4;
            cp_async16(bAh + off, Ah_g + ao);
            cp_async16(bAl + off, Al_g + ao);
        }
        {
            int r = tid >> 2, q = tid & 3;
            uint32_t off = (uint32_t)(buf*BSZ + r*RSU + q*4) * 4;
            size_t bo = (size_t)(c0 + r)*K2 + t*16 + q*4;
            cp_async16(bBh + off, Bh_g + bo);
            cp_async16(bBl + off, Bl_g + bo);
        }
        CP_COMMIT();
    };

    const int T = KE / 32;
    issue(0);
    for (int t = 0; t < T; t++) {
        CP_WAIT0();
        __syncthreads();
        if (t + 1 < T) issue(t + 1);
        int buf = t & 1;
        COMPUTE_BODY(buf, bAh, bAl, bBh, bBl)
    }

    #pragma unroll
    for (int mi = 0; mi < 2; mi++) {
        #pragma unroll
        for (int ni = 0; ni < NFRAG; ni++) {
            int n0 = m0 + wm + mi*16 + l4;
            int cc = c0 + wn + ni*8 + lk*2;
            int h = cc >> 5, il = cc & 31;
            float en0 = En[((size_t)b*8 + h)*512 + n0];
            float en1 = En[((size_t)b*8 + h)*512 + n0 + 8];
            float v00 = acc[mi][ni][0]*en0, v01 = acc[mi][ni][1]*en0;
            float v10 = acc[mi][ni][2]*en1, v11 = acc[mi][ni][3]*en1;
            if (il < 3) {
                v00 -= x[((size_t)b*512 + n0  )*32 + il];
                v10 -= x[((size_t)b*512 + n0+8)*32 + il];
            }
            if (il + 1 < 3) {
                v01 -= x[((size_t)b*512 + n0  )*32 + il + 1];
                v11 -= x[((size_t)b*512 + n0+8)*32 + il + 1];
            }
            uint32_t h0, l0, h1, l1;
            split_pair(v00, v01, h0, l0);
            split_pair(v10, v11, h1, l1);
            size_t r0 = ((size_t)b*512 + n0)*128 + (cc >> 1);
            size_t r1 = ((size_t)b*512 + n0 + 8)*128 + (cc >> 1);
            Vhi[r0] = h0; Vlo[r0] = l0;
            Vhi[r1] = h1; Vlo[r1] = l1;
        }
    }
}

// ---------------- gemm_ps (bf16 pair, TN=64) + fused column stats ----------------
__global__ void __launch_bounds__(256, 3) gemm_ps_kernel(
    const uint32_t* __restrict__ Ah_g, const uint32_t* __restrict__ Al_g,
    const uint32_t* __restrict__ Bh_g, const uint32_t* __restrict__ Bl_g,
    const float* __restrict__ bias, float* __restrict__ Y,
    float* __restrict__ pS, float* __restrict__ pS2, int K, int C)
{
    extern __shared__ uint32_t smem_u[];
    const uint32_t sbase = smem_u32(smem_u);
    const uint32_t bAh = sbase;
    const uint32_t bAl = sbase + 2*ASZ*4;
    const uint32_t bBh = sbase + 4*ASZ*4;
    const uint32_t bBl = sbase + (4*ASZ + 2*BSZ)*4;

    const int tid = threadIdx.x, wid = tid >> 5, lane = tid & 31;
    const int wm = (wid >> 1) * 32, wn = (wid & 1) * (TN/2);
    const int mw = wid >> 1;
    const int l4 = lane >> 2, lk = lane & 3;
    const int rowA = lane & 15, colA = (lane >> 4) * 4;
    const int rowB = ((lane >> 4) & 1) * 8 + (lane & 7);
    const int colB = ((lane >> 3) & 1) * 4;
    const int m0 = blockIdx.y * 128, c0 = blockIdx.x * TN;
    const int K2 = K >> 1;

    float acc[2][NFRAG][4];
    #pragma unroll
    for (int a = 0; a < 2; a++)
        #pragma unroll
        for (int q = 0; q < NFRAG; q++)
            { acc[a][q][0]=0.f; acc[a][q][1]=0.f; acc[a][q][2]=0.f; acc[a][q][3]=0.f; }

    auto issue = [&](int t) {
        int buf = t & 1;
        #pragma unroll
        for (int j = 0; j < 2; j++) {
            int lin = tid + j*256; int r = lin >> 2, q = lin & 3;
            uint32_t off = (uint32_t)(buf*ASZ + r*RSU + q*4) * 4;
            size_t ao = (size_t)(m0 + r)*K2 + t*16 + q*4;
            cp_async16(bAh + off, Ah_g + ao);
            cp_async16(bAl + off, Al_g + ao);
        }
        {
            int r = tid >> 2, q = tid & 3;
            uint32_t off = (uint32_t)(buf*BSZ + r*RSU + q*4) * 4;
            size_t bo = (size_t)(c0 + r)*K2 + t*16 + q*4;
            cp_async16(bBh + off, Bh_g + bo);
            cp_async16(bBl + off, Bl_g + bo);
        }
        CP_COMMIT();
    };

    const int T = K / 32;
    issue(0);
    for (int t = 0; t < T; t++) {
        CP_WAIT0();
        __syncthreads();
        if (t + 1 < T) issue(t + 1);
        int buf = t & 1;
        COMPUTE_BODY(buf, bAh, bAl, bBh, bBl)
    }
    __syncthreads();   // smem reused for stats below

    float* sbufS  = (float*)smem_u;
    float* sbufS2 = sbufS + 4*TN;

    #pragma unroll
    for (int ni = 0; ni < NFRAG; ni++) {
        int col = c0 + wn + ni*8 + lk*2;
        float2 b2 = *(const float2*)(bias + col);
        float s0 = 0.f, s1 = 0.f, q0 = 0.f, q1 = 0.f;
        #pragma unroll
        for (int mi = 0; mi < 2; mi++) {
            int row = m0 + wm + mi*16 + l4;
            float e0 = acc[mi][ni][0] + b2.x;
            float e1 = acc[mi][ni][1] + b2.y;
            float e2 = acc[mi][ni][2] + b2.x;
            float e3 = acc[mi][ni][3] + b2.y;
            *(float2*)(Y + (size_t)row * C + col)       = make_float2(e0, e1);
            *(float2*)(Y + (size_t)(row + 8) * C + col) = make_float2(e2, e3);
            s0 += e0 + e2; s1 += e1 + e3;
            q0 += e0*e0 + e2*e2; q1 += e1*e1 + e3*e3;
        }
        #pragma unroll
        for (int off = 16; off >= 4; off >>= 1) {
            s0 += __shfl_down_sync(0xffffffffu, s0, off);
            s1 += __shfl_down_sync(0xffffffffu, s1, off);
            q0 += __shfl_down_sync(0xffffffffu, q0, off);
            q1 += __shfl_down_sync(0xffffffffu, q1, off);
        }
        if (lane < 4) {
            int cb = wn + ni*8 + lk*2;
            sbufS [mw*TN + cb]     = s0;
            sbufS [mw*TN + cb + 1] = s1;
            sbufS2[mw*TN + cb]     = q0;
            sbufS2[mw*TN + cb + 1] = q1;
        }
    }
    __syncthreads();
    if (tid < TN) {
        float s = sbufS [tid] + sbufS [TN + tid] + sbufS [2*TN + tid] + sbufS [3*TN + tid];
        float q = sbufS2[tid] + sbufS2[TN + tid] + sbufS2[2*TN + tid] + sbufS2[3*TN + tid];
        pS [blockIdx.y * C + c0 + tid] = s;
        pS2[blockIdx.y * C + c0 + tid] = q;
    }
}

// ---------------- stats_final ----------------
__global__ void __launch_bounds__(256) stats_final_kernel(
    const float* __restrict__ pS, const float* __restrict__ pS2,
    const float* __restrict__ g, const float* __restrict__ bt,
    int M, int C, float* __restrict__ scale, float* __restrict__ shift)
{
    const int c = blockIdx.x * 8 + (threadIdx.x >> 5);
    const int j = threadIdx.x & 31;
    float s  = pS [j * C + c] + pS [(j + 32) * C + c];
    float s2 = pS2[j * C + c] + pS2[(j + 32) * C + c];
    #pragma unroll
    for (int off = 16; off > 0; off >>= 1) {
        s  += __shfl_down_sync(0xffffffffu, s,  off);
        s2 += __shfl_down_sync(0xffffffffu, s2, off);
    }
    if (j == 0) {
        float invM = 1.f / (float)M;
        float mean = s * invM;
        float var  = fmaf(-mean, mean, s2 * invM);
        float inv  = rsqrtf(var + EPSV);
        float scv  = g[c] * inv;
        scale[c] = scv;
        shift[c] = fmaf(-mean, scv, bt[c]);
    }
}

// ---------------- bnconvert ----------------
__global__ void __launch_bounds__(256) bnconvert_kernel(
    const float* __restrict__ Y, const float* __restrict__ scale,
    const float* __restrict__ shift, uint32_t* __restrict__ hi, uint32_t* __restrict__ lo,
    int total4, int C4)
{
    int idx = blockIdx.x * blockDim.x + threadIdx.x;
    if (idx >= total4) return;
    int c4 = idx % C4;
    float4 y  = ((const float4*)Y)[idx];
    float4 sc = ((const float4*)scale)[c4];
    float4 sh = ((const float4*)shift)[c4];
    float v[4];
    v[0] = fmaf(y.x, sc.x, sh.x); v[1] = fmaf(y.y, sc.y, sh.y);
    v[2] = fmaf(y.z, sc.z, sh.z); v[3] = fmaf(y.w, sc.w, sh.w);
    #pragma unroll
    for (int q = 0; q < 4; q++) v[q] = v[q] > 0.f ? v[q] : v[q] * SLOPE;
    uint32_t h0, l0, h1, l1;
    split_pair(v[0], v[1], h0, l0);
    split_pair(v[2], v[3], h1, l1);
    ((uint2*)hi)[idx] = make_uint2(h0, h1);
    ((uint2*)lo)[idx] = make_uint2(l0, l1);
}

// ---------------- final BN apply ----------------
__global__ void __launch_bounds__(256) bnapply_kernel(
    const float* __restrict__ Y, const float* __restrict__ scale,
    const float* __restrict__ shift, float* __restrict__ out, int total4, int C4)
{
    int idx = blockIdx.x * blockDim.x + threadIdx.x;
    if (idx >= total4) return;
    int c4 = idx % C4;
    float4 y  = ((const float4*)Y)[idx];
    float4 sc = ((const float4*)scale)[c4];
    float4 sh = ((const float4*)shift)[c4];
    float4 o;
    o.x = fmaf(y.x, sc.x, sh.x);
    o.y = fmaf(y.y, sc.y, sh.y);
    o.z = fmaf(y.z, sc.z, sh.z);
    o.w = fmaf(y.w, sc.w, sh.w);
    ((float4*)out)[idx] = o;
}

// ---------------- host ----------------
extern "C" void kernel_launch(void* const* d_in, const int* in_sizes, int n_in,
                              void* d_out, int out_size)
{
    const float* x   = (const float*)d_in[0];
    const float* Q   = (const float*)d_in[1];
    const float* W1  = (const float*)d_in[2];
    const float* b1  = (const float*)d_in[3];
    const float* g1  = (const float*)d_in[4];
    const float* bt1 = (const float*)d_in[5];
    const float* W2  = (const float*)d_in[6];
    const float* b2  = (const float*)d_in[7];
    const float* g2  = (const float*)d_in[8];
    const float* bt2 = (const float*)d_in[9];
    const float* W3  = (const float*)d_in[10];
    const float* b3  = (const float*)d_in[11];
    const float* g3  = (const float*)d_in[12];
    const float* bt3 = (const float*)d_in[13];
    float* out = (float*)d_out;

    float *En, *Y1, *Y2, *Y3, *pS, *pS2, *scale, *shift;
    uint32_t *Xthi, *Xtlo, *Ghi, *Glo, *Vhi, *Vlo, *Axhi, *Axlo;
    uint32_t *W1hi, *W1lo, *W2hi, *W2lo, *W3hi, *W3lo;
    cudaGetSymbolAddress((void**)&En,   g_En);
    cudaGetSymbolAddress((void**)&Xthi, g_Xthi);  cudaGetSymbolAddress((void**)&Xtlo, g_Xtlo);
    cudaGetSymbolAddress((void**)&Ghi,  g_Ghi);   cudaGetSymbolAddress((void**)&Glo,  g_Glo);
    cudaGetSymbolAddress((void**)&Vhi,  g_Vhi);   cudaGetSymbolAddress((void**)&Vlo,  g_Vlo);
    cudaGetSymbolAddress((void**)&Axhi, g_Axhi);  cudaGetSymbolAddress((void**)&Axlo, g_Axlo);
    cudaGetSymbolAddress((void**)&W1hi, g_W1hi);  cudaGetSymbolAddress((void**)&W1lo, g_W1lo);
    cudaGetSymbolAddress((void**)&W2hi, g_W2hi);  cudaGetSymbolAddress((void**)&W2lo, g_W2lo);
    cudaGetSymbolAddress((void**)&W3hi, g_W3hi);  cudaGetSymbolAddress((void**)&W3lo, g_W3lo);
    cudaGetSymbolAddress((void**)&Y1, g_Y1);
    cudaGetSymbolAddress((void**)&Y2, g_Y2);
    cudaGetSymbolAddress((void**)&Y3, g_Y3);
    cudaGetSymbolAddress((void**)&pS, g_pS);      cudaGetSymbolAddress((void**)&pS2, g_pS2);
    cudaGetSymbolAddress((void**)&scale, g_scale); cudaGetSymbolAddress((void**)&shift, g_shift);

    const int SMEM64 = RSU * (2*128 + 2*64) * 2 * 4;   // 61440 B
    cudaFuncSetAttribute(vgemm_kernel,   cudaFuncAttributeMaxDynamicSharedMemorySize, SMEM64);
    cudaFuncSetAttribute(gemm_ps_kernel, cudaFuncAttributeMaxDynamicSharedMemorySize, SMEM64);

    // 1) prep + buildG
    prep_kernel<<<168, 256>>>(x, Q, En, Xthi, Xtlo,
                              W1, W1hi, W1lo, W2, W2hi, W2lo, W3, W3hi, W3lo);
    buildG_kernel<<<128, 256>>>(x, Ghi, Glo);

    // 2) V = En .* (G @ Xt^T) - pos
    vgemm_kernel<<<dim3(4, 4, 16), 256, SMEM64>>>(Ghi, Glo, Xthi, Xtlo, En, x, Vhi, Vlo);

    // 3) layer 1 (stats fused)
    gemm_ps_kernel<<<dim3(NH/64, MROWS/128), 256, SMEM64>>>(
        Vhi, Vlo, W1hi, W1lo, b1, Y1, pS, pS2, VDIM, NH);
    stats_final_kernel<<<NH/8, 256>>>(pS, pS2, g1, bt1, MROWS, NH, scale, shift);
    bnconvert_kernel<<<(MROWS*NH/4 + 255)/256, 256>>>(Y1, scale, shift, Axhi, Axlo, MROWS*NH/4, NH/4);

    // 4) layer 2
    gemm_ps_kernel<<<dim3(NH/64, MROWS/128), 256, SMEM64>>>(
        Axhi, Axlo, W2hi, W2lo, b2, Y2, pS, pS2, NH, NH);
    stats_final_kernel<<<NH/8, 256>>>(pS, pS2, g2, bt2, MROWS, NH, scale, shift);
    bnconvert_kernel<<<(MROWS*NH/4 + 255)/256, 256>>>(Y2, scale, shift, Axhi, Axlo, MROWS*NH/4, NH/4);

    // 5) layer 3
    gemm_ps_kernel<<<dim3(NO/64, MROWS/128), 256, SMEM64>>>(
        Axhi, Axlo, W3hi, W3lo, b3, Y3, pS, pS2, NH, NO);
    stats_final_kernel<<<NO/8, 256>>>(pS, pS2, g3, bt3, MROWS, NO, scale, shift);

    // 6) final BN apply -> out
    int total4 = MROWS * NO / 4;
    bnapply_kernel<<<(total4 + 255)/256, 256>>>(Y3, scale, shift, out, total4, NO/4);
}

// round 12
// speedup vs baseline: 1.0845x; 1.0845x over previous
#include <cuda_runtime.h>
#include <cuda_bf16.h>
#include <cstdint>
#include <math.h>

#define BATCH 16
#define SEQ   512
#define NI    32
#define NHEAD 8
#define NH    512
#define NO    64
#define MROWS (BATCH*SEQ)      // 8192
#define VDIM  (NHEAD*NI)       // 256
#define EPSV  1e-5f
#define SLOPE 0.05f
#define NPART 64

// ---------------- scratch ----------------
__device__ float    g_En  [16*8*512];
__device__ uint32_t g_Xthi[(size_t)16*256*256], g_Xtlo[(size_t)16*256*256];
__device__ uint32_t g_Ghi [(size_t)16*512*256], g_Glo [(size_t)16*512*256];
__device__ uint32_t g_Vhi [(size_t)8192*128],   g_Vlo [(size_t)8192*128];
__device__ uint32_t g_W1hi[512*128], g_W1lo[512*128];
__device__ uint32_t g_W2hi[512*256], g_W2lo[512*256];
__device__ uint32_t g_W3hi[64*256],  g_W3lo[64*256];
__device__ uint32_t g_Axhi[(size_t)8192*256],   g_Axlo[(size_t)8192*256];
__device__ float g_Y1[(size_t)MROWS * NH];
__device__ float g_Y2[(size_t)MROWS * NH];
__device__ float g_Y3[(size_t)MROWS * NO];
__device__ float g_pS [NPART * NH];
__device__ float g_pS2[NPART * NH];
__device__ float g_scale[NH];
__device__ float g_shift[NH];

// ---------------- helpers ----------------
__device__ __forceinline__ void split_pair(float v0, float v1, uint32_t& hi, uint32_t& lo) {
    __nv_bfloat16 h0 = __float2bfloat16(v0);
    __nv_bfloat16 h1 = __float2bfloat16(v1);
    float r0 = v0 - __bfloat162float(h0);
    float r1 = v1 - __bfloat162float(h1);
    __nv_bfloat16 l0 = __float2bfloat16(r0);
    __nv_bfloat16 l1 = __float2bfloat16(r1);
    hi = ((uint32_t)__bfloat16_as_ushort(h1) << 16) | __bfloat16_as_ushort(h0);
    lo = ((uint32_t)__bfloat16_as_ushort(l1) << 16) | __bfloat16_as_ushort(l0);
}

__device__ __forceinline__ void mma_bf16(float* d, const uint32_t* a, const uint32_t* b) {
    asm volatile(
        "mma.sync.aligned.m16n8k16.row.col.f32.bf16.bf16.f32 "
        "{%0,%1,%2,%3}, {%4,%5,%6,%7}, {%8,%9}, {%0,%1,%2,%3};"
        : "+f"(d[0]), "+f"(d[1]), "+f"(d[2]), "+f"(d[3])
        : "r"(a[0]), "r"(a[1]), "r"(a[2]), "r"(a[3]), "r"(b[0]), "r"(b[1]));
}

__device__ __forceinline__ void ldsm4(uint32_t* r, uint32_t addr) {
    asm volatile("ldmatrix.sync.aligned.m8n8.x4.shared.b16 {%0,%1,%2,%3}, [%4];"
        : "=r"(r[0]), "=r"(r[1]), "=r"(r[2]), "=r"(r[3]) : "r"(addr));
}

__device__ __forceinline__ uint32_t smem_u32(const void* p) {
    uint32_t a;
    asm("{ .reg .u64 t; cvta.to.shared.u64 t, %1; cvt.u32.u64 %0, t; }" : "=r"(a) : "l"(p));
    return a;
}
__device__ __forceinline__ void cp_async16(uint32_t saddr, const void* gptr) {
    asm volatile("cp.async.cg.shared.global [%0], [%1], 16;" :: "r"(saddr), "l"(gptr));
}
#define CP_COMMIT() asm volatile("cp.async.commit_group;" ::: "memory")
#define CP_WAIT0()  asm volatile("cp.async.wait_group 0;" ::: "memory")

// ---------------- prep: En tables, Xt build, W splits ----------------
__global__ void __launch_bounds__(256) prep_kernel(
    const float* __restrict__ x, const float* __restrict__ Q,
    float* __restrict__ En,
    uint32_t* __restrict__ Xthi, uint32_t* __restrict__ Xtlo,
    const float* __restrict__ W1, uint32_t* __restrict__ W1hi, uint32_t* __restrict__ W1lo,
    const float* __restrict__ W2, uint32_t* __restrict__ W2hi, uint32_t* __restrict__ W2lo,
    const float* __restrict__ W3, uint32_t* __restrict__ W3hi, uint32_t* __restrict__ W3lo)
{
    const int blk = blockIdx.x;
    const int tid = threadIdx.x;

    if (blk >= 64) {
        int widx = blk - 64;
        const float* src; uint32_t* hi; uint32_t* lo; int base;
        if (widx < 32)      { src = W1; hi = W1hi; lo = W1lo; base = widx * 2048; }
        else if (widx < 96) { src = W2; hi = W2hi; lo = W2lo; base = (widx - 32) * 2048; }
        else                { src = W3; hi = W3hi; lo = W3lo; base = (widx - 96) * 2048; }
        int p = base + tid;
        #pragma unroll
        for (int j = 0; j < 8; j++, p += 256) {
            float2 v = ((const float2*)src)[p];
            uint32_t h, l; split_pair(v.x, v.y, h, l);
            hi[p] = h; lo[p] = l;
        }
        return;
    }

    const int b = blk >> 2, chunk = blk & 3;

    __shared__ float sEm[8][128];
    __shared__ float sQ[8][4];
    __shared__ uint32_t shi[256][8], slo[256][8];

    if (tid < 8) {
        float a = Q[tid*3+0], bq = Q[tid*3+1], cq = Q[tid*3+2];
        sQ[tid][0] = a; sQ[tid][1] = bq; sQ[tid][2] = cq;
        sQ[tid][3] = a*a + bq*bq + cq*cq;
    }
    __syncthreads();

    if (tid < 128) {
        int m = chunk*128 + tid;
        const float* xp = x + ((size_t)b*512 + m)*32;
        float px = xp[0], py = xp[1], pz = xp[2];
        #pragma unroll
        for (int h = 0; h < 8; h++) {
            float dot = px*sQ[h][0] + py*sQ[h][1] + pz*sQ[h][2];
            float em = __expf(-2.f*dot);
            float en = __expf(2.f*dot - sQ[h][3]);
            sEm[h][tid] = em;
            En[((size_t)b*8 + h)*512 + m] = en;
        }
    }
    __syncthreads();

    const int c = tid, h = c >> 5, i = c & 31;
    for (int grp = 0; grp < 8; grp++) {
        #pragma unroll
        for (int j = 0; j < 8; j++) {
            int mloc = (grp*8 + j)*2;
            int m = chunk*128 + mloc;
            float v0 = sEm[h][mloc]   * x[((size_t)b*512 + m  )*32 + i];
            float v1 = sEm[h][mloc+1] * x[((size_t)b*512 + m+1)*32 + i];
            uint32_t hh, ll; split_pair(v0, v1, hh, ll);
            shi[c][j] = hh; slo[c][j] = ll;
        }
        __syncthreads();
        int cc = tid >> 3, j2 = tid & 7;
        #pragma unroll
        for (int rep = 0; rep < 8; rep++) {
            int ccc = cc + rep*32;
            size_t addr = ((size_t)b*256 + ccc)*256 + chunk*64 + grp*8 + j2;
            Xthi[addr] = shi[ccc][j2];
            Xtlo[addr] = slo[ccc][j2];
        }
        __syncthreads();
    }
}

// ---------------- buildG ----------------
__global__ void __launch_bounds__(256) buildG_kernel(
    const float* __restrict__ x, uint32_t* __restrict__ Ghi, uint32_t* __restrict__ Glo)
{
    const int b  = blockIdx.x >> 3, nt = blockIdx.x & 7;
    const int tid = threadIdx.x;
    const int n = tid & 63, mq = tid >> 6;

    __shared__ float pn3[64][5];
    __shared__ float pm3[128][4];

    if (tid < 64) {
        const float* xp = x + ((size_t)b*512 + nt*64 + tid)*32;
        pn3[tid][0] = xp[0]; pn3[tid][1] = xp[1]; pn3[tid][2] = xp[2];
    }

    for (int mc = 0; mc < 4; mc++) {
        __syncthreads();
        if (tid < 128) {
            const float* xp = x + ((size_t)b*512 + mc*128 + tid)*32;
            pm3[tid][0] = xp[0]; pm3[tid][1] = xp[1]; pm3[tid][2] = xp[2];
        }
        __syncthreads();
        float px = pn3[n][0], py = pn3[n][1], pz = pn3[n][2];
        uint32_t outh[16], outl[16];
        #pragma unroll
        for (int j = 0; j < 16; j++) {
            int ml = mq*32 + j*2;
            float dx0 = px - pm3[ml][0],   dy0 = py - pm3[ml][1],   dz0 = pz - pm3[ml][2];
            float dx1 = px - pm3[ml+1][0], dy1 = py - pm3[ml+1][1], dz1 = pz - pm3[ml+1][2];
            float e0 = __expf(-(dx0*dx0 + dy0*dy0 + dz0*dz0));
            float e1 = __expf(-(dx1*dx1 + dy1*dy1 + dz1*dz1));
            split_pair(e0, e1, outh[j], outl[j]);
        }
        size_t base = ((size_t)b*512 + nt*64 + n)*256 + mc*64 + mq*16;
        #pragma unroll
        for (int j4 = 0; j4 < 4; j4++) {
            ((uint4*)(Ghi + base))[j4] = make_uint4(outh[j4*4], outh[j4*4+1], outh[j4*4+2], outh[j4*4+3]);
            ((uint4*)(Glo + base))[j4] = make_uint4(outl[j4*4], outl[j4*4+1], outl[j4*4+2], outl[j4*4+3]);
        }
    }
}

// ================= GEMM machinery =================
#define RSU 20
#define TN  64
#define NFRAG (TN/16)
#define ASZ (128*RSU)
#define BSZ (TN*RSU)

// ---------------- vgemm: V = En .* (G @ Xt^T) - pos (R10 proven) ----------------
__global__ void __launch_bounds__(256, 3) vgemm_kernel(
    const uint32_t* __restrict__ Ghi, const uint32_t* __restrict__ Glo,
    const uint32_t* __restrict__ Bhi_g, const uint32_t* __restrict__ Blo_g,
    const float* __restrict__ En, const float* __restrict__ x,
    uint32_t* __restrict__ Vhi, uint32_t* __restrict__ Vlo)
{
    constexpr int KE = 512, K2 = KE/2;
    extern __shared__ uint32_t smem_u[];
    const uint32_t sbase = smem_u32(smem_u);
    const uint32_t bAh = sbase;
    const uint32_t bAl = sbase + 2*ASZ*4;
    const uint32_t bBh = sbase + 4*ASZ*4;
    const uint32_t bBl = sbase + (4*ASZ + 2*BSZ)*4;

    const int tid = threadIdx.x, wid = tid >> 5, lane = tid & 31;
    const int wm = (wid >> 1) * 32, wn = (wid & 1) * (TN/2);
    const int l4 = lane >> 2, lk = lane & 3;
    const int rowA = lane & 15, colA = (lane >> 4) * 4;
    const int rowB = ((lane >> 4) & 1) * 8 + (lane & 7);
    const int colB = ((lane >> 3) & 1) * 4;
    const int b = blockIdx.z;
    const int m0 = blockIdx.y * 128, c0 = blockIdx.x * TN;

    const uint32_t* Ah_g = Ghi + (size_t)b*512*K2;
    const uint32_t* Al_g = Glo + (size_t)b*512*K2;
    const uint32_t* Bh_g = Bhi_g + (size_t)b*256*K2;
    const uint32_t* Bl_g = Blo_g + (size_t)b*256*K2;

    float acc[2][NFRAG][4];
    #pragma unroll
    for (int a = 0; a < 2; a++)
        #pragma unroll
        for (int q = 0; q < NFRAG; q++)
            { acc[a][q][0]=0.f; acc[a][q][1]=0.f; acc[a][q][2]=0.f; acc[a][q][3]=0.f; }

    auto issue = [&](int t) {
        int buf = t & 1;
        #pragma unroll
        for (int j = 0; j < 2; j++) {
            int lin = tid + j*256; int r = lin >> 2, q = lin & 3;
            uint32_t off = (uint32_t)(buf*ASZ + r*RSU + q*4) * 4;
            size_t ao = (size_t)(m0 + r)*K2 + t*16 + q*4;
            cp_async16(bAh + off, Ah_g + ao);
            cp_async16(bAl + off, Al_g + ao);
        }
        {
            int r = tid >> 2, q = tid & 3;
            uint32_t off = (uint32_t)(buf*BSZ + r*RSU + q*4) * 4;
            size_t bo = (size_t)(c0 + r)*K2 + t*16 + q*4;
            cp_async16(bBh + off, Bh_g + bo);
            cp_async16(bBl + off, Bl_g + bo);
        }
        CP_COMMIT();
    };

    auto compute = [&](int buf) {
        #pragma unroll
        for (int kk = 0; kk < 2; kk++) {
            uint32_t ah[2][4], al[2][4];
            #pragma unroll
            for (int mi = 0; mi < 2; mi++) {
                uint32_t off = (uint32_t)(buf*ASZ + (wm + mi*16 + rowA)*RSU + kk*8 + colA) * 4;
                ldsm4(ah[mi], bAh + off);
                ldsm4(al[mi], bAl + off);
            }
            #pragma unroll
            for (int np = 0; np < NFRAG/2; np++) {
                uint32_t off = (uint32_t)(buf*BSZ + (wn + np*16 + rowB)*RSU + kk*8 + colB) * 4;
                uint32_t th[4], tl[4];
                ldsm4(th, bBh + off);
                ldsm4(tl, bBl + off);
                #pragma unroll
                for (int sub = 0; sub < 2; sub++) {
                    int ni = np*2 + sub;
                    uint32_t bhp[2] = {th[sub*2], th[sub*2+1]};
                    uint32_t blp[2] = {tl[sub*2], tl[sub*2+1]};
                    #pragma unroll
                    for (int mi = 0; mi < 2; mi++) {
                        mma_bf16(acc[mi][ni], ah[mi], bhp);
                        mma_bf16(acc[mi][ni], ah[mi], blp);
                        mma_bf16(acc[mi][ni], al[mi], bhp);
                    }
                }
            }
        }
    };

    const int T = KE / 32;
    issue(0);
    for (int t = 0; t < T; t++) {
        CP_WAIT0();
        __syncthreads();
        if (t + 1 < T) issue(t + 1);
        compute(t & 1);
    }

    #pragma unroll
    for (int mi = 0; mi < 2; mi++) {
        #pragma unroll
        for (int ni = 0; ni < NFRAG; ni++) {
            int n0 = m0 + wm + mi*16 + l4;
            int cc = c0 + wn + ni*8 + lk*2;
            int h = cc >> 5, il = cc & 31;
            float en0 = En[((size_t)b*8 + h)*512 + n0];
            float en1 = En[((size_t)b*8 + h)*512 + n0 + 8];
            float v00 = acc[mi][ni][0]*en0, v01 = acc[mi][ni][1]*en0;
            float v10 = acc[mi][ni][2]*en1, v11 = acc[mi][ni][3]*en1;
            if (il < 3) {
                v00 -= x[((size_t)b*512 + n0  )*32 + il];
                v10 -= x[((size_t)b*512 + n0+8)*32 + il];
            }
            if (il + 1 < 3) {
                v01 -= x[((size_t)b*512 + n0  )*32 + il + 1];
                v11 -= x[((size_t)b*512 + n0+8)*32 + il + 1];
            }
            uint32_t h0, l0, h1, l1;
            split_pair(v00, v01, h0, l0);
            split_pair(v10, v11, h1, l1);
            size_t r0 = ((size_t)b*512 + n0)*128 + (cc >> 1);
            size_t r1 = ((size_t)b*512 + n0 + 8)*128 + (cc >> 1);
            Vhi[r0] = h0; Vlo[r0] = l0;
            Vhi[r1] = h1; Vlo[r1] = l1;
        }
    }
}

// ---------------- gemm_big: 512 threads, TM=256 x TNB=128, fused stats ----------------
#define TNB  128
#define NFB  (TNB/16)          // 8 n-fragments per warp (warp tile 32x64)
#define ASZB (256*RSU)
#define BSZB (128*RSU)

__global__ void __launch_bounds__(512, 1) gemm_big_kernel(
    const uint32_t* __restrict__ Ah_g, const uint32_t* __restrict__ Al_g,
    const uint32_t* __restrict__ Bh_g, const uint32_t* __restrict__ Bl_g,
    const float* __restrict__ bias, float* __restrict__ Y,
    float* __restrict__ pS, float* __restrict__ pS2, int K, int C)
{
    extern __shared__ uint32_t smem_u[];
    const uint32_t sbase = smem_u32(smem_u);
    const uint32_t bAh = sbase;
    const uint32_t bAl = sbase + 2*ASZB*4;
    const uint32_t bBh = sbase + 4*ASZB*4;
    const uint32_t bBl = sbase + (4*ASZB + 2*BSZB)*4;

    const int tid = threadIdx.x, wid = tid >> 5, lane = tid & 31;
    const int wm = (wid >> 1) * 32;          // 0..224
    const int wn = (wid & 1) * 64;           // 0 or 64
    const int mw = wid >> 1;                 // 0..7
    const int l4 = lane >> 2, lk = lane & 3;
    const int rowA = lane & 15, colA = (lane >> 4) * 4;
    const int rowB = ((lane >> 4) & 1) * 8 + (lane & 7);
    const int colB = ((lane >> 3) & 1) * 4;
    const int m0 = blockIdx.y * 256, c0 = blockIdx.x * TNB;
    const int K2 = K >> 1;

    float acc[2][NFB][4];
    #pragma unroll
    for (int a = 0; a < 2; a++)
        #pragma unroll
        for (int q = 0; q < NFB; q++)
            { acc[a][q][0]=0.f; acc[a][q][1]=0.f; acc[a][q][2]=0.f; acc[a][q][3]=0.f; }

    auto issue = [&](int t) {
        int buf = t & 1;
        #pragma unroll
        for (int j = 0; j < 2; j++) {
            int lin = tid + j*512; int r = lin >> 2, q = lin & 3;   // r < 256
            uint32_t off = (uint32_t)(buf*ASZB + r*RSU + q*4) * 4;
            size_t ao = (size_t)(m0 + r)*K2 + t*16 + q*4;
            cp_async16(bAh + off, Ah_g + ao);
            cp_async16(bAl + off, Al_g + ao);
        }
        {
            int r = tid >> 2, q = tid & 3;                          // r < 128
            uint32_t off = (uint32_t)(buf*BSZB + r*RSU + q*4) * 4;
            size_t bo = (size_t)(c0 + r)*K2 + t*16 + q*4;
            cp_async16(bBh + off, Bh_g + bo);
            cp_async16(bBl + off, Bl_g + bo);
        }
        CP_COMMIT();
    };

    auto compute = [&](int buf) {
        #pragma unroll
        for (int kk = 0; kk < 2; kk++) {
            uint32_t ah[2][4], al[2][4];
            #pragma unroll
            for (int mi = 0; mi < 2; mi++) {
                uint32_t off = (uint32_t)(buf*ASZB + (wm + mi*16 + rowA)*RSU + kk*8 + colA) * 4;
                ldsm4(ah[mi], bAh + off);
                ldsm4(al[mi], bAl + off);
            }
            #pragma unroll
            for (int np = 0; np < NFB/2; np++) {
                uint32_t off = (uint32_t)(buf*BSZB + (wn + np*16 + rowB)*RSU + kk*8 + colB) * 4;
                uint32_t th[4], tl[4];
                ldsm4(th, bBh + off);
                ldsm4(tl, bBl + off);
                #pragma unroll
                for (int sub = 0; sub < 2; sub++) {
                    int ni = np*2 + sub;
                    uint32_t bhp[2] = {th[sub*2], th[sub*2+1]};
                    uint32_t blp[2] = {tl[sub*2], tl[sub*2+1]};
                    #pragma unroll
                    for (int mi = 0; mi < 2; mi++) {
                        mma_bf16(acc[mi][ni], ah[mi], bhp);
                        mma_bf16(acc[mi][ni], ah[mi], blp);
                        mma_bf16(acc[mi][ni], al[mi], bhp);
                    }
                }
            }
        }
    };

    const int T = K / 32;
    issue(0);
    for (int t = 0; t < T; t++) {
        CP_WAIT0();
        __syncthreads();
        if (t + 1 < T) issue(t + 1);
        compute(t & 1);
    }
    __syncthreads();   // smem reused for stats below

    float* sbufS  = (float*)smem_u;          // [8][TNB]
    float* sbufS2 = sbufS + 8*TNB;

    #pragma unroll
    for (int ni = 0; ni < NFB; ni++) {
        int col = c0 + wn + ni*8 + lk*2;
        float2 b2 = *(const float2*)(bias + col);
        float s0 = 0.f, s1 = 0.f, q0 = 0.f, q1 = 0.f;
        #pragma unroll
        for (int mi = 0; mi < 2; mi++) {
            int row = m0 + wm + mi*16 + l4;
            float e0 = acc[mi][ni][0] + b2.x;
            float e1 = acc[mi][ni][1] + b2.y;
            float e2 = acc[mi][ni][2] + b2.x;
            float e3 = acc[mi][ni][3] + b2.y;
            *(float2*)(Y + (size_t)row * C + col)       = make_float2(e0, e1);
            *(float2*)(Y + (size_t)(row + 8) * C + col) = make_float2(e2, e3);
            s0 += e0 + e2; s1 += e1 + e3;
            q0 += e0*e0 + e2*e2; q1 += e1*e1 + e3*e3;
        }
        #pragma unroll
        for (int off = 16; off >= 4; off >>= 1) {
            s0 += __shfl_down_sync(0xffffffffu, s0, off);
            s1 += __shfl_down_sync(0xffffffffu, s1, off);
            q0 += __shfl_down_sync(0xffffffffu, q0, off);
            q1 += __shfl_down_sync(0xffffffffu, q1, off);
        }
        if (lane < 4) {
            int cb = wn + ni*8 + lk*2;
            sbufS [mw*TNB + cb]     = s0;
            sbufS [mw*TNB + cb + 1] = s1;
            sbufS2[mw*TNB + cb]     = q0;
            sbufS2[mw*TNB + cb + 1] = q1;
        }
    }
    __syncthreads();
    if (tid < TNB) {
        float s = 0.f, q = 0.f;
        #pragma unroll
        for (int r = 0; r < 8; r++) { s += sbufS[r*TNB + tid]; q += sbufS2[r*TNB + tid]; }
        pS [blockIdx.y * C + c0 + tid] = s;
        pS2[blockIdx.y * C + c0 + tid] = q;
    }
}

// ---------------- gemm_ps (TN=64, R10 proven) for layer 3 ----------------
__global__ void __launch_bounds__(256, 3) gemm_ps_kernel(
    const uint32_t* __restrict__ Ah_g, const uint32_t* __restrict__ Al_g,
    const uint32_t* __restrict__ Bh_g, const uint32_t* __restrict__ Bl_g,
    const float* __restrict__ bias, float* __restrict__ Y,
    float* __restrict__ pS, float* __restrict__ pS2, int K, int C)
{
    extern __shared__ uint32_t smem_u[];
    const uint32_t sbase = smem_u32(smem_u);
    const uint32_t bAh = sbase;
    const uint32_t bAl = sbase + 2*ASZ*4;
    const uint32_t bBh = sbase + 4*ASZ*4;
    const uint32_t bBl = sbase + (4*ASZ + 2*BSZ)*4;

    const int tid = threadIdx.x, wid = tid >> 5, lane = tid & 31;
    const int wm = (wid >> 1) * 32, wn = (wid & 1) * (TN/2);
    const int mw = wid >> 1;
    const int l4 = lane >> 2, lk = lane & 3;
    const int rowA = lane & 15, colA = (lane >> 4) * 4;
    const int rowB = ((lane >> 4) & 1) * 8 + (lane & 7);
    const int colB = ((lane >> 3) & 1) * 4;
    const int m0 = blockIdx.y * 128, c0 = blockIdx.x * TN;
    const int K2 = K >> 1;

    float acc[2][NFRAG][4];
    #pragma unroll
    for (int a = 0; a < 2; a++)
        #pragma unroll
        for (int q = 0; q < NFRAG; q++)
            { acc[a][q][0]=0.f; acc[a][q][1]=0.f; acc[a][q][2]=0.f; acc[a][q][3]=0.f; }

    auto issue = [&](int t) {
        int buf = t & 1;
        #pragma unroll
        for (int j = 0; j < 2; j++) {
            int lin = tid + j*256; int r = lin >> 2, q = lin & 3;
            uint32_t off = (uint32_t)(buf*ASZ + r*RSU + q*4) * 4;
            size_t ao = (size_t)(m0 + r)*K2 + t*16 + q*4;
            cp_async16(bAh + off, Ah_g + ao);
            cp_async16(bAl + off, Al_g + ao);
        }
        {
            int r = tid >> 2, q = tid & 3;
            uint32_t off = (uint32_t)(buf*BSZ + r*RSU + q*4) * 4;
            size_t bo = (size_t)(c0 + r)*K2 + t*16 + q*4;
            cp_async16(bBh + off, Bh_g + bo);
            cp_async16(bBl + off, Bl_g + bo);
        }
        CP_COMMIT();
    };

    auto compute = [&](int buf) {
        #pragma unroll
        for (int kk = 0; kk < 2; kk++) {
            uint32_t ah[2][4], al[2][4];
            #pragma unroll
            for (int mi = 0; mi < 2; mi++) {
                uint32_t off = (uint32_t)(buf*ASZ + (wm + mi*16 + rowA)*RSU + kk*8 + colA) * 4;
                ldsm4(ah[mi], bAh + off);
                ldsm4(al[mi], bAl + off);
            }
            #pragma unroll
            for (int np = 0; np < NFRAG/2; np++) {
                uint32_t off = (uint32_t)(buf*BSZ + (wn + np*16 + rowB)*RSU + kk*8 + colB) * 4;
                uint32_t th[4], tl[4];
                ldsm4(th, bBh + off);
                ldsm4(tl, bBl + off);
                #pragma unroll
                for (int sub = 0; sub < 2; sub++) {
                    int ni = np*2 + sub;
                    uint32_t bhp[2] = {th[sub*2], th[sub*2+1]};
                    uint32_t blp[2] = {tl[sub*2], tl[sub*2+1]};
                    #pragma unroll
                    for (int mi = 0; mi < 2; mi++) {
                        mma_bf16(acc[mi][ni], ah[mi], bhp);
                        mma_bf16(acc[mi][ni], ah[mi], blp);
                        mma_bf16(acc[mi][ni], al[mi], bhp);
                    }
                }
            }
        }
    };

    const int T = K / 32;
    issue(0);
    for (int t = 0; t < T; t++) {
        CP_WAIT0();
        __syncthreads();
        if (t + 1 < T) issue(t + 1);
        compute(t & 1);
    }
    __syncthreads();

    float* sbufS  = (float*)smem_u;
    float* sbufS2 = sbufS + 4*TN;

    #pragma unroll
    for (int ni = 0; ni < NFRAG; ni++) {
        int col = c0 + wn + ni*8 + lk*2;
        float2 b2 = *(const float2*)(bias + col);
        float s0 = 0.f, s1 = 0.f, q0 = 0.f, q1 = 0.f;
        #pragma unroll
        for (int mi = 0; mi < 2; mi++) {
            int row = m0 + wm + mi*16 + l4;
            float e0 = acc[mi][ni][0] + b2.x;
            float e1 = acc[mi][ni][1] + b2.y;
            float e2 = acc[mi][ni][2] + b2.x;
            float e3 = acc[mi][ni][3] + b2.y;
            *(float2*)(Y + (size_t)row * C + col)       = make_float2(e0, e1);
            *(float2*)(Y + (size_t)(row + 8) * C + col) = make_float2(e2, e3);
            s0 += e0 + e2; s1 += e1 + e3;
            q0 += e0*e0 + e2*e2; q1 += e1*e1 + e3*e3;
        }
        #pragma unroll
        for (int off = 16; off >= 4; off >>= 1) {
            s0 += __shfl_down_sync(0xffffffffu, s0, off);
            s1 += __shfl_down_sync(0xffffffffu, s1, off);
            q0 += __shfl_down_sync(0xffffffffu, q0, off);
            q1 += __shfl_down_sync(0xffffffffu, q1, off);
        }
        if (lane < 4) {
            int cb = wn + ni*8 + lk*2;
            sbufS [mw*TN + cb]     = s0;
            sbufS [mw*TN + cb + 1] = s1;
            sbufS2[mw*TN + cb]     = q0;
            sbufS2[mw*TN + cb + 1] = q1;
        }
    }
    __syncthreads();
    if (tid < TN) {
        float s = sbufS [tid] + sbufS [TN + tid] + sbufS [2*TN + tid] + sbufS [3*TN + tid];
        float q = sbufS2[tid] + sbufS2[TN + tid] + sbufS2[2*TN + tid] + sbufS2[3*TN + tid];
        pS [blockIdx.y * C + c0 + tid] = s;
        pS2[blockIdx.y * C + c0 + tid] = q;
    }
}

// ---------------- stats_final (variable partial count) ----------------
__global__ void __launch_bounds__(256) stats_final_kernel(
    const float* __restrict__ pS, const float* __restrict__ pS2,
    const float* __restrict__ g, const float* __restrict__ bt,
    int M, int C, int npart, float* __restrict__ scale, float* __restrict__ shift)
{
    const int c = blockIdx.x * 8 + (threadIdx.x >> 5);
    const int j = threadIdx.x & 31;
    float s = 0.f, s2 = 0.f;
    for (int p = j; p < npart; p += 32) {
        s  += pS [p * C + c];
        s2 += pS2[p * C + c];
    }
    #pragma unroll
    for (int off = 16; off > 0; off >>= 1) {
        s  += __shfl_down_sync(0xffffffffu, s,  off);
        s2 += __shfl_down_sync(0xffffffffu, s2, off);
    }
    if (j == 0) {
        float invM = 1.f / (float)M;
        float mean = s * invM;
        float var  = fmaf(-mean, mean, s2 * invM);
        float inv  = rsqrtf(var + EPSV);
        float scv  = g[c] * inv;
        scale[c] = scv;
        shift[c] = fmaf(-mean, scv, bt[c]);
    }
}

// ---------------- bnconvert ----------------
__global__ void __launch_bounds__(256) bnconvert_kernel(
    const float* __restrict__ Y, const float* __restrict__ scale,
    const float* __restrict__ shift, uint32_t* __restrict__ hi, uint32_t* __restrict__ lo,
    int total4, int C4)
{
    int idx = blockIdx.x * blockDim.x + threadIdx.x;
    if (idx >= total4) return;
    int c4 = idx % C4;
    float4 y  = ((const float4*)Y)[idx];
    float4 sc = ((const float4*)scale)[c4];
    float4 sh = ((const float4*)shift)[c4];
    float v[4];
    v[0] = fmaf(y.x, sc.x, sh.x); v[1] = fmaf(y.y, sc.y, sh.y);
    v[2] = fmaf(y.z, sc.z, sh.z); v[3] = fmaf(y.w, sc.w, sh.w);
    #pragma unroll
    for (int q = 0; q < 4; q++) v[q] = v[q] > 0.f ? v[q] : v[q] * SLOPE;
    uint32_t h0, l0, h1, l1;
    split_pair(v[0], v[1], h0, l0);
    split_pair(v[2], v[3], h1, l1);
    ((uint2*)hi)[idx] = make_uint2(h0, h1);
    ((uint2*)lo)[idx] = make_uint2(l0, l1);
}

// ---------------- final BN apply ----------------
__global__ void __launch_bounds__(256) bnapply_kernel(
    const float* __restrict__ Y, const float* __restrict__ scale,
    const float* __restrict__ shift, float* __restrict__ out, int total4, int C4)
{
    int idx = blockIdx.x * blockDim.x + threadIdx.x;
    if (idx >= total4) return;
    int c4 = idx % C4;
    float4 y  = ((const float4*)Y)[idx];
    float4 sc = ((const float4*)scale)[c4];
    float4 sh = ((const float4*)shift)[c4];
    float4 o;
    o.x = fmaf(y.x, sc.x, sh.x);
    o.y = fmaf(y.y, sc.y, sh.y);
    o.z = fmaf(y.z, sc.z, sh.z);
    o.w = fmaf(y.w, sc.w, sh.w);
    ((float4*)out)[idx] = o;
}

// ---------------- host ----------------
extern "C" void kernel_launch(void* const* d_in, const int* in_sizes, int n_in,
                              void* d_out, int out_size)
{
    const float* x   = (const float*)d_in[0];
    const float* Q   = (const float*)d_in[1];
    const float* W1  = (const float*)d_in[2];
    const float* b1  = (const float*)d_in[3];
    const float* g1  = (const float*)d_in[4];
    const float* bt1 = (const float*)d_in[5];
    const float* W2  = (const float*)d_in[6];
    const float* b2  = (const float*)d_in[7];
    const float* g2  = (const float*)d_in[8];
    const float* bt2 = (const float*)d_in[9];
    const float* W3  = (const float*)d_in[10];
    const float* b3  = (const float*)d_in[11];
    const float* g3  = (const float*)d_in[12];
    const float* bt3 = (const float*)d_in[13];
    float* out = (float*)d_out;

    float *En, *Y1, *Y2, *Y3, *pS, *pS2, *scale, *shift;
    uint32_t *Xthi, *Xtlo, *Ghi, *Glo, *Vhi, *Vlo, *Axhi, *Axlo;
    uint32_t *W1hi, *W1lo, *W2hi, *W2lo, *W3hi, *W3lo;
    cudaGetSymbolAddress((void**)&En,   g_En);
    cudaGetSymbolAddress((void**)&Xthi, g_Xthi);  cudaGetSymbolAddress((void**)&Xtlo, g_Xtlo);
    cudaGetSymbolAddress((void**)&Ghi,  g_Ghi);   cudaGetSymbolAddress((void**)&Glo,  g_Glo);
    cudaGetSymbolAddress((void**)&Vhi,  g_Vhi);   cudaGetSymbolAddress((void**)&Vlo,  g_Vlo);
    cudaGetSymbolAddress((void**)&Axhi, g_Axhi);  cudaGetSymbolAddress((void**)&Axlo, g_Axlo);
    cudaGetSymbolAddress((void**)&W1hi, g_W1hi);  cudaGetSymbolAddress((void**)&W1lo, g_W1lo);
    cudaGetSymbolAddress((void**)&W2hi, g_W2hi);  cudaGetSymbolAddress((void**)&W2lo, g_W2lo);
    cudaGetSymbolAddress((void**)&W3hi, g_W3hi);  cudaGetSymbolAddress((void**)&W3lo, g_W3lo);
    cudaGetSymbolAddress((void**)&Y1, g_Y1);
    cudaGetSymbolAddress((void**)&Y2, g_Y2);
    cudaGetSymbolAddress((void**)&Y3, g_Y3);
    cudaGetSymbolAddress((void**)&pS, g_pS);      cudaGetSymbolAddress((void**)&pS2, g_pS2);
    cudaGetSymbolAddress((void**)&scale, g_scale); cudaGetSymbolAddress((void**)&shift, g_shift);

    const int SMEM64  = RSU * (2*128 + 2*64) * 2 * 4;        // 61440 B
    const int SMEMBIG = RSU * (2*256 + 2*128) * 2 * 4;       // 122880 B
    cudaFuncSetAttribute(vgemm_kernel,    cudaFuncAttributeMaxDynamicSharedMemorySize, SMEM64);
    cudaFuncSetAttribute(gemm_ps_kernel,  cudaFuncAttributeMaxDynamicSharedMemorySize, SMEM64);
    cudaFuncSetAttribute(gemm_big_kernel, cudaFuncAttributeMaxDynamicSharedMemorySize, SMEMBIG);

    // 1) prep + buildG
    prep_kernel<<<168, 256>>>(x, Q, En, Xthi, Xtlo,
                              W1, W1hi, W1lo, W2, W2hi, W2lo, W3, W3hi, W3lo);
    buildG_kernel<<<128, 256>>>(x, Ghi, Glo);

    // 2) V = En .* (G @ Xt^T) - pos
    vgemm_kernel<<<dim3(4, 4, 16), 256, SMEM64>>>(Ghi, Glo, Xthi, Xtlo, En, x, Vhi, Vlo);

    // 3) layer 1 (big tiles, stats fused: 32 partials)
    gemm_big_kernel<<<dim3(NH/128, MROWS/256), 512, SMEMBIG>>>(
        Vhi, Vlo, W1hi, W1lo, b1, Y1, pS, pS2, VDIM, NH);
    stats_final_kernel<<<NH/8, 256>>>(pS, pS2, g1, bt1, MROWS, NH, 32, scale, shift);
    bnconvert_kernel<<<(MROWS*NH/4 + 255)/256, 256>>>(Y1, scale, shift, Axhi, Axlo, MROWS*NH/4, NH/4);

    // 4) layer 2 (big tiles)
    gemm_big_kernel<<<dim3(NH/128, MROWS/256), 512, SMEMBIG>>>(
        Axhi, Axlo, W2hi, W2lo, b2, Y2, pS, pS2, NH, NH);
    stats_final_kernel<<<NH/8, 256>>>(pS, pS2, g2, bt2, MROWS, NH, 32, scale, shift);
    bnconvert_kernel<<<(MROWS*NH/4 + 255)/256, 256>>>(Y2, scale, shift, Axhi, Axlo, MROWS*NH/4, NH/4);

    // 5) layer 3 (small, 64 partials)
    gemm_ps_kernel<<<dim3(NO/64, MROWS/128), 256, SMEM64>>>(
        Axhi, Axlo, W3hi, W3lo, b3, Y3, pS, pS2, NH, NO);
    stats_final_kernel<<<NO/8, 256>>>(pS, pS2, g3, bt3, MROWS, NO, 64, scale, shift);

    // 6) final BN apply -> out
    int total4 = MROWS * NO / 4;
    bnapply_kernel<<<(total4 + 255)/256, 256>>>(Y3, scale, shift, out, total4, NO/4);
}

// round 13
// speedup vs baseline: 1.2921x; 1.1914x over previous
#include <cuda_runtime.h>
#include <cuda_fp16.h>
#include <cstdint>
#include <math.h>

#define BATCH 16
#define SEQ   512
#define NI    32
#define NHEAD 8
#define NH    512
#define NO    64
#define MROWS (BATCH*SEQ)      // 8192
#define VDIM  (NHEAD*NI)       // 256
#define EPSV  1e-5f
#define SLOPE 0.05f
#define NPART 64

// ---------------- scratch ----------------
__device__ float    g_En  [16*8*512];
__device__ uint32_t g_Xth [(size_t)16*256*256];                 // Xt single fp16
__device__ uint32_t g_Ghi [(size_t)16*512*256], g_Glo [(size_t)16*512*256];
__device__ uint32_t g_Vhi [(size_t)8192*128],   g_Vlo [(size_t)8192*128];
__device__ uint32_t g_W1h[512*128];                             // W single fp16
__device__ uint32_t g_W2h[512*256];
__device__ uint32_t g_W3h[64*256];
__device__ uint32_t g_Axhi[(size_t)8192*256],   g_Axlo[(size_t)8192*256];
__device__ float g_Y1[(size_t)MROWS * NH];
__device__ float g_Y2[(size_t)MROWS * NH];
__device__ float g_Y3[(size_t)MROWS * NO];
__device__ float g_pS [NPART * NH];
__device__ float g_pS2[NPART * NH];
__device__ float g_scale[NH];
__device__ float g_shift[NH];

// ---------------- helpers ----------------
__device__ __forceinline__ void split_pair_h(float v0, float v1, uint32_t& hi, uint32_t& lo) {
    __half h0 = __float2half(v0);
    __half h1 = __float2half(v1);
    float r0 = v0 - __half2float(h0);
    float r1 = v1 - __half2float(h1);
    __half l0 = __float2half(r0);
    __half l1 = __float2half(r1);
    hi = ((uint32_t)__half_as_ushort(h1) << 16) | __half_as_ushort(h0);
    lo = ((uint32_t)__half_as_ushort(l1) << 16) | __half_as_ushort(l0);
}
__device__ __forceinline__ uint32_t pack_h(float v0, float v1) {
    __half h0 = __float2half(v0);
    __half h1 = __float2half(v1);
    return ((uint32_t)__half_as_ushort(h1) << 16) | __half_as_ushort(h0);
}

__device__ __forceinline__ void mma_f16(float* d, const uint32_t* a, const uint32_t* b) {
    asm volatile(
        "mma.sync.aligned.m16n8k16.row.col.f32.f16.f16.f32 "
        "{%0,%1,%2,%3}, {%4,%5,%6,%7}, {%8,%9}, {%0,%1,%2,%3};"
        : "+f"(d[0]), "+f"(d[1]), "+f"(d[2]), "+f"(d[3])
        : "r"(a[0]), "r"(a[1]), "r"(a[2]), "r"(a[3]), "r"(b[0]), "r"(b[1]));
}

__device__ __forceinline__ void ldsm4(uint32_t* r, uint32_t addr) {
    asm volatile("ldmatrix.sync.aligned.m8n8.x4.shared.b16 {%0,%1,%2,%3}, [%4];"
        : "=r"(r[0]), "=r"(r[1]), "=r"(r[2]), "=r"(r[3]) : "r"(addr));
}

__device__ __forceinline__ uint32_t smem_u32(const void* p) {
    uint32_t a;
    asm("{ .reg .u64 t; cvta.to.shared.u64 t, %1; cvt.u32.u64 %0, t; }" : "=r"(a) : "l"(p));
    return a;
}
__device__ __forceinline__ void cp_async16(uint32_t saddr, const void* gptr) {
    asm volatile("cp.async.cg.shared.global [%0], [%1], 16;" :: "r"(saddr), "l"(gptr));
}
#define CP_COMMIT() asm volatile("cp.async.commit_group;" ::: "memory")
#define CP_WAIT0()  asm volatile("cp.async.wait_group 0;" ::: "memory")

// ---------------- prep: En tables, Xt build (fp16), W fp16 convert ----------------
__global__ void __launch_bounds__(256) prep_kernel(
    const float* __restrict__ x, const float* __restrict__ Q,
    float* __restrict__ En,
    uint32_t* __restrict__ Xth,
    const float* __restrict__ W1, uint32_t* __restrict__ W1h,
    const float* __restrict__ W2, uint32_t* __restrict__ W2h,
    const float* __restrict__ W3, uint32_t* __restrict__ W3h)
{
    const int blk = blockIdx.x;
    const int tid = threadIdx.x;

    if (blk >= 64) {
        int widx = blk - 64;
        const float* src; uint32_t* dst; int base;
        if (widx < 32)      { src = W1; dst = W1h; base = widx * 2048; }
        else if (widx < 96) { src = W2; dst = W2h; base = (widx - 32) * 2048; }
        else                { src = W3; dst = W3h; base = (widx - 96) * 2048; }
        int p = base + tid;
        #pragma unroll
        for (int j = 0; j < 8; j++, p += 256) {
            float2 v = ((const float2*)src)[p];
            dst[p] = pack_h(v.x, v.y);
        }
        return;
    }

    const int b = blk >> 2, chunk = blk & 3;

    __shared__ float sEm[8][128];
    __shared__ float sQ[8][4];
    __shared__ uint32_t shi[256][8];

    if (tid < 8) {
        float a = Q[tid*3+0], bq = Q[tid*3+1], cq = Q[tid*3+2];
        sQ[tid][0] = a; sQ[tid][1] = bq; sQ[tid][2] = cq;
        sQ[tid][3] = a*a + bq*bq + cq*cq;
    }
    __syncthreads();

    if (tid < 128) {
        int m = chunk*128 + tid;
        const float* xp = x + ((size_t)b*512 + m)*32;
        float px = xp[0], py = xp[1], pz = xp[2];
        #pragma unroll
        for (int h = 0; h < 8; h++) {
            float dot = px*sQ[h][0] + py*sQ[h][1] + pz*sQ[h][2];
            float em = __expf(-2.f*dot);
            float en = __expf(2.f*dot - sQ[h][3]);
            sEm[h][tid] = em;
            En[((size_t)b*8 + h)*512 + m] = en;
        }
    }
    __syncthreads();

    const int c = tid, h = c >> 5, i = c & 31;
    for (int grp = 0; grp < 8; grp++) {
        #pragma unroll
        for (int j = 0; j < 8; j++) {
            int mloc = (grp*8 + j)*2;
            int m = chunk*128 + mloc;
            float v0 = sEm[h][mloc]   * x[((size_t)b*512 + m  )*32 + i];
            float v1 = sEm[h][mloc+1] * x[((size_t)b*512 + m+1)*32 + i];
            shi[c][j] = pack_h(v0, v1);
        }
        __syncthreads();
        int cc = tid >> 3, j2 = tid & 7;
        #pragma unroll
        for (int rep = 0; rep < 8; rep++) {
            int ccc = cc + rep*32;
            size_t addr = ((size_t)b*256 + ccc)*256 + chunk*64 + grp*8 + j2;
            Xth[addr] = shi[ccc][j2];
        }
        __syncthreads();
    }
}

// ---------------- buildG (fp16 hi/lo) ----------------
__global__ void __launch_bounds__(256) buildG_kernel(
    const float* __restrict__ x, uint32_t* __restrict__ Ghi, uint32_t* __restrict__ Glo)
{
    const int b  = blockIdx.x >> 3, nt = blockIdx.x & 7;
    const int tid = threadIdx.x;
    const int n = tid & 63, mq = tid >> 6;

    __shared__ float pn3[64][5];
    __shared__ float pm3[128][4];

    if (tid < 64) {
        const float* xp = x + ((size_t)b*512 + nt*64 + tid)*32;
        pn3[tid][0] = xp[0]; pn3[tid][1] = xp[1]; pn3[tid][2] = xp[2];
    }

    for (int mc = 0; mc < 4; mc++) {
        __syncthreads();
        if (tid < 128) {
            const float* xp = x + ((size_t)b*512 + mc*128 + tid)*32;
            pm3[tid][0] = xp[0]; pm3[tid][1] = xp[1]; pm3[tid][2] = xp[2];
        }
        __syncthreads();
        float px = pn3[n][0], py = pn3[n][1], pz = pn3[n][2];
        uint32_t outh[16], outl[16];
        #pragma unroll
        for (int j = 0; j < 16; j++) {
            int ml = mq*32 + j*2;
            float dx0 = px - pm3[ml][0],   dy0 = py - pm3[ml][1],   dz0 = pz - pm3[ml][2];
            float dx1 = px - pm3[ml+1][0], dy1 = py - pm3[ml+1][1], dz1 = pz - pm3[ml+1][2];
            float e0 = __expf(-(dx0*dx0 + dy0*dy0 + dz0*dz0));
            float e1 = __expf(-(dx1*dx1 + dy1*dy1 + dz1*dz1));
            split_pair_h(e0, e1, outh[j], outl[j]);
        }
        size_t base = ((size_t)b*512 + nt*64 + n)*256 + mc*64 + mq*16;
        #pragma unroll
        for (int j4 = 0; j4 < 4; j4++) {
            ((uint4*)(Ghi + base))[j4] = make_uint4(outh[j4*4], outh[j4*4+1], outh[j4*4+2], outh[j4*4+3]);
            ((uint4*)(Glo + base))[j4] = make_uint4(outl[j4*4], outl[j4*4+1], outl[j4*4+2], outl[j4*4+3]);
        }
    }
}

// ================= GEMM machinery: A = fp16 hi/lo, B = fp16 single, 2 MMAs =================
#define RSU 20
#define TN  64
#define NFRAG (TN/16)
#define ASZ (128*RSU)
#define BSZ (TN*RSU)

// ---------------- vgemm: V = En .* (G @ Xt^T) - pos ----------------
__global__ void __launch_bounds__(256, 3) vgemm_kernel(
    const uint32_t* __restrict__ Ghi, const uint32_t* __restrict__ Glo,
    const uint32_t* __restrict__ Bh_gl,
    const float* __restrict__ En, const float* __restrict__ x,
    uint32_t* __restrict__ Vhi, uint32_t* __restrict__ Vlo)
{
    constexpr int KE = 512, K2 = KE/2;
    extern __shared__ uint32_t smem_u[];
    const uint32_t sbase = smem_u32(smem_u);
    const uint32_t bAh = sbase;
    const uint32_t bAl = sbase + 2*ASZ*4;
    const uint32_t bBh = sbase + 4*ASZ*4;

    const int tid = threadIdx.x, wid = tid >> 5, lane = tid & 31;
    const int wm = (wid >> 1) * 32, wn = (wid & 1) * (TN/2);
    const int l4 = lane >> 2, lk = lane & 3;
    const int rowA = lane & 15, colA = (lane >> 4) * 4;
    const int rowB = ((lane >> 4) & 1) * 8 + (lane & 7);
    const int colB = ((lane >> 3) & 1) * 4;
    const int b = blockIdx.z;
    const int m0 = blockIdx.y * 128, c0 = blockIdx.x * TN;

    const uint32_t* Ah_g = Ghi + (size_t)b*512*K2;
    const uint32_t* Al_g = Glo + (size_t)b*512*K2;
    const uint32_t* Bh_g = Bh_gl + (size_t)b*256*K2;

    float acc[2][NFRAG][4];
    #pragma unroll
    for (int a = 0; a < 2; a++)
        #pragma unroll
        for (int q = 0; q < NFRAG; q++)
            { acc[a][q][0]=0.f; acc[a][q][1]=0.f; acc[a][q][2]=0.f; acc[a][q][3]=0.f; }

    auto issue = [&](int t) {
        int buf = t & 1;
        #pragma unroll
        for (int j = 0; j < 2; j++) {
            int lin = tid + j*256; int r = lin >> 2, q = lin & 3;
            uint32_t off = (uint32_t)(buf*ASZ + r*RSU + q*4) * 4;
            size_t ao = (size_t)(m0 + r)*K2 + t*16 + q*4;
            cp_async16(bAh + off, Ah_g + ao);
            cp_async16(bAl + off, Al_g + ao);
        }
        {
            int r = tid >> 2, q = tid & 3;
            uint32_t off = (uint32_t)(buf*BSZ + r*RSU + q*4) * 4;
            size_t bo = (size_t)(c0 + r)*K2 + t*16 + q*4;
            cp_async16(bBh + off, Bh_g + bo);
        }
        CP_COMMIT();
    };

    auto compute = [&](int buf) {
        #pragma unroll
        for (int kk = 0; kk < 2; kk++) {
            uint32_t ah[2][4], al[2][4];
            #pragma unroll
            for (int mi = 0; mi < 2; mi++) {
                uint32_t off = (uint32_t)(buf*ASZ + (wm + mi*16 + rowA)*RSU + kk*8 + colA) * 4;
                ldsm4(ah[mi], bAh + off);
                ldsm4(al[mi], bAl + off);
            }
            #pragma unroll
            for (int np = 0; np < NFRAG/2; np++) {
                uint32_t off = (uint32_t)(buf*BSZ + (wn + np*16 + rowB)*RSU + kk*8 + colB) * 4;
                uint32_t th[4];
                ldsm4(th, bBh + off);
                #pragma unroll
                for (int sub = 0; sub < 2; sub++) {
                    int ni = np*2 + sub;
                    uint32_t bhp[2] = {th[sub*2], th[sub*2+1]};
                    #pragma unroll
                    for (int mi = 0; mi < 2; mi++) {
                        mma_f16(acc[mi][ni], ah[mi], bhp);
                        mma_f16(acc[mi][ni], al[mi], bhp);
                    }
                }
            }
        }
    };

    const int T = KE / 32;
    issue(0);
    for (int t = 0; t < T; t++) {
        CP_WAIT0();
        __syncthreads();
        if (t + 1 < T) issue(t + 1);
        compute(t & 1);
    }

    #pragma unroll
    for (int mi = 0; mi < 2; mi++) {
        #pragma unroll
        for (int ni = 0; ni < NFRAG; ni++) {
            int n0 = m0 + wm + mi*16 + l4;
            int cc = c0 + wn + ni*8 + lk*2;
            int h = cc >> 5, il = cc & 31;
            float en0 = En[((size_t)b*8 + h)*512 + n0];
            float en1 = En[((size_t)b*8 + h)*512 + n0 + 8];
            float v00 = acc[mi][ni][0]*en0, v01 = acc[mi][ni][1]*en0;
            float v10 = acc[mi][ni][2]*en1, v11 = acc[mi][ni][3]*en1;
            if (il < 3) {
                v00 -= x[((size_t)b*512 + n0  )*32 + il];
                v10 -= x[((size_t)b*512 + n0+8)*32 + il];
            }
            if (il + 1 < 3) {
                v01 -= x[((size_t)b*512 + n0  )*32 + il + 1];
                v11 -= x[((size_t)b*512 + n0+8)*32 + il + 1];
            }
            uint32_t h0, l0, h1, l1;
            split_pair_h(v00, v01, h0, l0);
            split_pair_h(v10, v11, h1, l1);
            size_t r0 = ((size_t)b*512 + n0)*128 + (cc >> 1);
            size_t r1 = ((size_t)b*512 + n0 + 8)*128 + (cc >> 1);
            Vhi[r0] = h0; Vlo[r0] = l0;
            Vhi[r1] = h1; Vlo[r1] = l1;
        }
    }
}

// ---------------- gemm_big: 512 threads, TM=256 x TNB=128, fused stats ----------------
#define TNB  128
#define NFB  (TNB/16)
#define ASZB (256*RSU)
#define BSZB (128*RSU)

__global__ void __launch_bounds__(512, 1) gemm_big_kernel(
    const uint32_t* __restrict__ Ah_g, const uint32_t* __restrict__ Al_g,
    const uint32_t* __restrict__ Bh_g,
    const float* __restrict__ bias, float* __restrict__ Y,
    float* __restrict__ pS, float* __restrict__ pS2, int K, int C)
{
    extern __shared__ uint32_t smem_u[];
    const uint32_t sbase = smem_u32(smem_u);
    const uint32_t bAh = sbase;
    const uint32_t bAl = sbase + 2*ASZB*4;
    const uint32_t bBh = sbase + 4*ASZB*4;

    const int tid = threadIdx.x, wid = tid >> 5, lane = tid & 31;
    const int wm = (wid >> 1) * 32;
    const int wn = (wid & 1) * 64;
    const int mw = wid >> 1;
    const int l4 = lane >> 2, lk = lane & 3;
    const int rowA = lane & 15, colA = (lane >> 4) * 4;
    const int rowB = ((lane >> 4) & 1) * 8 + (lane & 7);
    const int colB = ((lane >> 3) & 1) * 4;
    const int m0 = blockIdx.y * 256, c0 = blockIdx.x * TNB;
    const int K2 = K >> 1;

    float acc[2][NFB][4];
    #pragma unroll
    for (int a = 0; a < 2; a++)
        #pragma unroll
        for (int q = 0; q < NFB; q++)
            { acc[a][q][0]=0.f; acc[a][q][1]=0.f; acc[a][q][2]=0.f; acc[a][q][3]=0.f; }

    auto issue = [&](int t) {
        int buf = t & 1;
        #pragma unroll
        for (int j = 0; j < 2; j++) {
            int lin = tid + j*512; int r = lin >> 2, q = lin & 3;
            uint32_t off = (uint32_t)(buf*ASZB + r*RSU + q*4) * 4;
            size_t ao = (size_t)(m0 + r)*K2 + t*16 + q*4;
            cp_async16(bAh + off, Ah_g + ao);
            cp_async16(bAl + off, Al_g + ao);
        }
        {
            int r = tid >> 2, q = tid & 3;
            uint32_t off = (uint32_t)(buf*BSZB + r*RSU + q*4) * 4;
            size_t bo = (size_t)(c0 + r)*K2 + t*16 + q*4;
            cp_async16(bBh + off, Bh_g + bo);
        }
        CP_COMMIT();
    };

    auto compute = [&](int buf) {
        #pragma unroll
        for (int kk = 0; kk < 2; kk++) {
            uint32_t ah[2][4], al[2][4];
            #pragma unroll
            for (int mi = 0; mi < 2; mi++) {
                uint32_t off = (uint32_t)(buf*ASZB + (wm + mi*16 + rowA)*RSU + kk*8 + colA) * 4;
                ldsm4(ah[mi], bAh + off);
                ldsm4(al[mi], bAl + off);
            }
            #pragma unroll
            for (int np = 0; np < NFB/2; np++) {
                uint32_t off = (uint32_t)(buf*BSZB + (wn + np*16 + rowB)*RSU + kk*8 + colB) * 4;
                uint32_t th[4];
                ldsm4(th, bBh + off);
                #pragma unroll
                for (int sub = 0; sub < 2; sub++) {
                    int ni = np*2 + sub;
                    uint32_t bhp[2] = {th[sub*2], th[sub*2+1]};
                    #pragma unroll
                    for (int mi = 0; mi < 2; mi++) {
                        mma_f16(acc[mi][ni], ah[mi], bhp);
                        mma_f16(acc[mi][ni], al[mi], bhp);
                    }
                }
            }
        }
    };

    const int T = K / 32;
    issue(0);
    for (int t = 0; t < T; t++) {
        CP_WAIT0();
        __syncthreads();
        if (t + 1 < T) issue(t + 1);
        compute(t & 1);
    }
    __syncthreads();

    float* sbufS  = (float*)smem_u;
    float* sbufS2 = sbufS + 8*TNB;

    #pragma unroll
    for (int ni = 0; ni < NFB; ni++) {
        int col = c0 + wn + ni*8 + lk*2;
        float2 b2 = *(const float2*)(bias + col);
        float s0 = 0.f, s1 = 0.f, q0 = 0.f, q1 = 0.f;
        #pragma unroll
        for (int mi = 0; mi < 2; mi++) {
            int row = m0 + wm + mi*16 + l4;
            float e0 = acc[mi][ni][0] + b2.x;
            float e1 = acc[mi][ni][1] + b2.y;
            float e2 = acc[mi][ni][2] + b2.x;
            float e3 = acc[mi][ni][3] + b2.y;
            *(float2*)(Y + (size_t)row * C + col)       = make_float2(e0, e1);
            *(float2*)(Y + (size_t)(row + 8) * C + col) = make_float2(e2, e3);
            s0 += e0 + e2; s1 += e1 + e3;
            q0 += e0*e0 + e2*e2; q1 += e1*e1 + e3*e3;
        }
        #pragma unroll
        for (int off = 16; off >= 4; off >>= 1) {
            s0 += __shfl_down_sync(0xffffffffu, s0, off);
            s1 += __shfl_down_sync(0xffffffffu, s1, off);
            q0 += __shfl_down_sync(0xffffffffu, q0, off);
            q1 += __shfl_down_sync(0xffffffffu, q1, off);
        }
        if (lane < 4) {
            int cb = wn + ni*8 + lk*2;
            sbufS [mw*TNB + cb]     = s0;
            sbufS [mw*TNB + cb + 1] = s1;
            sbufS2[mw*TNB + cb]     = q0;
            sbufS2[mw*TNB + cb + 1] = q1;
        }
    }
    __syncthreads();
    if (tid < TNB) {
        float s = 0.f, q = 0.f;
        #pragma unroll
        for (int r = 0; r < 8; r++) { s += sbufS[r*TNB + tid]; q += sbufS2[r*TNB + tid]; }
        pS [blockIdx.y * C + c0 + tid] = s;
        pS2[blockIdx.y * C + c0 + tid] = q;
    }
}

// ---------------- gemm_ps (TN=64) for layer 3 ----------------
__global__ void __launch_bounds__(256, 3) gemm_ps_kernel(
    const uint32_t* __restrict__ Ah_g, const uint32_t* __restrict__ Al_g,
    const uint32_t* __restrict__ Bh_g,
    const float* __restrict__ bias, float* __restrict__ Y,
    float* __restrict__ pS, float* __restrict__ pS2, int K, int C)
{
    extern __shared__ uint32_t smem_u[];
    const uint32_t sbase = smem_u32(smem_u);
    const uint32_t bAh = sbase;
    const uint32_t bAl = sbase + 2*ASZ*4;
    const uint32_t bBh = sbase + 4*ASZ*4;

    const int tid = threadIdx.x, wid = tid >> 5, lane = tid & 31;
    const int wm = (wid >> 1) * 32, wn = (wid & 1) * (TN/2);
    const int mw = wid >> 1;
    const int l4 = lane >> 2, lk = lane & 3;
    const int rowA = lane & 15, colA = (lane >> 4) * 4;
    const int rowB = ((lane >> 4) & 1) * 8 + (lane & 7);
    const int colB = ((lane >> 3) & 1) * 4;
    const int m0 = blockIdx.y * 128, c0 = blockIdx.x * TN;
    const int K2 = K >> 1;

    float acc[2][NFRAG][4];
    #pragma unroll
    for (int a = 0; a < 2; a++)
        #pragma unroll
        for (int q = 0; q < NFRAG; q++)
            { acc[a][q][0]=0.f; acc[a][q][1]=0.f; acc[a][q][2]=0.f; acc[a][q][3]=0.f; }

    auto issue = [&](int t) {
        int buf = t & 1;
        #pragma unroll
        for (int j = 0; j < 2; j++) {
            int lin = tid + j*256; int r = lin >> 2, q = lin & 3;
            uint32_t off = (uint32_t)(buf*ASZ + r*RSU + q*4) * 4;
            size_t ao = (size_t)(m0 + r)*K2 + t*16 + q*4;
            cp_async16(bAh + off, Ah_g + ao);
            cp_async16(bAl + off, Al_g + ao);
        }
        {
            int r = tid >> 2, q = tid & 3;
            uint32_t off = (uint32_t)(buf*BSZ + r*RSU + q*4) * 4;
            size_t bo = (size_t)(c0 + r)*K2 + t*16 + q*4;
            cp_async16(bBh + off, Bh_g + bo);
        }
        CP_COMMIT();
    };

    auto compute = [&](int buf) {
        #pragma unroll
        for (int kk = 0; kk < 2; kk++) {
            uint32_t ah[2][4], al[2][4];
            #pragma unroll
            for (int mi = 0; mi < 2; mi++) {
                uint32_t off = (uint32_t)(buf*ASZ + (wm + mi*16 + rowA)*RSU + kk*8 + colA) * 4;
                ldsm4(ah[mi], bAh + off);
                ldsm4(al[mi], bAl + off);
            }
            #pragma unroll
            for (int np = 0; np < NFRAG/2; np++) {
                uint32_t off = (uint32_t)(buf*BSZ + (wn + np*16 + rowB)*RSU + kk*8 + colB) * 4;
                uint32_t th[4];
                ldsm4(th, bBh + off);
                #pragma unroll
                for (int sub = 0; sub < 2; sub++) {
                    int ni = np*2 + sub;
                    uint32_t bhp[2] = {th[sub*2], th[sub*2+1]};
                    #pragma unroll
                    for (int mi = 0; mi < 2; mi++) {
                        mma_f16(acc[mi][ni], ah[mi], bhp);
                        mma_f16(acc[mi][ni], al[mi], bhp);
                    }
                }
            }
        }
    };

    const int T = K / 32;
    issue(0);
    for (int t = 0; t < T; t++) {
        CP_WAIT0();
        __syncthreads();
        if (t + 1 < T) issue(t + 1);
        compute(t & 1);
    }
    __syncthreads();

    float* sbufS  = (float*)smem_u;
    float* sbufS2 = sbufS + 4*TN;

    #pragma unroll
    for (int ni = 0; ni < NFRAG; ni++) {
        int col = c0 + wn + ni*8 + lk*2;
        float2 b2 = *(const float2*)(bias + col);
        float s0 = 0.f, s1 = 0.f, q0 = 0.f, q1 = 0.f;
        #pragma unroll
        for (int mi = 0; mi < 2; mi++) {
            int row = m0 + wm + mi*16 + l4;
            float e0 = acc[mi][ni][0] + b2.x;
            float e1 = acc[mi][ni][1] + b2.y;
            float e2 = acc[mi][ni][2] + b2.x;
            float e3 = acc[mi][ni][3] + b2.y;
            *(float2*)(Y + (size_t)row * C + col)       = make_float2(e0, e1);
            *(float2*)(Y + (size_t)(row + 8) * C + col) = make_float2(e2, e3);
            s0 += e0 + e2; s1 += e1 + e3;
            q0 += e0*e0 + e2*e2; q1 += e1*e1 + e3*e3;
        }
        #pragma unroll
        for (int off = 16; off >= 4; off >>= 1) {
            s0 += __shfl_down_sync(0xffffffffu, s0, off);
            s1 += __shfl_down_sync(0xffffffffu, s1, off);
            q0 += __shfl_down_sync(0xffffffffu, q0, off);
            q1 += __shfl_down_sync(0xffffffffu, q1, off);
        }
        if (lane < 4) {
            int cb = wn + ni*8 + lk*2;
            sbufS [mw*TN + cb]     = s0;
            sbufS [mw*TN + cb + 1] = s1;
            sbufS2[mw*TN + cb]     = q0;
            sbufS2[mw*TN + cb + 1] = q1;
        }
    }
    __syncthreads();
    if (tid < TN) {
        float s = sbufS [tid] + sbufS [TN + tid] + sbufS [2*TN + tid] + sbufS [3*TN + tid];
        float q = sbufS2[tid] + sbufS2[TN + tid] + sbufS2[2*TN + tid] + sbufS2[3*TN + tid];
        pS [blockIdx.y * C + c0 + tid] = s;
        pS2[blockIdx.y * C + c0 + tid] = q;
    }
}

// ---------------- stats_final ----------------
__global__ void __launch_bounds__(256) stats_final_kernel(
    const float* __restrict__ pS, const float* __restrict__ pS2,
    const float* __restrict__ g, const float* __restrict__ bt,
    int M, int C, int npart, float* __restrict__ scale, float* __restrict__ shift)
{
    const int c = blockIdx.x * 8 + (threadIdx.x >> 5);
    const int j = threadIdx.x & 31;
    float s = 0.f, s2 = 0.f;
    for (int p = j; p < npart; p += 32) {
        s  += pS [p * C + c];
        s2 += pS2[p * C + c];
    }
    #pragma unroll
    for (int off = 16; off > 0; off >>= 1) {
        s  += __shfl_down_sync(0xffffffffu, s,  off);
        s2 += __shfl_down_sync(0xffffffffu, s2, off);
    }
    if (j == 0) {
        float invM = 1.f / (float)M;
        float mean = s * invM;
        float var  = fmaf(-mean, mean, s2 * invM);
        float inv  = rsqrtf(var + EPSV);
        float scv  = g[c] * inv;
        scale[c] = scv;
        shift[c] = fmaf(-mean, scv, bt[c]);
    }
}

// ---------------- bnconvert: BN + leaky -> fp16 hi/lo ----------------
__global__ void __launch_bounds__(256) bnconvert_kernel(
    const float* __restrict__ Y, const float* __restrict__ scale,
    const float* __restrict__ shift, uint32_t* __restrict__ hi, uint32_t* __restrict__ lo,
    int total4, int C4)
{
    int idx = blockIdx.x * blockDim.x + threadIdx.x;
    if (idx >= total4) return;
    int c4 = idx % C4;
    float4 y  = ((const float4*)Y)[idx];
    float4 sc = ((const float4*)scale)[c4];
    float4 sh = ((const float4*)shift)[c4];
    float v[4];
    v[0] = fmaf(y.x, sc.x, sh.x); v[1] = fmaf(y.y, sc.y, sh.y);
    v[2] = fmaf(y.z, sc.z, sh.z); v[3] = fmaf(y.w, sc.w, sh.w);
    #pragma unroll
    for (int q = 0; q < 4; q++) v[q] = v[q] > 0.f ? v[q] : v[q] * SLOPE;
    uint32_t h0, l0, h1, l1;
    split_pair_h(v[0], v[1], h0, l0);
    split_pair_h(v[2], v[3], h1, l1);
    ((uint2*)hi)[idx] = make_uint2(h0, h1);
    ((uint2*)lo)[idx] = make_uint2(l0, l1);
}

// ---------------- final BN apply ----------------
__global__ void __launch_bounds__(256) bnapply_kernel(
    const float* __restrict__ Y, const float* __restrict__ scale,
    const float* __restrict__ shift, float* __restrict__ out, int total4, int C4)
{
    int idx = blockIdx.x * blockDim.x + threadIdx.x;
    if (idx >= total4) return;
    int c4 = idx % C4;
    float4 y  = ((const float4*)Y)[idx];
    float4 sc = ((const float4*)scale)[c4];
    float4 sh = ((const float4*)shift)[c4];
    float4 o;
    o.x = fmaf(y.x, sc.x, sh.x);
    o.y = fmaf(y.y, sc.y, sh.y);
    o.z = fmaf(y.z, sc.z, sh.z);
    o.w = fmaf(y.w, sc.w, sh.w);
    ((float4*)out)[idx] = o;
}

// ---------------- host ----------------
extern "C" void kernel_launch(void* const* d_in, const int* in_sizes, int n_in,
                              void* d_out, int out_size)
{
    const float* x   = (const float*)d_in[0];
    const float* Q   = (const float*)d_in[1];
    const float* W1  = (const float*)d_in[2];
    const float* b1  = (const float*)d_in[3];
    const float* g1  = (const float*)d_in[4];
    const float* bt1 = (const float*)d_in[5];
    const float* W2  = (const float*)d_in[6];
    const float* b2  = (const float*)d_in[7];
    const float* g2  = (const float*)d_in[8];
    const float* bt2 = (const float*)d_in[9];
    const float* W3  = (const float*)d_in[10];
    const float* b3  = (const float*)d_in[11];
    const float* g3  = (const float*)d_in[12];
    const float* bt3 = (const float*)d_in[13];
    float* out = (float*)d_out;

    float *En, *Y1, *Y2, *Y3, *pS, *pS2, *scale, *shift;
    uint32_t *Xth, *Ghi, *Glo, *Vhi, *Vlo, *Axhi, *Axlo;
    uint32_t *W1h, *W2h, *W3h;
    cudaGetSymbolAddress((void**)&En,   g_En);
    cudaGetSymbolAddress((void**)&Xth,  g_Xth);
    cudaGetSymbolAddress((void**)&Ghi,  g_Ghi);   cudaGetSymbolAddress((void**)&Glo,  g_Glo);
    cudaGetSymbolAddress((void**)&Vhi,  g_Vhi);   cudaGetSymbolAddress((void**)&Vlo,  g_Vlo);
    cudaGetSymbolAddress((void**)&Axhi, g_Axhi);  cudaGetSymbolAddress((void**)&Axlo, g_Axlo);
    cudaGetSymbolAddress((void**)&W1h,  g_W1h);
    cudaGetSymbolAddress((void**)&W2h,  g_W2h);
    cudaGetSymbolAddress((void**)&W3h,  g_W3h);
    cudaGetSymbolAddress((void**)&Y1, g_Y1);
    cudaGetSymbolAddress((void**)&Y2, g_Y2);
    cudaGetSymbolAddress((void**)&Y3, g_Y3);
    cudaGetSymbolAddress((void**)&pS, g_pS);      cudaGetSymbolAddress((void**)&pS2, g_pS2);
    cudaGetSymbolAddress((void**)&scale, g_scale); cudaGetSymbolAddress((void**)&shift, g_shift);

    const int SMEM64  = (2*ASZ  + BSZ ) * 2 * 4;   // 51200 B
    const int SMEMBIG = (2*ASZB + BSZB) * 2 * 4;   // 102400 B
    cudaFuncSetAttribute(vgemm_kernel,    cudaFuncAttributeMaxDynamicSharedMemorySize, SMEM64);
    cudaFuncSetAttribute(gemm_ps_kernel,  cudaFuncAttributeMaxDynamicSharedMemorySize, SMEM64);
    cudaFuncSetAttribute(gemm_big_kernel, cudaFuncAttributeMaxDynamicSharedMemorySize, SMEMBIG);

    // 1) prep + buildG
    prep_kernel<<<168, 256>>>(x, Q, En, Xth, W1, W1h, W2, W2h, W3, W3h);
    buildG_kernel<<<128, 256>>>(x, Ghi, Glo);

    // 2) V = En .* (G @ Xt^T) - pos
    vgemm_kernel<<<dim3(4, 4, 16), 256, SMEM64>>>(Ghi, Glo, Xth, En, x, Vhi, Vlo);

    // 3) layer 1 (big tiles, 32 partials)
    gemm_big_kernel<<<dim3(NH/128, MROWS/256), 512, SMEMBIG>>>(
        Vhi, Vlo, W1h, b1, Y1, pS, pS2, VDIM, NH);
    stats_final_kernel<<<NH/8, 256>>>(pS, pS2, g1, bt1, MROWS, NH, 32, scale, shift);
    bnconvert_kernel<<<(MROWS*NH/4 + 255)/256, 256>>>(Y1, scale, shift, Axhi, Axlo, MROWS*NH/4, NH/4);

    // 4) layer 2
    gemm_big_kernel<<<dim3(NH/128, MROWS/256), 512, SMEMBIG>>>(
        Axhi, Axlo, W2h, b2, Y2, pS, pS2, NH, NH);
    stats_final_kernel<<<NH/8, 256>>>(pS, pS2, g2, bt2, MROWS, NH, 32, scale, shift);
    bnconvert_kernel<<<(MROWS*NH/4 + 255)/256, 256>>>(Y2, scale, shift, Axhi, Axlo, MROWS*NH/4, NH/4);

    // 5) layer 3 (64 partials)
    gemm_ps_kernel<<<dim3(NO/64, MROWS/128), 256, SMEM64>>>(
        Axhi, Axlo, W3h, b3, Y3, pS, pS2, NH, NO);
    stats_final_kernel<<<NO/8, 256>>>(pS, pS2, g3, bt3, MROWS, NO, 64, scale, shift);

    // 6) final BN apply -> out
    int total4 = MROWS * NO / 4;
    bnapply_kernel<<<(total4 + 255)/256, 256>>>(Y3, scale, shift, out, total4, NO/4);
}

// round 14
// speedup vs baseline: 1.3985x; 1.0824x over previous
#include <cuda_runtime.h>
#include <cuda_fp16.h>
#include <cstdint>
#include <math.h>

#define BATCH 16
#define SEQ   512
#define NI    32
#define NHEAD 8
#define NH    512
#define NO    64
#define MROWS (BATCH*SEQ)      // 8192
#define VDIM  (NHEAD*NI)       // 256
#define EPSV  1e-5f
#define SLOPE 0.05f
#define NPART 64

// ---------------- scratch ----------------
__device__ float    g_En  [16*8*512];
__device__ uint32_t g_Xthi[(size_t)16*256*256], g_Xtlo[(size_t)16*256*256];  // Xt hi/lo (exact)
__device__ uint32_t g_Gh  [(size_t)16*512*256];                              // G single fp16
__device__ uint32_t g_Vh  [(size_t)8192*128];                                // V single fp16
__device__ uint32_t g_W1hi[512*128], g_W1lo[512*128];
__device__ uint32_t g_W2hi[512*256], g_W2lo[512*256];
__device__ uint32_t g_W3hi[64*256],  g_W3lo[64*256];
__device__ uint32_t g_Axh [(size_t)8192*256];                                // activations single fp16
__device__ float g_Y1[(size_t)MROWS * NH];
__device__ float g_Y2[(size_t)MROWS * NH];
__device__ float g_Y3[(size_t)MROWS * NO];
__device__ float g_pS [NPART * NH];
__device__ float g_pS2[NPART * NH];

// ---------------- helpers ----------------
__device__ __forceinline__ void split_pair_h(float v0, float v1, uint32_t& hi, uint32_t& lo) {
    __half h0 = __float2half(v0);
    __half h1 = __float2half(v1);
    float r0 = v0 - __half2float(h0);
    float r1 = v1 - __half2float(h1);
    __half l0 = __float2half(r0);
    __half l1 = __float2half(r1);
    hi = ((uint32_t)__half_as_ushort(h1) << 16) | __half_as_ushort(h0);
    lo = ((uint32_t)__half_as_ushort(l1) << 16) | __half_as_ushort(l0);
}
__device__ __forceinline__ uint32_t pack_h(float v0, float v1) {
    __half h0 = __float2half(v0);
    __half h1 = __float2half(v1);
    return ((uint32_t)__half_as_ushort(h1) << 16) | __half_as_ushort(h0);
}

__device__ __forceinline__ void mma_f16(float* d, const uint32_t* a, const uint32_t* b) {
    asm volatile(
        "mma.sync.aligned.m16n8k16.row.col.f32.f16.f16.f32 "
        "{%0,%1,%2,%3}, {%4,%5,%6,%7}, {%8,%9}, {%0,%1,%2,%3};"
        : "+f"(d[0]), "+f"(d[1]), "+f"(d[2]), "+f"(d[3])
        : "r"(a[0]), "r"(a[1]), "r"(a[2]), "r"(a[3]), "r"(b[0]), "r"(b[1]));
}

__device__ __forceinline__ void ldsm4(uint32_t* r, uint32_t addr) {
    asm volatile("ldmatrix.sync.aligned.m8n8.x4.shared.b16 {%0,%1,%2,%3}, [%4];"
        : "=r"(r[0]), "=r"(r[1]), "=r"(r[2]), "=r"(r[3]) : "r"(addr));
}

__device__ __forceinline__ uint32_t smem_u32(const void* p) {
    uint32_t a;
    asm("{ .reg .u64 t; cvta.to.shared.u64 t, %1; cvt.u32.u64 %0, t; }" : "=r"(a) : "l"(p));
    return a;
}
__device__ __forceinline__ void cp_async16(uint32_t saddr, const void* gptr) {
    asm volatile("cp.async.cg.shared.global [%0], [%1], 16;" :: "r"(saddr), "l"(gptr));
}
#define CP_COMMIT() asm volatile("cp.async.commit_group;" ::: "memory")
#define CP_WAIT0()  asm volatile("cp.async.wait_group 0;" ::: "memory")

// ---------------- prep_all: En/Xt(hi,lo) + W splits + buildG(single) ----------------
__global__ void __launch_bounds__(256) prep_all_kernel(
    const float* __restrict__ x, const float* __restrict__ Q,
    float* __restrict__ En,
    uint32_t* __restrict__ Xthi, uint32_t* __restrict__ Xtlo,
    const float* __restrict__ W1, uint32_t* __restrict__ W1hi, uint32_t* __restrict__ W1lo,
    const float* __restrict__ W2, uint32_t* __restrict__ W2hi, uint32_t* __restrict__ W2lo,
    const float* __restrict__ W3, uint32_t* __restrict__ W3hi, uint32_t* __restrict__ W3lo,
    uint32_t* __restrict__ Gh)
{
    const int blk = blockIdx.x;
    const int tid = threadIdx.x;

    __shared__ float sEm[8][128];
    __shared__ float sQ[8][4];
    __shared__ uint32_t shi[256][8], slo[256][8];
    __shared__ float pn3[64][5];
    __shared__ float pm3[128][4];

    if (blk >= 168) {
        // ---- buildG: G[b][n][m] = exp(-|pn-pm|^2), single fp16 ----
        const int g  = blk - 168;
        const int b  = g >> 3, nt = g & 7;
        const int n = tid & 63, mq = tid >> 6;

        if (tid < 64) {
            const float* xp = x + ((size_t)b*512 + nt*64 + tid)*32;
            pn3[tid][0] = xp[0]; pn3[tid][1] = xp[1]; pn3[tid][2] = xp[2];
        }
        for (int mc = 0; mc < 4; mc++) {
            __syncthreads();
            if (tid < 128) {
                const float* xp = x + ((size_t)b*512 + mc*128 + tid)*32;
                pm3[tid][0] = xp[0]; pm3[tid][1] = xp[1]; pm3[tid][2] = xp[2];
            }
            __syncthreads();
            float px = pn3[n][0], py = pn3[n][1], pz = pn3[n][2];
            uint32_t outh[16];
            #pragma unroll
            for (int j = 0; j < 16; j++) {
                int ml = mq*32 + j*2;
                float dx0 = px - pm3[ml][0],   dy0 = py - pm3[ml][1],   dz0 = pz - pm3[ml][2];
                float dx1 = px - pm3[ml+1][0], dy1 = py - pm3[ml+1][1], dz1 = pz - pm3[ml+1][2];
                float e0 = __expf(-(dx0*dx0 + dy0*dy0 + dz0*dz0));
                float e1 = __expf(-(dx1*dx1 + dy1*dy1 + dz1*dz1));
                outh[j] = pack_h(e0, e1);
            }
            size_t base = ((size_t)b*512 + nt*64 + n)*256 + mc*64 + mq*16;
            #pragma unroll
            for (int j4 = 0; j4 < 4; j4++)
                ((uint4*)(Gh + base))[j4] = make_uint4(outh[j4*4], outh[j4*4+1], outh[j4*4+2], outh[j4*4+3]);
        }
        return;
    }

    if (blk >= 64) {
        // ---- W fp32 -> fp16 hi/lo ----
        int widx = blk - 64;
        const float* src; uint32_t* hi; uint32_t* lo; int base;
        if (widx < 32)      { src = W1; hi = W1hi; lo = W1lo; base = widx * 2048; }
        else if (widx < 96) { src = W2; hi = W2hi; lo = W2lo; base = (widx - 32) * 2048; }
        else                { src = W3; hi = W3hi; lo = W3lo; base = (widx - 96) * 2048; }
        int p = base + tid;
        #pragma unroll
        for (int j = 0; j < 8; j++, p += 256) {
            float2 v = ((const float2*)src)[p];
            uint32_t h, l; split_pair_h(v.x, v.y, h, l);
            hi[p] = h; lo[p] = l;
        }
        return;
    }

    // ---- En tables + Xt build (hi/lo pair, exact) ----
    const int b = blk >> 2, chunk = blk & 3;

    if (tid < 8) {
        float a = Q[tid*3+0], bq = Q[tid*3+1], cq = Q[tid*3+2];
        sQ[tid][0] = a; sQ[tid][1] = bq; sQ[tid][2] = cq;
        sQ[tid][3] = a*a + bq*bq + cq*cq;
    }
    __syncthreads();

    if (tid < 128) {
        int m = chunk*128 + tid;
        const float* xp = x + ((size_t)b*512 + m)*32;
        float px = xp[0], py = xp[1], pz = xp[2];
        #pragma unroll
        for (int h = 0; h < 8; h++) {
            float dot = px*sQ[h][0] + py*sQ[h][1] + pz*sQ[h][2];
            float em = __expf(-2.f*dot);
            float en = __expf(2.f*dot - sQ[h][3]);
            sEm[h][tid] = em;
            En[((size_t)b*8 + h)*512 + m] = en;
        }
    }
    __syncthreads();

    const int c = tid, h = c >> 5, i = c & 31;
    for (int grp = 0; grp < 8; grp++) {
        #pragma unroll
        for (int j = 0; j < 8; j++) {
            int mloc = (grp*8 + j)*2;
            int m = chunk*128 + mloc;
            float v0 = sEm[h][mloc]   * x[((size_t)b*512 + m  )*32 + i];
            float v1 = sEm[h][mloc+1] * x[((size_t)b*512 + m+1)*32 + i];
            uint32_t hh, ll; split_pair_h(v0, v1, hh, ll);
            shi[c][j] = hh; slo[c][j] = ll;
        }
        __syncthreads();
        int cc = tid >> 3, j2 = tid & 7;
        #pragma unroll
        for (int rep = 0; rep < 8; rep++) {
            int ccc = cc + rep*32;
            size_t addr = ((size_t)b*256 + ccc)*256 + chunk*64 + grp*8 + j2;
            Xthi[addr] = shi[ccc][j2];
            Xtlo[addr] = slo[ccc][j2];
        }
        __syncthreads();
    }
}

// ================= GEMM machinery: A single fp16, B hi/lo pair, 2 MMAs =================
#define RSU 20
#define TN  64
#define NFRAG (TN/16)
#define ASZ (128*RSU)
#define BSZ (TN*RSU)

// ---------------- vgemm: V = En .* (G @ Xt^T) - pos ----------------
__global__ void __launch_bounds__(256, 3) vgemm_kernel(
    const uint32_t* __restrict__ Gh_g,
    const uint32_t* __restrict__ Bhi_g, const uint32_t* __restrict__ Blo_g,
    const float* __restrict__ En, const float* __restrict__ x,
    uint32_t* __restrict__ Vh)
{
    constexpr int KE = 512, K2 = KE/2;
    extern __shared__ uint32_t smem_u[];
    const uint32_t sbase = smem_u32(smem_u);
    const uint32_t bA  = sbase;
    const uint32_t bBh = sbase + 2*ASZ*4;
    const uint32_t bBl = sbase + (2*ASZ + 2*BSZ)*4;

    const int tid = threadIdx.x, wid = tid >> 5, lane = tid & 31;
    const int wm = (wid >> 1) * 32, wn = (wid & 1) * (TN/2);
    const int l4 = lane >> 2, lk = lane & 3;
    const int rowA = lane & 15, colA = (lane >> 4) * 4;
    const int rowB = ((lane >> 4) & 1) * 8 + (lane & 7);
    const int colB = ((lane >> 3) & 1) * 4;
    const int b = blockIdx.z;
    const int m0 = blockIdx.y * 128, c0 = blockIdx.x * TN;

    const uint32_t* A_g  = Gh_g + (size_t)b*512*K2;
    const uint32_t* Bh_g = Bhi_g + (size_t)b*256*K2;
    const uint32_t* Bl_g = Blo_g + (size_t)b*256*K2;

    float acc[2][NFRAG][4];
    #pragma unroll
    for (int a = 0; a < 2; a++)
        #pragma unroll
        for (int q = 0; q < NFRAG; q++)
            { acc[a][q][0]=0.f; acc[a][q][1]=0.f; acc[a][q][2]=0.f; acc[a][q][3]=0.f; }

    auto issue = [&](int t) {
        int buf = t & 1;
        #pragma unroll
        for (int j = 0; j < 2; j++) {
            int lin = tid + j*256; int r = lin >> 2, q = lin & 3;
            uint32_t off = (uint32_t)(buf*ASZ + r*RSU + q*4) * 4;
            size_t ao = (size_t)(m0 + r)*K2 + t*16 + q*4;
            cp_async16(bA + off, A_g + ao);
        }
        {
            int r = tid >> 2, q = tid & 3;
            uint32_t off = (uint32_t)(buf*BSZ + r*RSU + q*4) * 4;
            size_t bo = (size_t)(c0 + r)*K2 + t*16 + q*4;
            cp_async16(bBh + off, Bh_g + bo);
            cp_async16(bBl + off, Bl_g + bo);
        }
        CP_COMMIT();
    };

    auto compute = [&](int buf) {
        #pragma unroll
        for (int kk = 0; kk < 2; kk++) {
            uint32_t ah[2][4];
            #pragma unroll
            for (int mi = 0; mi < 2; mi++) {
                uint32_t off = (uint32_t)(buf*ASZ + (wm + mi*16 + rowA)*RSU + kk*8 + colA) * 4;
                ldsm4(ah[mi], bA + off);
            }
            #pragma unroll
            for (int np = 0; np < NFRAG/2; np++) {
                uint32_t off = (uint32_t)(buf*BSZ + (wn + np*16 + rowB)*RSU + kk*8 + colB) * 4;
                uint32_t th[4], tl[4];
                ldsm4(th, bBh + off);
                ldsm4(tl, bBl + off);
                #pragma unroll
                for (int sub = 0; sub < 2; sub++) {
                    int ni = np*2 + sub;
                    uint32_t bhp[2] = {th[sub*2], th[sub*2+1]};
                    uint32_t blp[2] = {tl[sub*2], tl[sub*2+1]};
                    #pragma unroll
                    for (int mi = 0; mi < 2; mi++) {
                        mma_f16(acc[mi][ni], ah[mi], bhp);
                        mma_f16(acc[mi][ni], ah[mi], blp);
                    }
                }
            }
        }
    };

    const int T = KE / 32;
    issue(0);
    for (int t = 0; t < T; t++) {
        CP_WAIT0();
        __syncthreads();
        if (t + 1 < T) issue(t + 1);
        compute(t & 1);
    }

    #pragma unroll
    for (int mi = 0; mi < 2; mi++) {
        #pragma unroll
        for (int ni = 0; ni < NFRAG; ni++) {
            int n0 = m0 + wm + mi*16 + l4;
            int cc = c0 + wn + ni*8 + lk*2;
            int h = cc >> 5, il = cc & 31;
            float en0 = En[((size_t)b*8 + h)*512 + n0];
            float en1 = En[((size_t)b*8 + h)*512 + n0 + 8];
            float v00 = acc[mi][ni][0]*en0, v01 = acc[mi][ni][1]*en0;
            float v10 = acc[mi][ni][2]*en1, v11 = acc[mi][ni][3]*en1;
            if (il < 3) {
                v00 -= x[((size_t)b*512 + n0  )*32 + il];
                v10 -= x[((size_t)b*512 + n0+8)*32 + il];
            }
            if (il + 1 < 3) {
                v01 -= x[((size_t)b*512 + n0  )*32 + il + 1];
                v11 -= x[((size_t)b*512 + n0+8)*32 + il + 1];
            }
            size_t r0 = ((size_t)b*512 + n0)*128 + (cc >> 1);
            size_t r1 = ((size_t)b*512 + n0 + 8)*128 + (cc >> 1);
            Vh[r0] = pack_h(v00, v01);
            Vh[r1] = pack_h(v10, v11);
        }
    }
}

// ---------------- gemm_big: 512 threads, TM=256 x TNB=128, fused stats ----------------
#define TNB  128
#define NFB  (TNB/16)
#define ASZB (256*RSU)
#define BSZB (128*RSU)

__global__ void __launch_bounds__(512, 1) gemm_big_kernel(
    const uint32_t* __restrict__ A_g,
    const uint32_t* __restrict__ Bh_g, const uint32_t* __restrict__ Bl_g,
    const float* __restrict__ bias, float* __restrict__ Y,
    float* __restrict__ pS, float* __restrict__ pS2, int K, int C)
{
    extern __shared__ uint32_t smem_u[];
    const uint32_t sbase = smem_u32(smem_u);
    const uint32_t bA  = sbase;
    const uint32_t bBh = sbase + 2*ASZB*4;
    const uint32_t bBl = sbase + (2*ASZB + 2*BSZB)*4;

    const int tid = threadIdx.x, wid = tid >> 5, lane = tid & 31;
    const int wm = (wid >> 1) * 32;
    const int wn = (wid & 1) * 64;
    const int mw = wid >> 1;
    const int l4 = lane >> 2, lk = lane & 3;
    const int rowA = lane & 15, colA = (lane >> 4) * 4;
    const int rowB = ((lane >> 4) & 1) * 8 + (lane & 7);
    const int colB = ((lane >> 3) & 1) * 4;
    const int m0 = blockIdx.y * 256, c0 = blockIdx.x * TNB;
    const int K2 = K >> 1;

    float acc[2][NFB][4];
    #pragma unroll
    for (int a = 0; a < 2; a++)
        #pragma unroll
        for (int q = 0; q < NFB; q++)
            { acc[a][q][0]=0.f; acc[a][q][1]=0.f; acc[a][q][2]=0.f; acc[a][q][3]=0.f; }

    auto issue = [&](int t) {
        int buf = t & 1;
        #pragma unroll
        for (int j = 0; j < 2; j++) {
            int lin = tid + j*512; int r = lin >> 2, q = lin & 3;
            uint32_t off = (uint32_t)(buf*ASZB + r*RSU + q*4) * 4;
            size_t ao = (size_t)(m0 + r)*K2 + t*16 + q*4;
            cp_async16(bA + off, A_g + ao);
        }
        {
            int r = tid >> 2, q = tid & 3;
            uint32_t off = (uint32_t)(buf*BSZB + r*RSU + q*4) * 4;
            size_t bo = (size_t)(c0 + r)*K2 + t*16 + q*4;
            cp_async16(bBh + off, Bh_g + bo);
            cp_async16(bBl + off, Bl_g + bo);
        }
        CP_COMMIT();
    };

    auto compute = [&](int buf) {
        #pragma unroll
        for (int kk = 0; kk < 2; kk++) {
            uint32_t ah[2][4];
            #pragma unroll
            for (int mi = 0; mi < 2; mi++) {
                uint32_t off = (uint32_t)(buf*ASZB + (wm + mi*16 + rowA)*RSU + kk*8 + colA) * 4;
                ldsm4(ah[mi], bA + off);
            }
            #pragma unroll
            for (int np = 0; np < NFB/2; np++) {
                uint32_t off = (uint32_t)(buf*BSZB + (wn + np*16 + rowB)*RSU + kk*8 + colB) * 4;
                uint32_t th[4], tl[4];
                ldsm4(th, bBh + off);
                ldsm4(tl, bBl + off);
                #pragma unroll
                for (int sub = 0; sub < 2; sub++) {
                    int ni = np*2 + sub;
                    uint32_t bhp[2] = {th[sub*2], th[sub*2+1]};
                    uint32_t blp[2] = {tl[sub*2], tl[sub*2+1]};
                    #pragma unroll
                    for (int mi = 0; mi < 2; mi++) {
                        mma_f16(acc[mi][ni], ah[mi], bhp);
                        mma_f16(acc[mi][ni], ah[mi], blp);
                    }
                }
            }
        }
    };

    const int T = K / 32;
    issue(0);
    for (int t = 0; t < T; t++) {
        CP_WAIT0();
        __syncthreads();
        if (t + 1 < T) issue(t + 1);
        compute(t & 1);
    }
    __syncthreads();

    float* sbufS  = (float*)smem_u;
    float* sbufS2 = sbufS + 8*TNB;

    #pragma unroll
    for (int ni = 0; ni < NFB; ni++) {
        int col = c0 + wn + ni*8 + lk*2;
        float2 b2 = *(const float2*)(bias + col);
        float s0 = 0.f, s1 = 0.f, q0 = 0.f, q1 = 0.f;
        #pragma unroll
        for (int mi = 0; mi < 2; mi++) {
            int row = m0 + wm + mi*16 + l4;
            float e0 = acc[mi][ni][0] + b2.x;
            float e1 = acc[mi][ni][1] + b2.y;
            float e2 = acc[mi][ni][2] + b2.x;
            float e3 = acc[mi][ni][3] + b2.y;
            *(float2*)(Y + (size_t)row * C + col)       = make_float2(e0, e1);
            *(float2*)(Y + (size_t)(row + 8) * C + col) = make_float2(e2, e3);
            s0 += e0 + e2; s1 += e1 + e3;
            q0 += e0*e0 + e2*e2; q1 += e1*e1 + e3*e3;
        }
        #pragma unroll
        for (int off = 16; off >= 4; off >>= 1) {
            s0 += __shfl_down_sync(0xffffffffu, s0, off);
            s1 += __shfl_down_sync(0xffffffffu, s1, off);
            q0 += __shfl_down_sync(0xffffffffu, q0, off);
            q1 += __shfl_down_sync(0xffffffffu, q1, off);
        }
        if (lane < 4) {
            int cb = wn + ni*8 + lk*2;
            sbufS [mw*TNB + cb]     = s0;
            sbufS [mw*TNB + cb + 1] = s1;
            sbufS2[mw*TNB + cb]     = q0;
            sbufS2[mw*TNB + cb + 1] = q1;
        }
    }
    __syncthreads();
    if (tid < TNB) {
        float s = 0.f, q = 0.f;
        #pragma unroll
        for (int r = 0; r < 8; r++) { s += sbufS[r*TNB + tid]; q += sbufS2[r*TNB + tid]; }
        pS [blockIdx.y * C + c0 + tid] = s;
        pS2[blockIdx.y * C + c0 + tid] = q;
    }
}

// ---------------- gemm_ps (TN=64) for layer 3 ----------------
__global__ void __launch_bounds__(256, 3) gemm_ps_kernel(
    const uint32_t* __restrict__ A_g,
    const uint32_t* __restrict__ Bh_g, const uint32_t* __restrict__ Bl_g,
    const float* __restrict__ bias, float* __restrict__ Y,
    float* __restrict__ pS, float* __restrict__ pS2, int K, int C)
{
    extern __shared__ uint32_t smem_u[];
    const uint32_t sbase = smem_u32(smem_u);
    const uint32_t bA  = sbase;
    const uint32_t bBh = sbase + 2*ASZ*4;
    const uint32_t bBl = sbase + (2*ASZ + 2*BSZ)*4;

    const int tid = threadIdx.x, wid = tid >> 5, lane = tid & 31;
    const int wm = (wid >> 1) * 32, wn = (wid & 1) * (TN/2);
    const int mw = wid >> 1;
    const int l4 = lane >> 2, lk = lane & 3;
    const int rowA = lane & 15, colA = (lane >> 4) * 4;
    const int rowB = ((lane >> 4) & 1) * 8 + (lane & 7);
    const int colB = ((lane >> 3) & 1) * 4;
    const int m0 = blockIdx.y * 128, c0 = blockIdx.x * TN;
    const int K2 = K >> 1;

    float acc[2][NFRAG][4];
    #pragma unroll
    for (int a = 0; a < 2; a++)
        #pragma unroll
        for (int q = 0; q < NFRAG; q++)
            { acc[a][q][0]=0.f; acc[a][q][1]=0.f; acc[a][q][2]=0.f; acc[a][q][3]=0.f; }

    auto issue = [&](int t) {
        int buf = t & 1;
        #pragma unroll
        for (int j = 0; j < 2; j++) {
            int lin = tid + j*256; int r = lin >> 2, q = lin & 3;
            uint32_t off = (uint32_t)(buf*ASZ + r*RSU + q*4) * 4;
            size_t ao = (size_t)(m0 + r)*K2 + t*16 + q*4;
            cp_async16(bA + off, A_g + ao);
        }
        {
            int r = tid >> 2, q = tid & 3;
            uint32_t off = (uint32_t)(buf*BSZ + r*RSU + q*4) * 4;
            size_t bo = (size_t)(c0 + r)*K2 + t*16 + q*4;
            cp_async16(bBh + off, Bh_g + bo);
            cp_async16(bBl + off, Bl_g + bo);
        }
        CP_COMMIT();
    };

    auto compute = [&](int buf) {
        #pragma unroll
        for (int kk = 0; kk < 2; kk++) {
            uint32_t ah[2][4];
            #pragma unroll
            for (int mi = 0; mi < 2; mi++) {
                uint32_t off = (uint32_t)(buf*ASZ + (wm + mi*16 + rowA)*RSU + kk*8 + colA) * 4;
                ldsm4(ah[mi], bA + off);
            }
            #pragma unroll
            for (int np = 0; np < NFRAG/2; np++) {
                uint32_t off = (uint32_t)(buf*BSZ + (wn + np*16 + rowB)*RSU + kk*8 + colB) * 4;
                uint32_t th[4], tl[4];
                ldsm4(th, bBh + off);
                ldsm4(tl, bBl + off);
                #pragma unroll
                for (int sub = 0; sub < 2; sub++) {
                    int ni = np*2 + sub;
                    uint32_t bhp[2] = {th[sub*2], th[sub*2+1]};
                    uint32_t blp[2] = {tl[sub*2], tl[sub*2+1]};
                    #pragma unroll
                    for (int mi = 0; mi < 2; mi++) {
                        mma_f16(acc[mi][ni], ah[mi], bhp);
                        mma_f16(acc[mi][ni], ah[mi], blp);
                    }
                }
            }
        }
    };

    const int T = K / 32;
    issue(0);
    for (int t = 0; t < T; t++) {
        CP_WAIT0();
        __syncthreads();
        if (t + 1 < T) issue(t + 1);
        compute(t & 1);
    }
    __syncthreads();

    float* sbufS  = (float*)smem_u;
    float* sbufS2 = sbufS + 4*TN;

    #pragma unroll
    for (int ni = 0; ni < NFRAG; ni++) {
        int col = c0 + wn + ni*8 + lk*2;
        float2 b2 = *(const float2*)(bias + col);
        float s0 = 0.f, s1 = 0.f, q0 = 0.f, q1 = 0.f;
        #pragma unroll
        for (int mi = 0; mi < 2; mi++) {
            int row = m0 + wm + mi*16 + l4;
            float e0 = acc[mi][ni][0] + b2.x;
            float e1 = acc[mi][ni][1] + b2.y;
            float e2 = acc[mi][ni][2] + b2.x;
            float e3 = acc[mi][ni][3] + b2.y;
            *(float2*)(Y + (size_t)row * C + col)       = make_float2(e0, e1);
            *(float2*)(Y + (size_t)(row + 8) * C + col) = make_float2(e2, e3);
            s0 += e0 + e2; s1 += e1 + e3;
            q0 += e0*e0 + e2*e2; q1 += e1*e1 + e3*e3;
        }
        #pragma unroll
        for (int off = 16; off >= 4; off >>= 1) {
            s0 += __shfl_down_sync(0xffffffffu, s0, off);
            s1 += __shfl_down_sync(0xffffffffu, s1, off);
            q0 += __shfl_down_sync(0xffffffffu, q0, off);
            q1 += __shfl_down_sync(0xffffffffu, q1, off);
        }
        if (lane < 4) {
            int cb = wn + ni*8 + lk*2;
            sbufS [mw*TN + cb]     = s0;
            sbufS [mw*TN + cb + 1] = s1;
            sbufS2[mw*TN + cb]     = q0;
            sbufS2[mw*TN + cb + 1] = q1;
        }
    }
    __syncthreads();
    if (tid < TN) {
        float s = sbufS [tid] + sbufS [TN + tid] + sbufS [2*TN + tid] + sbufS [3*TN + tid];
        float q = sbufS2[tid] + sbufS2[TN + tid] + sbufS2[2*TN + tid] + sbufS2[3*TN + tid];
        pS [blockIdx.y * C + c0 + tid] = s;
        pS2[blockIdx.y * C + c0 + tid] = q;
    }
}

// ---------------- bnstats_convert: fused stats finalize + BN + leaky -> single fp16 ----------------
// grid (C/128=4, MROWS/128=64); block 256. Head reduces 32 partials for 128 cols.
__global__ void __launch_bounds__(256) bnstats_convert_kernel(
    const float* __restrict__ Y, const float* __restrict__ pS, const float* __restrict__ pS2,
    const float* __restrict__ g, const float* __restrict__ bt,
    uint32_t* __restrict__ Ah)
{
    __shared__ float ssc[128], ssh[128];
    const int tid = threadIdx.x;
    const int c0 = blockIdx.x * 128;
    const int r0 = blockIdx.y * 128;

    if (tid < 128) {
        int c = c0 + tid;
        float s = 0.f, q = 0.f;
        #pragma unroll 8
        for (int p = 0; p < 32; p++) {
            s += pS [p*512 + c];
            q += pS2[p*512 + c];
        }
        float mean = s * (1.f/8192.f);
        float var  = fmaf(-mean, mean, q * (1.f/8192.f));
        float inv  = rsqrtf(var + EPSV);
        float scv  = g[c] * inv;
        ssc[tid] = scv;
        ssh[tid] = fmaf(-mean, scv, bt[c]);
    }
    __syncthreads();

    #pragma unroll 4
    for (int it = 0; it < 16; it++) {
        int idx = it*256 + tid;
        int row = idx >> 5, c4 = idx & 31;
        float4 y  = ((const float4*)Y)[(size_t)(r0 + row)*128 + blockIdx.x*32 + c4];
        float4 sc = ((const float4*)ssc)[c4];
        float4 sh = ((const float4*)ssh)[c4];
        float v0 = fmaf(y.x, sc.x, sh.x);
        float v1 = fmaf(y.y, sc.y, sh.y);
        float v2 = fmaf(y.z, sc.z, sh.z);
        float v3 = fmaf(y.w, sc.w, sh.w);
        v0 = v0 > 0.f ? v0 : v0 * SLOPE;
        v1 = v1 > 0.f ? v1 : v1 * SLOPE;
        v2 = v2 > 0.f ? v2 : v2 * SLOPE;
        v3 = v3 > 0.f ? v3 : v3 * SLOPE;
        ((uint2*)Ah)[(size_t)(r0 + row)*128 + blockIdx.x*32 + c4] =
            make_uint2(pack_h(v0, v1), pack_h(v2, v3));
    }
}

// ---------------- bnstats_apply: stats finalize + BN -> out (C=64, 64 partials) ----------------
__global__ void __launch_bounds__(256) bnstats_apply_kernel(
    const float* __restrict__ Y, const float* __restrict__ pS, const float* __restrict__ pS2,
    const float* __restrict__ g, const float* __restrict__ bt, float* __restrict__ out)
{
    __shared__ float ssc[64], ssh[64];
    const int tid = threadIdx.x;
    if (tid < 64) {
        float s = 0.f, q = 0.f;
        #pragma unroll 8
        for (int j = 0; j < 64; j++) {
            s += pS [j*64 + tid];
            q += pS2[j*64 + tid];
        }
        float mean = s * (1.f/8192.f);
        float var  = fmaf(-mean, mean, q * (1.f/8192.f));
        float inv  = rsqrtf(var + EPSV);
        float scv  = g[tid] * inv;
        ssc[tid] = scv;
        ssh[tid] = fmaf(-mean, scv, bt[tid]);
    }
    __syncthreads();

    size_t base = (size_t)blockIdx.x * 2048;
    #pragma unroll 4
    for (int it = 0; it < 8; it++) {
        int idx = it*256 + tid;
        int c4 = idx & 15;
        float4 y  = ((const float4*)Y)[base + idx];
        float4 sc = ((const float4*)ssc)[c4];
        float4 sh = ((const float4*)ssh)[c4];
        float4 o;
        o.x = fmaf(y.x, sc.x, sh.x);
        o.y = fmaf(y.y, sc.y, sh.y);
        o.z = fmaf(y.z, sc.z, sh.z);
        o.w = fmaf(y.w, sc.w, sh.w);
        ((float4*)out)[base + idx] = o;
    }
}

// ---------------- host ----------------
extern "C" void kernel_launch(void* const* d_in, const int* in_sizes, int n_in,
                              void* d_out, int out_size)
{
    const float* x   = (const float*)d_in[0];
    const float* Q   = (const float*)d_in[1];
    const float* W1  = (const float*)d_in[2];
    const float* b1  = (const float*)d_in[3];
    const float* g1  = (const float*)d_in[4];
    const float* bt1 = (const float*)d_in[5];
    const float* W2  = (const float*)d_in[6];
    const float* b2  = (const float*)d_in[7];
    const float* g2  = (const float*)d_in[8];
    const float* bt2 = (const float*)d_in[9];
    const float* W3  = (const float*)d_in[10];
    const float* b3  = (const float*)d_in[11];
    const float* g3  = (const float*)d_in[12];
    const float* bt3 = (const float*)d_in[13];
    float* out = (float*)d_out;

    float *En, *Y1, *Y2, *Y3, *pS, *pS2;
    uint32_t *Xthi, *Xtlo, *Gh, *Vh, *Axh;
    uint32_t *W1hi, *W1lo, *W2hi, *W2lo, *W3hi, *W3lo;
    cudaGetSymbolAddress((void**)&En,   g_En);
    cudaGetSymbolAddress((void**)&Xthi, g_Xthi);  cudaGetSymbolAddress((void**)&Xtlo, g_Xtlo);
    cudaGetSymbolAddress((void**)&Gh,   g_Gh);
    cudaGetSymbolAddress((void**)&Vh,   g_Vh);
    cudaGetSymbolAddress((void**)&Axh,  g_Axh);
    cudaGetSymbolAddress((void**)&W1hi, g_W1hi);  cudaGetSymbolAddress((void**)&W1lo, g_W1lo);
    cudaGetSymbolAddress((void**)&W2hi, g_W2hi);  cudaGetSymbolAddress((void**)&W2lo, g_W2lo);
    cudaGetSymbolAddress((void**)&W3hi, g_W3hi);  cudaGetSymbolAddress((void**)&W3lo, g_W3lo);
    cudaGetSymbolAddress((void**)&Y1, g_Y1);
    cudaGetSymbolAddress((void**)&Y2, g_Y2);
    cudaGetSymbolAddress((void**)&Y3, g_Y3);
    cudaGetSymbolAddress((void**)&pS, g_pS);      cudaGetSymbolAddress((void**)&pS2, g_pS2);

    const int SMEM64  = (2*ASZ  + 4*BSZ ) * 4;   // (5120 + 10240)*4 = 61440... (2*2560 + 4*1280)*4 = 40960
    const int SMEMBIG = (2*ASZB + 4*BSZB) * 4;   // (10240 + 10240)*4 = 81920
    cudaFuncSetAttribute(vgemm_kernel,    cudaFuncAttributeMaxDynamicSharedMemorySize, SMEM64);
    cudaFuncSetAttribute(gemm_ps_kernel,  cudaFuncAttributeMaxDynamicSharedMemorySize, SMEM64);
    cudaFuncSetAttribute(gemm_big_kernel, cudaFuncAttributeMaxDynamicSharedMemorySize, SMEMBIG);

    // 1) prep (En/Xt + W splits + G build), one launch
    prep_all_kernel<<<296, 256>>>(x, Q, En, Xthi, Xtlo,
                                  W1, W1hi, W1lo, W2, W2hi, W2lo, W3, W3hi, W3lo, Gh);

    // 2) V = En .* (G @ Xt^T) - pos  -> single fp16
    vgemm_kernel<<<dim3(4, 4, 16), 256, SMEM64>>>(Gh, Xthi, Xtlo, En, x, Vh);

    // 3) layer 1 (A=Vh single, B=W1 pair; 32 stats partials)
    gemm_big_kernel<<<dim3(NH/128, MROWS/256), 512, SMEMBIG>>>(
        Vh, W1hi, W1lo, b1, Y1, pS, pS2, VDIM, NH);
    bnstats_convert_kernel<<<dim3(4, 64), 256>>>(Y1, pS, pS2, g1, bt1, Axh);

    // 4) layer 2
    gemm_big_kernel<<<dim3(NH/128, MROWS/256), 512, SMEMBIG>>>(
        Axh, W2hi, W2lo, b2, Y2, pS, pS2, NH, NH);
    bnstats_convert_kernel<<<dim3(4, 64), 256>>>(Y2, pS, pS2, g2, bt2, Axh);

    // 5) layer 3 (64 partials)
    gemm_ps_kernel<<<dim3(NO/64, MROWS/128), 256, SMEM64>>>(
        Axh, W3hi, W3lo, b3, Y3, pS, pS2, NH, NO);

    // 6) stats finalize + BN apply -> out
    bnstats_apply_kernel<<<64, 256>>>(Y3, pS, pS2, g3, bt3, out);
}

// round 15
// speedup vs baseline: 1.4799x; 1.0582x over previous
#include <cuda_runtime.h>
#include <cuda_fp16.h>
#include <cstdint>
#include <math.h>

#define BATCH 16
#define SEQ   512
#define NI    32
#define NHEAD 8
#define NH    512
#define NO    64
#define MROWS (BATCH*SEQ)      // 8192
#define VDIM  (NHEAD*NI)       // 256
#define EPSV  1e-5f
#define SLOPE 0.05f
#define NPART 64

// ---------------- scratch ----------------
__device__ float    g_En  [16*8*512];
__device__ uint32_t g_Xthi[(size_t)16*256*256], g_Xtlo[(size_t)16*256*256];
__device__ uint32_t g_Gh  [(size_t)16*512*256];
__device__ uint32_t g_Vh  [(size_t)8192*128];
__device__ uint32_t g_W1hi[512*128], g_W1lo[512*128];
__device__ uint32_t g_W2hi[512*256], g_W2lo[512*256];
__device__ uint32_t g_W3hi[64*256],  g_W3lo[64*256];
__device__ uint32_t g_Axh [(size_t)8192*256];
__device__ float g_Y1[(size_t)MROWS * NH];
__device__ float g_Y2[(size_t)MROWS * NH];
__device__ float g_Y3[(size_t)MROWS * NO];
__device__ float g_pS [NPART * NH];
__device__ float g_pS2[NPART * NH];

// ---------------- helpers ----------------
__device__ __forceinline__ void split_pair_h(float v0, float v1, uint32_t& hi, uint32_t& lo) {
    __half h0 = __float2half(v0);
    __half h1 = __float2half(v1);
    float r0 = v0 - __half2float(h0);
    float r1 = v1 - __half2float(h1);
    __half l0 = __float2half(r0);
    __half l1 = __float2half(r1);
    hi = ((uint32_t)__half_as_ushort(h1) << 16) | __half_as_ushort(h0);
    lo = ((uint32_t)__half_as_ushort(l1) << 16) | __half_as_ushort(l0);
}
__device__ __forceinline__ uint32_t pack_h(float v0, float v1) {
    __half h0 = __float2half(v0);
    __half h1 = __float2half(v1);
    return ((uint32_t)__half_as_ushort(h1) << 16) | __half_as_ushort(h0);
}

__device__ __forceinline__ void mma_f16(float* d, const uint32_t* a, const uint32_t* b) {
    asm volatile(
        "mma.sync.aligned.m16n8k16.row.col.f32.f16.f16.f32 "
        "{%0,%1,%2,%3}, {%4,%5,%6,%7}, {%8,%9}, {%0,%1,%2,%3};"
        : "+f"(d[0]), "+f"(d[1]), "+f"(d[2]), "+f"(d[3])
        : "r"(a[0]), "r"(a[1]), "r"(a[2]), "r"(a[3]), "r"(b[0]), "r"(b[1]));
}

__device__ __forceinline__ void ldsm4(uint32_t* r, uint32_t addr) {
    asm volatile("ldmatrix.sync.aligned.m8n8.x4.shared.b16 {%0,%1,%2,%3}, [%4];"
        : "=r"(r[0]), "=r"(r[1]), "=r"(r[2]), "=r"(r[3]) : "r"(addr));
}

__device__ __forceinline__ uint32_t smem_u32(const void* p) {
    uint32_t a;
    asm("{ .reg .u64 t; cvta.to.shared.u64 t, %1; cvt.u32.u64 %0, t; }" : "=r"(a) : "l"(p));
    return a;
}
__device__ __forceinline__ void cp_async16(uint32_t saddr, const void* gptr) {
    asm volatile("cp.async.cg.shared.global [%0], [%1], 16;" :: "r"(saddr), "l"(gptr));
}
#define CP_COMMIT() asm volatile("cp.async.commit_group;" ::: "memory")
#define CP_WAIT0()  asm volatile("cp.async.wait_group 0;" ::: "memory")

// ---------------- prep_all: En/Xt(hi,lo) + W splits + buildG(single) ----------------
__global__ void __launch_bounds__(256) prep_all_kernel(
    const float* __restrict__ x, const float* __restrict__ Q,
    float* __restrict__ En,
    uint32_t* __restrict__ Xthi, uint32_t* __restrict__ Xtlo,
    const float* __restrict__ W1, uint32_t* __restrict__ W1hi, uint32_t* __restrict__ W1lo,
    const float* __restrict__ W2, uint32_t* __restrict__ W2hi, uint32_t* __restrict__ W2lo,
    const float* __restrict__ W3, uint32_t* __restrict__ W3hi, uint32_t* __restrict__ W3lo,
    uint32_t* __restrict__ Gh)
{
    const int blk = blockIdx.x;
    const int tid = threadIdx.x;

    __shared__ float sEm[8][128];
    __shared__ float sQ[8][4];
    __shared__ uint32_t shi[256][8], slo[256][8];
    __shared__ float pn3[64][5];
    __shared__ float pm3[128][4];

    if (blk >= 168) {
        const int g  = blk - 168;
        const int b  = g >> 3, nt = g & 7;
        const int n = tid & 63, mq = tid >> 6;

        if (tid < 64) {
            const float* xp = x + ((size_t)b*512 + nt*64 + tid)*32;
            pn3[tid][0] = xp[0]; pn3[tid][1] = xp[1]; pn3[tid][2] = xp[2];
        }
        for (int mc = 0; mc < 4; mc++) {
            __syncthreads();
            if (tid < 128) {
                const float* xp = x + ((size_t)b*512 + mc*128 + tid)*32;
                pm3[tid][0] = xp[0]; pm3[tid][1] = xp[1]; pm3[tid][2] = xp[2];
            }
            __syncthreads();
            float px = pn3[n][0], py = pn3[n][1], pz = pn3[n][2];
            uint32_t outh[16];
            #pragma unroll
            for (int j = 0; j < 16; j++) {
                int ml = mq*32 + j*2;
                float dx0 = px - pm3[ml][0],   dy0 = py - pm3[ml][1],   dz0 = pz - pm3[ml][2];
                float dx1 = px - pm3[ml+1][0], dy1 = py - pm3[ml+1][1], dz1 = pz - pm3[ml+1][2];
                float e0 = __expf(-(dx0*dx0 + dy0*dy0 + dz0*dz0));
                float e1 = __expf(-(dx1*dx1 + dy1*dy1 + dz1*dz1));
                outh[j] = pack_h(e0, e1);
            }
            size_t base = ((size_t)b*512 + nt*64 + n)*256 + mc*64 + mq*16;
            #pragma unroll
            for (int j4 = 0; j4 < 4; j4++)
                ((uint4*)(Gh + base))[j4] = make_uint4(outh[j4*4], outh[j4*4+1], outh[j4*4+2], outh[j4*4+3]);
        }
        return;
    }

    if (blk >= 64) {
        int widx = blk - 64;
        const float* src; uint32_t* hi; uint32_t* lo; int base;
        if (widx < 32)      { src = W1; hi = W1hi; lo = W1lo; base = widx * 2048; }
        else if (widx < 96) { src = W2; hi = W2hi; lo = W2lo; base = (widx - 32) * 2048; }
        else                { src = W3; hi = W3hi; lo = W3lo; base = (widx - 96) * 2048; }
        int p = base + tid;
        #pragma unroll
        for (int j = 0; j < 8; j++, p += 256) {
            float2 v = ((const float2*)src)[p];
            uint32_t h, l; split_pair_h(v.x, v.y, h, l);
            hi[p] = h; lo[p] = l;
        }
        return;
    }

    const int b = blk >> 2, chunk = blk & 3;

    if (tid < 8) {
        float a = Q[tid*3+0], bq = Q[tid*3+1], cq = Q[tid*3+2];
        sQ[tid][0] = a; sQ[tid][1] = bq; sQ[tid][2] = cq;
        sQ[tid][3] = a*a + bq*bq + cq*cq;
    }
    __syncthreads();

    if (tid < 128) {
        int m = chunk*128 + tid;
        const float* xp = x + ((size_t)b*512 + m)*32;
        float px = xp[0], py = xp[1], pz = xp[2];
        #pragma unroll
        for (int h = 0; h < 8; h++) {
            float dot = px*sQ[h][0] + py*sQ[h][1] + pz*sQ[h][2];
            float em = __expf(-2.f*dot);
            float en = __expf(2.f*dot - sQ[h][3]);
            sEm[h][tid] = em;
            En[((size_t)b*8 + h)*512 + m] = en;
        }
    }
    __syncthreads();

    const int c = tid, h = c >> 5, i = c & 31;
    for (int grp = 0; grp < 8; grp++) {
        #pragma unroll
        for (int j = 0; j < 8; j++) {
            int mloc = (grp*8 + j)*2;
            int m = chunk*128 + mloc;
            float v0 = sEm[h][mloc]   * x[((size_t)b*512 + m  )*32 + i];
            float v1 = sEm[h][mloc+1] * x[((size_t)b*512 + m+1)*32 + i];
            uint32_t hh, ll; split_pair_h(v0, v1, hh, ll);
            shi[c][j] = hh; slo[c][j] = ll;
        }
        __syncthreads();
        int cc = tid >> 3, j2 = tid & 7;
        #pragma unroll
        for (int rep = 0; rep < 8; rep++) {
            int ccc = cc + rep*32;
            size_t addr = ((size_t)b*256 + ccc)*256 + chunk*64 + grp*8 + j2;
            Xthi[addr] = shi[ccc][j2];
            Xtlo[addr] = slo[ccc][j2];
        }
        __syncthreads();
    }
}

// ================= GEMM machinery: A single fp16, B hi/lo pair, 2 MMAs =================
#define RSU 20
#define TN  64
#define NFRAG (TN/16)
#define ASZ (128*RSU)
#define BSZ (TN*RSU)

// ---------------- vgemm: V = En .* (G @ Xt^T) - pos ----------------
__global__ void __launch_bounds__(256, 3) vgemm_kernel(
    const uint32_t* __restrict__ Gh_g,
    const uint32_t* __restrict__ Bhi_g, const uint32_t* __restrict__ Blo_g,
    const float* __restrict__ En, const float* __restrict__ x,
    uint32_t* __restrict__ Vh)
{
    constexpr int KE = 512, K2 = KE/2;
    extern __shared__ uint32_t smem_u[];
    const uint32_t sbase = smem_u32(smem_u);
    const uint32_t bA  = sbase;
    const uint32_t bBh = sbase + 2*ASZ*4;
    const uint32_t bBl = sbase + (2*ASZ + 2*BSZ)*4;

    const int tid = threadIdx.x, wid = tid >> 5, lane = tid & 31;
    const int wm = (wid >> 1) * 32, wn = (wid & 1) * (TN/2);
    const int l4 = lane >> 2, lk = lane & 3;
    const int rowA = lane & 15, colA = (lane >> 4) * 4;
    const int rowB = ((lane >> 4) & 1) * 8 + (lane & 7);
    const int colB = ((lane >> 3) & 1) * 4;
    const int b = blockIdx.z;
    const int m0 = blockIdx.y * 128, c0 = blockIdx.x * TN;

    const uint32_t* A_g  = Gh_g + (size_t)b*512*K2;
    const uint32_t* Bh_g = Bhi_g + (size_t)b*256*K2;
    const uint32_t* Bl_g = Blo_g + (size_t)b*256*K2;

    float acc[2][NFRAG][4];
    #pragma unroll
    for (int a = 0; a < 2; a++)
        #pragma unroll
        for (int q = 0; q < NFRAG; q++)
            { acc[a][q][0]=0.f; acc[a][q][1]=0.f; acc[a][q][2]=0.f; acc[a][q][3]=0.f; }

    auto issue = [&](int t) {
        int buf = t & 1;
        #pragma unroll
        for (int j = 0; j < 2; j++) {
            int lin = tid + j*256; int r = lin >> 2, q = lin & 3;
            uint32_t off = (uint32_t)(buf*ASZ + r*RSU + q*4) * 4;
            size_t ao = (size_t)(m0 + r)*K2 + t*16 + q*4;
            cp_async16(bA + off, A_g + ao);
        }
        {
            int r = tid >> 2, q = tid & 3;
            uint32_t off = (uint32_t)(buf*BSZ + r*RSU + q*4) * 4;
            size_t bo = (size_t)(c0 + r)*K2 + t*16 + q*4;
            cp_async16(bBh + off, Bh_g + bo);
            cp_async16(bBl + off, Bl_g + bo);
        }
        CP_COMMIT();
    };

    auto compute = [&](int buf) {
        #pragma unroll
        for (int kk = 0; kk < 2; kk++) {
            uint32_t ah[2][4];
            #pragma unroll
            for (int mi = 0; mi < 2; mi++) {
                uint32_t off = (uint32_t)(buf*ASZ + (wm + mi*16 + rowA)*RSU + kk*8 + colA) * 4;
                ldsm4(ah[mi], bA + off);
            }
            #pragma unroll
            for (int np = 0; np < NFRAG/2; np++) {
                uint32_t off = (uint32_t)(buf*BSZ + (wn + np*16 + rowB)*RSU + kk*8 + colB) * 4;
                uint32_t th[4], tl[4];
                ldsm4(th, bBh + off);
                ldsm4(tl, bBl + off);
                #pragma unroll
                for (int sub = 0; sub < 2; sub++) {
                    int ni = np*2 + sub;
                    uint32_t bhp[2] = {th[sub*2], th[sub*2+1]};
                    uint32_t blp[2] = {tl[sub*2], tl[sub*2+1]};
                    #pragma unroll
                    for (int mi = 0; mi < 2; mi++) {
                        mma_f16(acc[mi][ni], ah[mi], bhp);
                        mma_f16(acc[mi][ni], ah[mi], blp);
                    }
                }
            }
        }
    };

    const int T = KE / 32;
    issue(0);
    for (int t = 0; t < T; t++) {
        CP_WAIT0();
        __syncthreads();
        if (t + 1 < T) issue(t + 1);
        compute(t & 1);
    }

    #pragma unroll
    for (int mi = 0; mi < 2; mi++) {
        #pragma unroll
        for (int ni = 0; ni < NFRAG; ni++) {
            int n0 = m0 + wm + mi*16 + l4;
            int cc = c0 + wn + ni*8 + lk*2;
            int h = cc >> 5, il = cc & 31;
            float en0 = En[((size_t)b*8 + h)*512 + n0];
            float en1 = En[((size_t)b*8 + h)*512 + n0 + 8];
            float v00 = acc[mi][ni][0]*en0, v01 = acc[mi][ni][1]*en0;
            float v10 = acc[mi][ni][2]*en1, v11 = acc[mi][ni][3]*en1;
            if (il < 3) {
                v00 -= x[((size_t)b*512 + n0  )*32 + il];
                v10 -= x[((size_t)b*512 + n0+8)*32 + il];
            }
            if (il + 1 < 3) {
                v01 -= x[((size_t)b*512 + n0  )*32 + il + 1];
                v11 -= x[((size_t)b*512 + n0+8)*32 + il + 1];
            }
            size_t r0 = ((size_t)b*512 + n0)*128 + (cc >> 1);
            size_t r1 = ((size_t)b*512 + n0 + 8)*128 + (cc >> 1);
            Vh[r0] = pack_h(v00, v01);
            Vh[r1] = pack_h(v10, v11);
        }
    }
}

// ---------------- gemm_big: 512 threads, TM=256 x TNB=128, fused stats ----------------
#define TNB  128
#define NFB  (TNB/16)
#define ASZB (256*RSU)
#define BSZB (128*RSU)

__global__ void __launch_bounds__(512, 1) gemm_big_kernel(
    const uint32_t* __restrict__ A_g,
    const uint32_t* __restrict__ Bh_g, const uint32_t* __restrict__ Bl_g,
    const float* __restrict__ bias, float* __restrict__ Y,
    float* __restrict__ pS, float* __restrict__ pS2, int K, int C)
{
    extern __shared__ uint32_t smem_u[];
    const uint32_t sbase = smem_u32(smem_u);
    const uint32_t bA  = sbase;
    const uint32_t bBh = sbase + 2*ASZB*4;
    const uint32_t bBl = sbase + (2*ASZB + 2*BSZB)*4;

    const int tid = threadIdx.x, wid = tid >> 5, lane = tid & 31;
    const int wm = (wid >> 1) * 32;
    const int wn = (wid & 1) * 64;
    const int mw = wid >> 1;
    const int l4 = lane >> 2, lk = lane & 3;
    const int rowA = lane & 15, colA = (lane >> 4) * 4;
    const int rowB = ((lane >> 4) & 1) * 8 + (lane & 7);
    const int colB = ((lane >> 3) & 1) * 4;
    const int m0 = blockIdx.y * 256, c0 = blockIdx.x * TNB;
    const int K2 = K >> 1;

    float acc[2][NFB][4];
    #pragma unroll
    for (int a = 0; a < 2; a++)
        #pragma unroll
        for (int q = 0; q < NFB; q++)
            { acc[a][q][0]=0.f; acc[a][q][1]=0.f; acc[a][q][2]=0.f; acc[a][q][3]=0.f; }

    auto issue = [&](int t) {
        int buf = t & 1;
        #pragma unroll
        for (int j = 0; j < 2; j++) {
            int lin = tid + j*512; int r = lin >> 2, q = lin & 3;
            uint32_t off = (uint32_t)(buf*ASZB + r*RSU + q*4) * 4;
            size_t ao = (size_t)(m0 + r)*K2 + t*16 + q*4;
            cp_async16(bA + off, A_g + ao);
        }
        {
            int r = tid >> 2, q = tid & 3;
            uint32_t off = (uint32_t)(buf*BSZB + r*RSU + q*4) * 4;
            size_t bo = (size_t)(c0 + r)*K2 + t*16 + q*4;
            cp_async16(bBh + off, Bh_g + bo);
            cp_async16(bBl + off, Bl_g + bo);
        }
        CP_COMMIT();
    };

    auto compute = [&](int buf) {
        #pragma unroll
        for (int kk = 0; kk < 2; kk++) {
            uint32_t ah[2][4];
            #pragma unroll
            for (int mi = 0; mi < 2; mi++) {
                uint32_t off = (uint32_t)(buf*ASZB + (wm + mi*16 + rowA)*RSU + kk*8 + colA) * 4;
                ldsm4(ah[mi], bA + off);
            }
            #pragma unroll
            for (int np = 0; np < NFB/2; np++) {
                uint32_t off = (uint32_t)(buf*BSZB + (wn + np*16 + rowB)*RSU + kk*8 + colB) * 4;
                uint32_t th[4], tl[4];
                ldsm4(th, bBh + off);
                ldsm4(tl, bBl + off);
                #pragma unroll
                for (int sub = 0; sub < 2; sub++) {
                    int ni = np*2 + sub;
                    uint32_t bhp[2] = {th[sub*2], th[sub*2+1]};
                    uint32_t blp[2] = {tl[sub*2], tl[sub*2+1]};
                    #pragma unroll
                    for (int mi = 0; mi < 2; mi++) {
                        mma_f16(acc[mi][ni], ah[mi], bhp);
                        mma_f16(acc[mi][ni], ah[mi], blp);
                    }
                }
            }
        }
    };

    const int T = K / 32;
    issue(0);
    for (int t = 0; t < T; t++) {
        CP_WAIT0();
        __syncthreads();
        if (t + 1 < T) issue(t + 1);
        compute(t & 1);
    }
    __syncthreads();

    float* sbufS  = (float*)smem_u;
    float* sbufS2 = sbufS + 8*TNB;

    #pragma unroll
    for (int ni = 0; ni < NFB; ni++) {
        int col = c0 + wn + ni*8 + lk*2;
        float2 b2 = *(const float2*)(bias + col);
        float s0 = 0.f, s1 = 0.f, q0 = 0.f, q1 = 0.f;
        #pragma unroll
        for (int mi = 0; mi < 2; mi++) {
            int row = m0 + wm + mi*16 + l4;
            float e0 = acc[mi][ni][0] + b2.x;
            float e1 = acc[mi][ni][1] + b2.y;
            float e2 = acc[mi][ni][2] + b2.x;
            float e3 = acc[mi][ni][3] + b2.y;
            *(float2*)(Y + (size_t)row * C + col)       = make_float2(e0, e1);
            *(float2*)(Y + (size_t)(row + 8) * C + col) = make_float2(e2, e3);
            s0 += e0 + e2; s1 += e1 + e3;
            q0 += e0*e0 + e2*e2; q1 += e1*e1 + e3*e3;
        }
        #pragma unroll
        for (int off = 16; off >= 4; off >>= 1) {
            s0 += __shfl_down_sync(0xffffffffu, s0, off);
            s1 += __shfl_down_sync(0xffffffffu, s1, off);
            q0 += __shfl_down_sync(0xffffffffu, q0, off);
            q1 += __shfl_down_sync(0xffffffffu, q1, off);
        }
        if (lane < 4) {
            int cb = wn + ni*8 + lk*2;
            sbufS [mw*TNB + cb]     = s0;
            sbufS [mw*TNB + cb + 1] = s1;
            sbufS2[mw*TNB + cb]     = q0;
            sbufS2[mw*TNB + cb + 1] = q1;
        }
    }
    __syncthreads();
    if (tid < TNB) {
        float s = 0.f, q = 0.f;
        #pragma unroll
        for (int r = 0; r < 8; r++) { s += sbufS[r*TNB + tid]; q += sbufS2[r*TNB + tid]; }
        pS [blockIdx.y * C + c0 + tid] = s;
        pS2[blockIdx.y * C + c0 + tid] = q;
    }
}

// ---------------- gemm_ps (TN=64) for layer 3 ----------------
__global__ void __launch_bounds__(256, 3) gemm_ps_kernel(
    const uint32_t* __restrict__ A_g,
    const uint32_t* __restrict__ Bh_g, const uint32_t* __restrict__ Bl_g,
    const float* __restrict__ bias, float* __restrict__ Y,
    float* __restrict__ pS, float* __restrict__ pS2, int K, int C)
{
    extern __shared__ uint32_t smem_u[];
    const uint32_t sbase = smem_u32(smem_u);
    const uint32_t bA  = sbase;
    const uint32_t bBh = sbase + 2*ASZ*4;
    const uint32_t bBl = sbase + (2*ASZ + 2*BSZ)*4;

    const int tid = threadIdx.x, wid = tid >> 5, lane = tid & 31;
    const int wm = (wid >> 1) * 32, wn = (wid & 1) * (TN/2);
    const int mw = wid >> 1;
    const int l4 = lane >> 2, lk = lane & 3;
    const int rowA = lane & 15, colA = (lane >> 4) * 4;
    const int rowB = ((lane >> 4) & 1) * 8 + (lane & 7);
    const int colB = ((lane >> 3) & 1) * 4;
    const int m0 = blockIdx.y * 128, c0 = blockIdx.x * TN;
    const int K2 = K >> 1;

    float acc[2][NFRAG][4];
    #pragma unroll
    for (int a = 0; a < 2; a++)
        #pragma unroll
        for (int q = 0; q < NFRAG; q++)
            { acc[a][q][0]=0.f; acc[a][q][1]=0.f; acc[a][q][2]=0.f; acc[a][q][3]=0.f; }

    auto issue = [&](int t) {
        int buf = t & 1;
        #pragma unroll
        for (int j = 0; j < 2; j++) {
            int lin = tid + j*256; int r = lin >> 2, q = lin & 3;
            uint32_t off = (uint32_t)(buf*ASZ + r*RSU + q*4) * 4;
            size_t ao = (size_t)(m0 + r)*K2 + t*16 + q*4;
            cp_async16(bA + off, A_g + ao);
        }
        {
            int r = tid >> 2, q = tid & 3;
            uint32_t off = (uint32_t)(buf*BSZ + r*RSU + q*4) * 4;
            size_t bo = (size_t)(c0 + r)*K2 + t*16 + q*4;
            cp_async16(bBh + off, Bh_g + bo);
            cp_async16(bBl + off, Bl_g + bo);
        }
        CP_COMMIT();
    };

    auto compute = [&](int buf) {
        #pragma unroll
        for (int kk = 0; kk < 2; kk++) {
            uint32_t ah[2][4];
            #pragma unroll
            for (int mi = 0; mi < 2; mi++) {
                uint32_t off = (uint32_t)(buf*ASZ + (wm + mi*16 + rowA)*RSU + kk*8 + colA) * 4;
                ldsm4(ah[mi], bA + off);
            }
            #pragma unroll
            for (int np = 0; np < NFRAG/2; np++) {
                uint32_t off = (uint32_t)(buf*BSZ + (wn + np*16 + rowB)*RSU + kk*8 + colB) * 4;
                uint32_t th[4], tl[4];
                ldsm4(th, bBh + off);
                ldsm4(tl, bBl + off);
                #pragma unroll
                for (int sub = 0; sub < 2; sub++) {
                    int ni = np*2 + sub;
                    uint32_t bhp[2] = {th[sub*2], th[sub*2+1]};
                    uint32_t blp[2] = {tl[sub*2], tl[sub*2+1]};
                    #pragma unroll
                    for (int mi = 0; mi < 2; mi++) {
                        mma_f16(acc[mi][ni], ah[mi], bhp);
                        mma_f16(acc[mi][ni], ah[mi], blp);
                    }
                }
            }
        }
    };

    const int T = K / 32;
    issue(0);
    for (int t = 0; t < T; t++) {
        CP_WAIT0();
        __syncthreads();
        if (t + 1 < T) issue(t + 1);
        compute(t & 1);
    }
    __syncthreads();

    float* sbufS  = (float*)smem_u;
    float* sbufS2 = sbufS + 4*TN;

    #pragma unroll
    for (int ni = 0; ni < NFRAG; ni++) {
        int col = c0 + wn + ni*8 + lk*2;
        float2 b2 = *(const float2*)(bias + col);
        float s0 = 0.f, s1 = 0.f, q0 = 0.f, q1 = 0.f;
        #pragma unroll
        for (int mi = 0; mi < 2; mi++) {
            int row = m0 + wm + mi*16 + l4;
            float e0 = acc[mi][ni][0] + b2.x;
            float e1 = acc[mi][ni][1] + b2.y;
            float e2 = acc[mi][ni][2] + b2.x;
            float e3 = acc[mi][ni][3] + b2.y;
            *(float2*)(Y + (size_t)row * C + col)       = make_float2(e0, e1);
            *(float2*)(Y + (size_t)(row + 8) * C + col) = make_float2(e2, e3);
            s0 += e0 + e2; s1 += e1 + e3;
            q0 += e0*e0 + e2*e2; q1 += e1*e1 + e3*e3;
        }
        #pragma unroll
        for (int off = 16; off >= 4; off >>= 1) {
            s0 += __shfl_down_sync(0xffffffffu, s0, off);
            s1 += __shfl_down_sync(0xffffffffu, s1, off);
            q0 += __shfl_down_sync(0xffffffffu, q0, off);
            q1 += __shfl_down_sync(0xffffffffu, q1, off);
        }
        if (lane < 4) {
            int cb = wn + ni*8 + lk*2;
            sbufS [mw*TN + cb]     = s0;
            sbufS [mw*TN + cb + 1] = s1;
            sbufS2[mw*TN + cb]     = q0;
            sbufS2[mw*TN + cb + 1] = q1;
        }
    }
    __syncthreads();
    if (tid < TN) {
        float s = sbufS [tid] + sbufS [TN + tid] + sbufS [2*TN + tid] + sbufS [3*TN + tid];
        float q = sbufS2[tid] + sbufS2[TN + tid] + sbufS2[2*TN + tid] + sbufS2[3*TN + tid];
        pS [blockIdx.y * C + c0 + tid] = s;
        pS2[blockIdx.y * C + c0 + tid] = q;
    }
}

// ---------------- bnstats_convert: fused stats finalize + BN + leaky -> single fp16 ----------------
// grid (C/128=4, MROWS/32=256); block 256. Head reduces 32 partials for 128 cols (parallel halves).
__global__ void __launch_bounds__(256) bnstats_convert_kernel(
    const float* __restrict__ Y, const float* __restrict__ pS, const float* __restrict__ pS2,
    const float* __restrict__ g, const float* __restrict__ bt,
    uint32_t* __restrict__ Ah)
{
    __shared__ float ssc[128], ssh[128];
    __shared__ float spart[2][2][128];   // [half][S/S2][col]
    const int tid = threadIdx.x;
    const int c0 = blockIdx.x * 128;
    const int r0 = blockIdx.y * 32;

    {
        int cl = tid & 127, half = tid >> 7;
        int c = c0 + cl;
        float s = 0.f, q = 0.f;
        #pragma unroll
        for (int p = half*16; p < half*16 + 16; p++) {
            s += pS [p*512 + c];
            q += pS2[p*512 + c];
        }
        spart[half][0][cl] = s;
        spart[half][1][cl] = q;
    }
    __syncthreads();
    if (tid < 128) {
        int c = c0 + tid;
        float s = spart[0][0][tid] + spart[1][0][tid];
        float q = spart[0][1][tid] + spart[1][1][tid];
        float mean = s * (1.f/8192.f);
        float var  = fmaf(-mean, mean, q * (1.f/8192.f));
        float inv  = rsqrtf(var + EPSV);
        float scv  = g[c] * inv;
        ssc[tid] = scv;
        ssh[tid] = fmaf(-mean, scv, bt[c]);
    }
    __syncthreads();

    #pragma unroll
    for (int it = 0; it < 4; it++) {
        int idx = it*256 + tid;
        int row = idx >> 5, c4 = idx & 31;
        float4 y  = ((const float4*)Y)[(size_t)(r0 + row)*128 + blockIdx.x*32 + c4];
        float4 sc = ((const float4*)ssc)[c4];
        float4 sh = ((const float4*)ssh)[c4];
        float v0 = fmaf(y.x, sc.x, sh.x);
        float v1 = fmaf(y.y, sc.y, sh.y);
        float v2 = fmaf(y.z, sc.z, sh.z);
        float v3 = fmaf(y.w, sc.w, sh.w);
        v0 = v0 > 0.f ? v0 : v0 * SLOPE;
        v1 = v1 > 0.f ? v1 : v1 * SLOPE;
        v2 = v2 > 0.f ? v2 : v2 * SLOPE;
        v3 = v3 > 0.f ? v3 : v3 * SLOPE;
        ((uint2*)Ah)[(size_t)(r0 + row)*128 + blockIdx.x*32 + c4] =
            make_uint2(pack_h(v0, v1), pack_h(v2, v3));
    }
}

// ---------------- bnstats_apply: stats finalize + BN -> out (C=64, 64 partials) ----------------
__global__ void __launch_bounds__(256) bnstats_apply_kernel(
    const float* __restrict__ Y, const float* __restrict__ pS, const float* __restrict__ pS2,
    const float* __restrict__ g, const float* __restrict__ bt, float* __restrict__ out)
{
    __shared__ float ssc[64], ssh[64];
    __shared__ float spart[4][2][64];
    const int tid = threadIdx.x;
    {
        int cl = tid & 63, quad = tid >> 6;
        float s = 0.f, q = 0.f;
        #pragma unroll
        for (int p = quad*16; p < quad*16 + 16; p++) {
            s += pS [p*64 + cl];
            q += pS2[p*64 + cl];
        }
        spart[quad][0][cl] = s;
        spart[quad][1][cl] = q;
    }
    __syncthreads();
    if (tid < 64) {
        float s = spart[0][0][tid] + spart[1][0][tid] + spart[2][0][tid] + spart[3][0][tid];
        float q = spart[0][1][tid] + spart[1][1][tid] + spart[2][1][tid] + spart[3][1][tid];
        float mean = s * (1.f/8192.f);
        float var  = fmaf(-mean, mean, q * (1.f/8192.f));
        float inv  = rsqrtf(var + EPSV);
        float scv  = g[tid] * inv;
        ssc[tid] = scv;
        ssh[tid] = fmaf(-mean, scv, bt[tid]);
    }
    __syncthreads();

    size_t base = (size_t)blockIdx.x * 1024;
    #pragma unroll
    for (int it = 0; it < 4; it++) {
        int idx = it*256 + tid;
        int c4 = idx & 15;
        float4 y  = ((const float4*)Y)[base + idx];
        float4 sc = ((const float4*)ssc)[c4];
        float4 sh = ((const float4*)ssh)[c4];
        float4 o;
        o.x = fmaf(y.x, sc.x, sh.x);
        o.y = fmaf(y.y, sc.y, sh.y);
        o.z = fmaf(y.z, sc.z, sh.z);
        o.w = fmaf(y.w, sc.w, sh.w);
        ((float4*)out)[base + idx] = o;
    }
}

// ---------------- host ----------------
extern "C" void kernel_launch(void* const* d_in, const int* in_sizes, int n_in,
                              void* d_out, int out_size)
{
    const float* x   = (const float*)d_in[0];
    const float* Q   = (const float*)d_in[1];
    const float* W1  = (const float*)d_in[2];
    const float* b1  = (const float*)d_in[3];
    const float* g1  = (const float*)d_in[4];
    const float* bt1 = (const float*)d_in[5];
    const float* W2  = (const float*)d_in[6];
    const float* b2  = (const float*)d_in[7];
    const float* g2  = (const float*)d_in[8];
    const float* bt2 = (const float*)d_in[9];
    const float* W3  = (const float*)d_in[10];
    const float* b3  = (const float*)d_in[11];
    const float* g3  = (const float*)d_in[12];
    const float* bt3 = (const float*)d_in[13];
    float* out = (float*)d_out;

    float *En, *Y1, *Y2, *Y3, *pS, *pS2;
    uint32_t *Xthi, *Xtlo, *Gh, *Vh, *Axh;
    uint32_t *W1hi, *W1lo, *W2hi, *W2lo, *W3hi, *W3lo;
    cudaGetSymbolAddress((void**)&En,   g_En);
    cudaGetSymbolAddress((void**)&Xthi, g_Xthi);  cudaGetSymbolAddress((void**)&Xtlo, g_Xtlo);
    cudaGetSymbolAddress((void**)&Gh,   g_Gh);
    cudaGetSymbolAddress((void**)&Vh,   g_Vh);
    cudaGetSymbolAddress((void**)&Axh,  g_Axh);
    cudaGetSymbolAddress((void**)&W1hi, g_W1hi);  cudaGetSymbolAddress((void**)&W1lo, g_W1lo);
    cudaGetSymbolAddress((void**)&W2hi, g_W2hi);  cudaGetSymbolAddress((void**)&W2lo, g_W2lo);
    cudaGetSymbolAddress((void**)&W3hi, g_W3hi);  cudaGetSymbolAddress((void**)&W3lo, g_W3lo);
    cudaGetSymbolAddress((void**)&Y1, g_Y1);
    cudaGetSymbolAddress((void**)&Y2, g_Y2);
    cudaGetSymbolAddress((void**)&Y3, g_Y3);
    cudaGetSymbolAddress((void**)&pS, g_pS);      cudaGetSymbolAddress((void**)&pS2, g_pS2);

    const int SMEM64  = (2*ASZ  + 4*BSZ ) * 4;   // 40960 B
    const int SMEMBIG = (2*ASZB + 4*BSZB) * 4;   // 81920 B
    cudaFuncSetAttribute(vgemm_kernel,    cudaFuncAttributeMaxDynamicSharedMemorySize, SMEM64);
    cudaFuncSetAttribute(gemm_ps_kernel,  cudaFuncAttributeMaxDynamicSharedMemorySize, SMEM64);
    cudaFuncSetAttribute(gemm_big_kernel, cudaFuncAttributeMaxDynamicSharedMemorySize, SMEMBIG);

    // 1) prep (En/Xt + W splits + G build), one launch
    prep_all_kernel<<<296, 256>>>(x, Q, En, Xthi, Xtlo,
                                  W1, W1hi, W1lo, W2, W2hi, W2lo, W3, W3hi, W3lo, Gh);

    // 2) V = En .* (G @ Xt^T) - pos  -> single fp16
    vgemm_kernel<<<dim3(4, 4, 16), 256, SMEM64>>>(Gh, Xthi, Xtlo, En, x, Vh);

    // 3) layer 1
    gemm_big_kernel<<<dim3(NH/128, MROWS/256), 512, SMEMBIG>>>(
        Vh, W1hi, W1lo, b1, Y1, pS, pS2, VDIM, NH);
    bnstats_convert_kernel<<<dim3(4, 256), 256>>>(Y1, pS, pS2, g1, bt1, Axh);

    // 4) layer 2
    gemm_big_kernel<<<dim3(NH/128, MROWS/256), 512, SMEMBIG>>>(
        Axh, W2hi, W2lo, b2, Y2, pS, pS2, NH, NH);
    bnstats_convert_kernel<<<dim3(4, 256), 256>>>(Y2, pS, pS2, g2, bt2, Axh);

    // 5) layer 3 (64 partials)
    gemm_ps_kernel<<<dim3(NO/64, MROWS/128), 256, SMEM64>>>(
        Axh, W3hi, W3lo, b3, Y3, pS, pS2, NH, NO);

    // 6) stats finalize + BN apply -> out
    bnstats_apply_kernel<<<128, 256>>>(Y3, pS, pS2, g3, bt3, out);
}

// round 16
// speedup vs baseline: 1.6937x; 1.1444x over previous
#include <cuda_runtime.h>
#include <cuda_fp16.h>
#include <cstdint>
#include <math.h>

#define BATCH 16
#define SEQ   512
#define NI    32
#define NHEAD 8
#define NH    512
#define NO    64
#define MROWS (BATCH*SEQ)      // 8192
#define VDIM  (NHEAD*NI)       // 256
#define EPSV  1e-5f
#define SLOPE 0.05f
#define NPART 64

// ---------------- scratch ----------------
__device__ float    g_En  [16*8*512];
__device__ uint32_t g_Xthi[(size_t)16*256*256], g_Xtlo[(size_t)16*256*256];
__device__ uint32_t g_Gh  [(size_t)16*512*256];
__device__ uint32_t g_Vh  [(size_t)8192*128];
__device__ uint32_t g_W1h [512*128];            // single fp16
__device__ uint32_t g_W2h [512*256];            // single fp16
__device__ uint32_t g_W3hi[64*256], g_W3lo[64*256];   // pair (exact)
__device__ uint32_t g_Axh [(size_t)8192*256];
__device__ float g_Y1[(size_t)MROWS * NH];
__device__ float g_Y2[(size_t)MROWS * NH];
__device__ float g_Y3[(size_t)MROWS * NO];
__device__ float g_pS [NPART * NH];
__device__ float g_pS2[NPART * NH];
__device__ float g_scale[NH];
__device__ float g_shift[NH];

// ---------------- helpers ----------------
__device__ __forceinline__ void split_pair_h(float v0, float v1, uint32_t& hi, uint32_t& lo) {
    __half h0 = __float2half(v0);
    __half h1 = __float2half(v1);
    float r0 = v0 - __half2float(h0);
    float r1 = v1 - __half2float(h1);
    __half l0 = __float2half(r0);
    __half l1 = __float2half(r1);
    hi = ((uint32_t)__half_as_ushort(h1) << 16) | __half_as_ushort(h0);
    lo = ((uint32_t)__half_as_ushort(l1) << 16) | __half_as_ushort(l0);
}
__device__ __forceinline__ uint32_t pack_h(float v0, float v1) {
    __half h0 = __float2half(v0);
    __half h1 = __float2half(v1);
    return ((uint32_t)__half_as_ushort(h1) << 16) | __half_as_ushort(h0);
}

__device__ __forceinline__ void mma_f16(float* d, const uint32_t* a, const uint32_t* b) {
    asm volatile(
        "mma.sync.aligned.m16n8k16.row.col.f32.f16.f16.f32 "
        "{%0,%1,%2,%3}, {%4,%5,%6,%7}, {%8,%9}, {%0,%1,%2,%3};"
        : "+f"(d[0]), "+f"(d[1]), "+f"(d[2]), "+f"(d[3])
        : "r"(a[0]), "r"(a[1]), "r"(a[2]), "r"(a[3]), "r"(b[0]), "r"(b[1]));
}

__device__ __forceinline__ void ldsm4(uint32_t* r, uint32_t addr) {
    asm volatile("ldmatrix.sync.aligned.m8n8.x4.shared.b16 {%0,%1,%2,%3}, [%4];"
        : "=r"(r[0]), "=r"(r[1]), "=r"(r[2]), "=r"(r[3]) : "r"(addr));
}

__device__ __forceinline__ uint32_t smem_u32(const void* p) {
    uint32_t a;
    asm("{ .reg .u64 t; cvta.to.shared.u64 t, %1; cvt.u32.u64 %0, t; }" : "=r"(a) : "l"(p));
    return a;
}
__device__ __forceinline__ void cp_async16(uint32_t saddr, const void* gptr) {
    asm volatile("cp.async.cg.shared.global [%0], [%1], 16;" :: "r"(saddr), "l"(gptr));
}
#define CP_COMMIT() asm volatile("cp.async.commit_group;" ::: "memory")
#define CP_WAIT0()  asm volatile("cp.async.wait_group 0;" ::: "memory")

// ---------------- prep_all: En/Xt(hi,lo) + W converts + buildG(single) ----------------
__global__ void __launch_bounds__(256) prep_all_kernel(
    const float* __restrict__ x, const float* __restrict__ Q,
    float* __restrict__ En,
    uint32_t* __restrict__ Xthi, uint32_t* __restrict__ Xtlo,
    const float* __restrict__ W1, uint32_t* __restrict__ W1h,
    const float* __restrict__ W2, uint32_t* __restrict__ W2h,
    const float* __restrict__ W3, uint32_t* __restrict__ W3hi, uint32_t* __restrict__ W3lo,
    uint32_t* __restrict__ Gh)
{
    const int blk = blockIdx.x;
    const int tid = threadIdx.x;

    __shared__ float sEm[8][128];
    __shared__ float sQ[8][4];
    __shared__ uint32_t shi[256][8], slo[256][8];
    __shared__ float pn3[64][5];
    __shared__ float pm3[128][4];

    if (blk >= 168) {
        const int g  = blk - 168;
        const int b  = g >> 3, nt = g & 7;
        const int n = tid & 63, mq = tid >> 6;

        if (tid < 64) {
            const float* xp = x + ((size_t)b*512 + nt*64 + tid)*32;
            pn3[tid][0] = xp[0]; pn3[tid][1] = xp[1]; pn3[tid][2] = xp[2];
        }
        for (int mc = 0; mc < 4; mc++) {
            __syncthreads();
            if (tid < 128) {
                const float* xp = x + ((size_t)b*512 + mc*128 + tid)*32;
                pm3[tid][0] = xp[0]; pm3[tid][1] = xp[1]; pm3[tid][2] = xp[2];
            }
            __syncthreads();
            float px = pn3[n][0], py = pn3[n][1], pz = pn3[n][2];
            uint32_t outh[16];
            #pragma unroll
            for (int j = 0; j < 16; j++) {
                int ml = mq*32 + j*2;
                float dx0 = px - pm3[ml][0],   dy0 = py - pm3[ml][1],   dz0 = pz - pm3[ml][2];
                float dx1 = px - pm3[ml+1][0], dy1 = py - pm3[ml+1][1], dz1 = pz - pm3[ml+1][2];
                float e0 = __expf(-(dx0*dx0 + dy0*dy0 + dz0*dz0));
                float e1 = __expf(-(dx1*dx1 + dy1*dy1 + dz1*dz1));
                outh[j] = pack_h(e0, e1);
            }
            size_t base = ((size_t)b*512 + nt*64 + n)*256 + mc*64 + mq*16;
            #pragma unroll
            for (int j4 = 0; j4 < 4; j4++)
                ((uint4*)(Gh + base))[j4] = make_uint4(outh[j4*4], outh[j4*4+1], outh[j4*4+2], outh[j4*4+3]);
        }
        return;
    }

    if (blk >= 64) {
        int widx = blk - 64;
        if (widx < 32) {
            int p = widx * 2048 + tid;
            #pragma unroll
            for (int j = 0; j < 8; j++, p += 256) {
                float2 v = ((const float2*)W1)[p];
                W1h[p] = pack_h(v.x, v.y);
            }
        } else if (widx < 96) {
            int p = (widx - 32) * 2048 + tid;
            #pragma unroll
            for (int j = 0; j < 8; j++, p += 256) {
                float2 v = ((const float2*)W2)[p];
                W2h[p] = pack_h(v.x, v.y);
            }
        } else {
            int p = (widx - 96) * 2048 + tid;
            #pragma unroll
            for (int j = 0; j < 8; j++, p += 256) {
                float2 v = ((const float2*)W3)[p];
                uint32_t h, l; split_pair_h(v.x, v.y, h, l);
                W3hi[p] = h; W3lo[p] = l;
            }
        }
        return;
    }

    const int b = blk >> 2, chunk = blk & 3;

    if (tid < 8) {
        float a = Q[tid*3+0], bq = Q[tid*3+1], cq = Q[tid*3+2];
        sQ[tid][0] = a; sQ[tid][1] = bq; sQ[tid][2] = cq;
        sQ[tid][3] = a*a + bq*bq + cq*cq;
    }
    __syncthreads();

    if (tid < 128) {
        int m = chunk*128 + tid;
        const float* xp = x + ((size_t)b*512 + m)*32;
        float px = xp[0], py = xp[1], pz = xp[2];
        #pragma unroll
        for (int h = 0; h < 8; h++) {
            float dot = px*sQ[h][0] + py*sQ[h][1] + pz*sQ[h][2];
            float em = __expf(-2.f*dot);
            float en = __expf(2.f*dot - sQ[h][3]);
            sEm[h][tid] = em;
            En[((size_t)b*8 + h)*512 + m] = en;
        }
    }
    __syncthreads();

    const int c = tid, h = c >> 5, i = c & 31;
    for (int grp = 0; grp < 8; grp++) {
        #pragma unroll
        for (int j = 0; j < 8; j++) {
            int mloc = (grp*8 + j)*2;
            int m = chunk*128 + mloc;
            float v0 = sEm[h][mloc]   * x[((size_t)b*512 + m  )*32 + i];
            float v1 = sEm[h][mloc+1] * x[((size_t)b*512 + m+1)*32 + i];
            uint32_t hh, ll; split_pair_h(v0, v1, hh, ll);
            shi[c][j] = hh; slo[c][j] = ll;
        }
        __syncthreads();
        int cc = tid >> 3, j2 = tid & 7;
        #pragma unroll
        for (int rep = 0; rep < 8; rep++) {
            int ccc = cc + rep*32;
            size_t addr = ((size_t)b*256 + ccc)*256 + chunk*64 + grp*8 + j2;
            Xthi[addr] = shi[ccc][j2];
            Xtlo[addr] = slo[ccc][j2];
        }
        __syncthreads();
    }
}

// ================= GEMM machinery =================
#define RSU 20
#define TN  64
#define NFRAG (TN/16)
#define ASZ (128*RSU)
#define BSZ (TN*RSU)

// ---------------- vgemm: V = En .* (G @ Xt^T) - pos (A single, B pair) ----------------
__global__ void __launch_bounds__(256, 3) vgemm_kernel(
    const uint32_t* __restrict__ Gh_g,
    const uint32_t* __restrict__ Bhi_g, const uint32_t* __restrict__ Blo_g,
    const float* __restrict__ En, const float* __restrict__ x,
    uint32_t* __restrict__ Vh)
{
    constexpr int KE = 512, K2 = KE/2;
    extern __shared__ uint32_t smem_u[];
    const uint32_t sbase = smem_u32(smem_u);
    const uint32_t bA  = sbase;
    const uint32_t bBh = sbase + 2*ASZ*4;
    const uint32_t bBl = sbase + (2*ASZ + 2*BSZ)*4;

    const int tid = threadIdx.x, wid = tid >> 5, lane = tid & 31;
    const int wm = (wid >> 1) * 32, wn = (wid & 1) * (TN/2);
    const int l4 = lane >> 2, lk = lane & 3;
    const int rowA = lane & 15, colA = (lane >> 4) * 4;
    const int rowB = ((lane >> 4) & 1) * 8 + (lane & 7);
    const int colB = ((lane >> 3) & 1) * 4;
    const int b = blockIdx.z;
    const int m0 = blockIdx.y * 128, c0 = blockIdx.x * TN;

    const uint32_t* A_g  = Gh_g + (size_t)b*512*K2;
    const uint32_t* Bh_g = Bhi_g + (size_t)b*256*K2;
    const uint32_t* Bl_g = Blo_g + (size_t)b*256*K2;

    float acc[2][NFRAG][4];
    #pragma unroll
    for (int a = 0; a < 2; a++)
        #pragma unroll
        for (int q = 0; q < NFRAG; q++)
            { acc[a][q][0]=0.f; acc[a][q][1]=0.f; acc[a][q][2]=0.f; acc[a][q][3]=0.f; }

    auto issue = [&](int t) {
        int buf = t & 1;
        #pragma unroll
        for (int j = 0; j < 2; j++) {
            int lin = tid + j*256; int r = lin >> 2, q = lin & 3;
            uint32_t off = (uint32_t)(buf*ASZ + r*RSU + q*4) * 4;
            size_t ao = (size_t)(m0 + r)*K2 + t*16 + q*4;
            cp_async16(bA + off, A_g + ao);
        }
        {
            int r = tid >> 2, q = tid & 3;
            uint32_t off = (uint32_t)(buf*BSZ + r*RSU + q*4) * 4;
            size_t bo = (size_t)(c0 + r)*K2 + t*16 + q*4;
            cp_async16(bBh + off, Bh_g + bo);
            cp_async16(bBl + off, Bl_g + bo);
        }
        CP_COMMIT();
    };

    auto compute = [&](int buf) {
        #pragma unroll
        for (int kk = 0; kk < 2; kk++) {
            uint32_t ah[2][4];
            #pragma unroll
            for (int mi = 0; mi < 2; mi++) {
                uint32_t off = (uint32_t)(buf*ASZ + (wm + mi*16 + rowA)*RSU + kk*8 + colA) * 4;
                ldsm4(ah[mi], bA + off);
            }
            #pragma unroll
            for (int np = 0; np < NFRAG/2; np++) {
                uint32_t off = (uint32_t)(buf*BSZ + (wn + np*16 + rowB)*RSU + kk*8 + colB) * 4;
                uint32_t th[4], tl[4];
                ldsm4(th, bBh + off);
                ldsm4(tl, bBl + off);
                #pragma unroll
                for (int sub = 0; sub < 2; sub++) {
                    int ni = np*2 + sub;
                    uint32_t bhp[2] = {th[sub*2], th[sub*2+1]};
                    uint32_t blp[2] = {tl[sub*2], tl[sub*2+1]};
                    #pragma unroll
                    for (int mi = 0; mi < 2; mi++) {
                        mma_f16(acc[mi][ni], ah[mi], bhp);
                        mma_f16(acc[mi][ni], ah[mi], blp);
                    }
                }
            }
        }
    };

    const int T = KE / 32;
    issue(0);
    for (int t = 0; t < T; t++) {
        CP_WAIT0();
        __syncthreads();
        if (t + 1 < T) issue(t + 1);
        compute(t & 1);
    }

    #pragma unroll
    for (int mi = 0; mi < 2; mi++) {
        #pragma unroll
        for (int ni = 0; ni < NFRAG; ni++) {
            int n0 = m0 + wm + mi*16 + l4;
            int cc = c0 + wn + ni*8 + lk*2;
            int h = cc >> 5, il = cc & 31;
            float en0 = En[((size_t)b*8 + h)*512 + n0];
            float en1 = En[((size_t)b*8 + h)*512 + n0 + 8];
            float v00 = acc[mi][ni][0]*en0, v01 = acc[mi][ni][1]*en0;
            float v10 = acc[mi][ni][2]*en1, v11 = acc[mi][ni][3]*en1;
            if (il < 3) {
                v00 -= x[((size_t)b*512 + n0  )*32 + il];
                v10 -= x[((size_t)b*512 + n0+8)*32 + il];
            }
            if (il + 1 < 3) {
                v01 -= x[((size_t)b*512 + n0  )*32 + il + 1];
                v11 -= x[((size_t)b*512 + n0+8)*32 + il + 1];
            }
            size_t r0 = ((size_t)b*512 + n0)*128 + (cc >> 1);
            size_t r1 = ((size_t)b*512 + n0 + 8)*128 + (cc >> 1);
            Vh[r0] = pack_h(v00, v01);
            Vh[r1] = pack_h(v10, v11);
        }
    }
}

// ---------------- gemm_big: 512 threads, TM=256 x TNB=128, A+B single fp16 (1 MMA), fused stats ----------------
#define TNB  128
#define NFB  (TNB/16)
#define ASZB (256*RSU)
#define BSZB (128*RSU)

__global__ void __launch_bounds__(512, 1) gemm_big_kernel(
    const uint32_t* __restrict__ A_g,
    const uint32_t* __restrict__ Bh_g,
    const float* __restrict__ bias, float* __restrict__ Y,
    float* __restrict__ pS, float* __restrict__ pS2, int K, int C)
{
    extern __shared__ uint32_t smem_u[];
    const uint32_t sbase = smem_u32(smem_u);
    const uint32_t bA  = sbase;
    const uint32_t bBh = sbase + 2*ASZB*4;

    const int tid = threadIdx.x, wid = tid >> 5, lane = tid & 31;
    const int wm = (wid >> 1) * 32;
    const int wn = (wid & 1) * 64;
    const int mw = wid >> 1;
    const int l4 = lane >> 2, lk = lane & 3;
    const int rowA = lane & 15, colA = (lane >> 4) * 4;
    const int rowB = ((lane >> 4) & 1) * 8 + (lane & 7);
    const int colB = ((lane >> 3) & 1) * 4;
    const int m0 = blockIdx.y * 256, c0 = blockIdx.x * TNB;
    const int K2 = K >> 1;

    float acc[2][NFB][4];
    #pragma unroll
    for (int a = 0; a < 2; a++)
        #pragma unroll
        for (int q = 0; q < NFB; q++)
            { acc[a][q][0]=0.f; acc[a][q][1]=0.f; acc[a][q][2]=0.f; acc[a][q][3]=0.f; }

    auto issue = [&](int t) {
        int buf = t & 1;
        #pragma unroll
        for (int j = 0; j < 2; j++) {
            int lin = tid + j*512; int r = lin >> 2, q = lin & 3;
            uint32_t off = (uint32_t)(buf*ASZB + r*RSU + q*4) * 4;
            size_t ao = (size_t)(m0 + r)*K2 + t*16 + q*4;
            cp_async16(bA + off, A_g + ao);
        }
        {
            int r = tid >> 2, q = tid & 3;
            uint32_t off = (uint32_t)(buf*BSZB + r*RSU + q*4) * 4;
            size_t bo = (size_t)(c0 + r)*K2 + t*16 + q*4;
            cp_async16(bBh + off, Bh_g + bo);
        }
        CP_COMMIT();
    };

    auto compute = [&](int buf) {
        #pragma unroll
        for (int kk = 0; kk < 2; kk++) {
            uint32_t ah[2][4];
            #pragma unroll
            for (int mi = 0; mi < 2; mi++) {
                uint32_t off = (uint32_t)(buf*ASZB + (wm + mi*16 + rowA)*RSU + kk*8 + colA) * 4;
                ldsm4(ah[mi], bA + off);
            }
            #pragma unroll
            for (int np = 0; np < NFB/2; np++) {
                uint32_t off = (uint32_t)(buf*BSZB + (wn + np*16 + rowB)*RSU + kk*8 + colB) * 4;
                uint32_t th[4];
                ldsm4(th, bBh + off);
                #pragma unroll
                for (int sub = 0; sub < 2; sub++) {
                    int ni = np*2 + sub;
                    uint32_t bhp[2] = {th[sub*2], th[sub*2+1]};
                    #pragma unroll
                    for (int mi = 0; mi < 2; mi++)
                        mma_f16(acc[mi][ni], ah[mi], bhp);
                }
            }
        }
    };

    const int T = K / 32;
    issue(0);
    for (int t = 0; t < T; t++) {
        CP_WAIT0();
        __syncthreads();
        if (t + 1 < T) issue(t + 1);
        compute(t & 1);
    }
    __syncthreads();

    float* sbufS  = (float*)smem_u;
    float* sbufS2 = sbufS + 8*TNB;

    #pragma unroll
    for (int ni = 0; ni < NFB; ni++) {
        int col = c0 + wn + ni*8 + lk*2;
        float2 b2 = *(const float2*)(bias + col);
        float s0 = 0.f, s1 = 0.f, q0 = 0.f, q1 = 0.f;
        #pragma unroll
        for (int mi = 0; mi < 2; mi++) {
            int row = m0 + wm + mi*16 + l4;
            float e0 = acc[mi][ni][0] + b2.x;
            float e1 = acc[mi][ni][1] + b2.y;
            float e2 = acc[mi][ni][2] + b2.x;
            float e3 = acc[mi][ni][3] + b2.y;
            *(float2*)(Y + (size_t)row * C + col)       = make_float2(e0, e1);
            *(float2*)(Y + (size_t)(row + 8) * C + col) = make_float2(e2, e3);
            s0 += e0 + e2; s1 += e1 + e3;
            q0 += e0*e0 + e2*e2; q1 += e1*e1 + e3*e3;
        }
        #pragma unroll
        for (int off = 16; off >= 4; off >>= 1) {
            s0 += __shfl_down_sync(0xffffffffu, s0, off);
            s1 += __shfl_down_sync(0xffffffffu, s1, off);
            q0 += __shfl_down_sync(0xffffffffu, q0, off);
            q1 += __shfl_down_sync(0xffffffffu, q1, off);
        }
        if (lane < 4) {
            int cb = wn + ni*8 + lk*2;
            sbufS [mw*TNB + cb]     = s0;
            sbufS [mw*TNB + cb + 1] = s1;
            sbufS2[mw*TNB + cb]     = q0;
            sbufS2[mw*TNB + cb + 1] = q1;
        }
    }
    __syncthreads();
    if (tid < TNB) {
        float s = 0.f, q = 0.f;
        #pragma unroll
        for (int r = 0; r < 8; r++) { s += sbufS[r*TNB + tid]; q += sbufS2[r*TNB + tid]; }
        pS [blockIdx.y * C + c0 + tid] = s;
        pS2[blockIdx.y * C + c0 + tid] = q;
    }
}

// ---------------- gemm_ps (TN=64, A single, B pair) for layer 3 ----------------
__global__ void __launch_bounds__(256, 3) gemm_ps_kernel(
    const uint32_t* __restrict__ A_g,
    const uint32_t* __restrict__ Bh_g, const uint32_t* __restrict__ Bl_g,
    const float* __restrict__ bias, float* __restrict__ Y,
    float* __restrict__ pS, float* __restrict__ pS2, int K, int C)
{
    extern __shared__ uint32_t smem_u[];
    const uint32_t sbase = smem_u32(smem_u);
    const uint32_t bA  = sbase;
    const uint32_t bBh = sbase + 2*ASZ*4;
    const uint32_t bBl = sbase + (2*ASZ + 2*BSZ)*4;

    const int tid = threadIdx.x, wid = tid >> 5, lane = tid & 31;
    const int wm = (wid >> 1) * 32, wn = (wid & 1) * (TN/2);
    const int mw = wid >> 1;
    const int l4 = lane >> 2, lk = lane & 3;
    const int rowA = lane & 15, colA = (lane >> 4) * 4;
    const int rowB = ((lane >> 4) & 1) * 8 + (lane & 7);
    const int colB = ((lane >> 3) & 1) * 4;
    const int m0 = blockIdx.y * 128, c0 = blockIdx.x * TN;
    const int K2 = K >> 1;

    float acc[2][NFRAG][4];
    #pragma unroll
    for (int a = 0; a < 2; a++)
        #pragma unroll
        for (int q = 0; q < NFRAG; q++)
            { acc[a][q][0]=0.f; acc[a][q][1]=0.f; acc[a][q][2]=0.f; acc[a][q][3]=0.f; }

    auto issue = [&](int t) {
        int buf = t & 1;
        #pragma unroll
        for (int j = 0; j < 2; j++) {
            int lin = tid + j*256; int r = lin >> 2, q = lin & 3;
            uint32_t off = (uint32_t)(buf*ASZ + r*RSU + q*4) * 4;
            size_t ao = (size_t)(m0 + r)*K2 + t*16 + q*4;
            cp_async16(bA + off, A_g + ao);
        }
        {
            int r = tid >> 2, q = tid & 3;
            uint32_t off = (uint32_t)(buf*BSZ + r*RSU + q*4) * 4;
            size_t bo = (size_t)(c0 + r)*K2 + t*16 + q*4;
            cp_async16(bBh + off, Bh_g + bo);
            cp_async16(bBl + off, Bl_g + bo);
        }
        CP_COMMIT();
    };

    auto compute = [&](int buf) {
        #pragma unroll
        for (int kk = 0; kk < 2; kk++) {
            uint32_t ah[2][4];
            #pragma unroll
            for (int mi = 0; mi < 2; mi++) {
                uint32_t off = (uint32_t)(buf*ASZ + (wm + mi*16 + rowA)*RSU + kk*8 + colA) * 4;
                ldsm4(ah[mi], bA + off);
            }
            #pragma unroll
            for (int np = 0; np < NFRAG/2; np++) {
                uint32_t off = (uint32_t)(buf*BSZ + (wn + np*16 + rowB)*RSU + kk*8 + colB) * 4;
                uint32_t th[4], tl[4];
                ldsm4(th, bBh + off);
                ldsm4(tl, bBl + off);
                #pragma unroll
                for (int sub = 0; sub < 2; sub++) {
                    int ni = np*2 + sub;
                    uint32_t bhp[2] = {th[sub*2], th[sub*2+1]};
                    uint32_t blp[2] = {tl[sub*2], tl[sub*2+1]};
                    #pragma unroll
                    for (int mi = 0; mi < 2; mi++) {
                        mma_f16(acc[mi][ni], ah[mi], bhp);
                        mma_f16(acc[mi][ni], ah[mi], blp);
                    }
                }
            }
        }
    };

    const int T = K / 32;
    issue(0);
    for (int t = 0; t < T; t++) {
        CP_WAIT0();
        __syncthreads();
        if (t + 1 < T) issue(t + 1);
        compute(t & 1);
    }
    __syncthreads();

    float* sbufS  = (float*)smem_u;
    float* sbufS2 = sbufS + 4*TN;

    #pragma unroll
    for (int ni = 0; ni < NFRAG; ni++) {
        int col = c0 + wn + ni*8 + lk*2;
        float2 b2 = *(const float2*)(bias + col);
        float s0 = 0.f, s1 = 0.f, q0 = 0.f, q1 = 0.f;
        #pragma unroll
        for (int mi = 0; mi < 2; mi++) {
            int row = m0 + wm + mi*16 + l4;
            float e0 = acc[mi][ni][0] + b2.x;
            float e1 = acc[mi][ni][1] + b2.y;
            float e2 = acc[mi][ni][2] + b2.x;
            float e3 = acc[mi][ni][3] + b2.y;
            *(float2*)(Y + (size_t)row * C + col)       = make_float2(e0, e1);
            *(float2*)(Y + (size_t)(row + 8) * C + col) = make_float2(e2, e3);
            s0 += e0 + e2; s1 += e1 + e3;
            q0 += e0*e0 + e2*e2; q1 += e1*e1 + e3*e3;
        }
        #pragma unroll
        for (int off = 16; off >= 4; off >>= 1) {
            s0 += __shfl_down_sync(0xffffffffu, s0, off);
            s1 += __shfl_down_sync(0xffffffffu, s1, off);
            q0 += __shfl_down_sync(0xffffffffu, q0, off);
            q1 += __shfl_down_sync(0xffffffffu, q1, off);
        }
        if (lane < 4) {
            int cb = wn + ni*8 + lk*2;
            sbufS [mw*TN + cb]     = s0;
            sbufS [mw*TN + cb + 1] = s1;
            sbufS2[mw*TN + cb]     = q0;
            sbufS2[mw*TN + cb + 1] = q1;
        }
    }
    __syncthreads();
    if (tid < TN) {
        float s = sbufS [tid] + sbufS [TN + tid] + sbufS [2*TN + tid] + sbufS [3*TN + tid];
        float q = sbufS2[tid] + sbufS2[TN + tid] + sbufS2[2*TN + tid] + sbufS2[3*TN + tid];
        pS [blockIdx.y * C + c0 + tid] = s;
        pS2[blockIdx.y * C + c0 + tid] = q;
    }
}

// ---------------- stats_final: reduce partials -> scale/shift ----------------
__global__ void __launch_bounds__(256) stats_final_kernel(
    const float* __restrict__ pS, const float* __restrict__ pS2,
    const float* __restrict__ g, const float* __restrict__ bt,
    int M, int C, int npart, float* __restrict__ scale, float* __restrict__ shift)
{
    const int c = blockIdx.x * 8 + (threadIdx.x >> 5);
    const int j = threadIdx.x & 31;
    float s = 0.f, s2 = 0.f;
    for (int p = j; p < npart; p += 32) {
        s  += pS [p * C + c];
        s2 += pS2[p * C + c];
    }
    #pragma unroll
    for (int off = 16; off > 0; off >>= 1) {
        s  += __shfl_down_sync(0xffffffffu, s,  off);
        s2 += __shfl_down_sync(0xffffffffu, s2, off);
    }
    if (j == 0) {
        float invM = 1.f / (float)M;
        float mean = s * invM;
        float var  = fmaf(-mean, mean, s2 * invM);
        float inv  = rsqrtf(var + EPSV);
        float scv  = g[c] * inv;
        scale[c] = scv;
        shift[c] = fmaf(-mean, scv, bt[c]);
    }
}

// ---------------- bnconvert_h: pure-streaming BN + leaky -> single fp16 ----------------
__global__ void __launch_bounds__(256) bnconvert_h_kernel(
    const float* __restrict__ Y, const float* __restrict__ scale,
    const float* __restrict__ shift, uint32_t* __restrict__ Ah, int C4)
{
    int idx = blockIdx.x * blockDim.x + threadIdx.x;
    int c4 = idx & (C4 - 1);
    float4 y  = ((const float4*)Y)[idx];
    float4 sc = __ldg(&((const float4*)scale)[c4]);
    float4 sh = __ldg(&((const float4*)shift)[c4]);
    float v0 = fmaf(y.x, sc.x, sh.x);
    float v1 = fmaf(y.y, sc.y, sh.y);
    float v2 = fmaf(y.z, sc.z, sh.z);
    float v3 = fmaf(y.w, sc.w, sh.w);
    v0 = v0 > 0.f ? v0 : v0 * SLOPE;
    v1 = v1 > 0.f ? v1 : v1 * SLOPE;
    v2 = v2 > 0.f ? v2 : v2 * SLOPE;
    v3 = v3 > 0.f ? v3 : v3 * SLOPE;
    ((uint2*)Ah)[idx] = make_uint2(pack_h(v0, v1), pack_h(v2, v3));
}

// ---------------- bnstats_apply: stats finalize + BN -> out (C=64, 64 partials) ----------------
__global__ void __launch_bounds__(256) bnstats_apply_kernel(
    const float* __restrict__ Y, const float* __restrict__ pS, const float* __restrict__ pS2,
    const float* __restrict__ g, const float* __restrict__ bt, float* __restrict__ out)
{
    __shared__ float ssc[64], ssh[64];
    __shared__ float spart[4][2][64];
    const int tid = threadIdx.x;
    {
        int cl = tid & 63, quad = tid >> 6;
        float s = 0.f, q = 0.f;
        #pragma unroll
        for (int p = quad*16; p < quad*16 + 16; p++) {
            s += pS [p*64 + cl];
            q += pS2[p*64 + cl];
        }
        spart[quad][0][cl] = s;
        spart[quad][1][cl] = q;
    }
    __syncthreads();
    if (tid < 64) {
        float s = spart[0][0][tid] + spart[1][0][tid] + spart[2][0][tid] + spart[3][0][tid];
        float q = spart[0][1][tid] + spart[1][1][tid] + spart[2][1][tid] + spart[3][1][tid];
        float mean = s * (1.f/8192.f);
        float var  = fmaf(-mean, mean, q * (1.f/8192.f));
        float inv  = rsqrtf(var + EPSV);
        float scv  = g[tid] * inv;
        ssc[tid] = scv;
        ssh[tid] = fmaf(-mean, scv, bt[tid]);
    }
    __syncthreads();

    size_t base = (size_t)blockIdx.x * 1024;
    #pragma unroll
    for (int it = 0; it < 4; it++) {
        int idx = it*256 + tid;
        int c4 = idx & 15;
        float4 y  = ((const float4*)Y)[base + idx];
        float4 sc = ((const float4*)ssc)[c4];
        float4 sh = ((const float4*)ssh)[c4];
        float4 o;
        o.x = fmaf(y.x, sc.x, sh.x);
        o.y = fmaf(y.y, sc.y, sh.y);
        o.z = fmaf(y.z, sc.z, sh.z);
        o.w = fmaf(y.w, sc.w, sh.w);
        ((float4*)out)[base + idx] = o;
    }
}

// ---------------- host ----------------
extern "C" void kernel_launch(void* const* d_in, const int* in_sizes, int n_in,
                              void* d_out, int out_size)
{
    const float* x   = (const float*)d_in[0];
    const float* Q   = (const float*)d_in[1];
    const float* W1  = (const float*)d_in[2];
    const float* b1  = (const float*)d_in[3];
    const float* g1  = (const float*)d_in[4];
    const float* bt1 = (const float*)d_in[5];
    const float* W2  = (const float*)d_in[6];
    const float* b2  = (const float*)d_in[7];
    const float* g2  = (const float*)d_in[8];
    const float* bt2 = (const float*)d_in[9];
    const float* W3  = (const float*)d_in[10];
    const float* b3  = (const float*)d_in[11];
    const float* g3  = (const float*)d_in[12];
    const float* bt3 = (const float*)d_in[13];
    float* out = (float*)d_out;

    float *En, *Y1, *Y2, *Y3, *pS, *pS2, *scale, *shift;
    uint32_t *Xthi, *Xtlo, *Gh, *Vh, *Axh;
    uint32_t *W1h, *W2h, *W3hi, *W3lo;
    cudaGetSymbolAddress((void**)&En,   g_En);
    cudaGetSymbolAddress((void**)&Xthi, g_Xthi);  cudaGetSymbolAddress((void**)&Xtlo, g_Xtlo);
    cudaGetSymbolAddress((void**)&Gh,   g_Gh);
    cudaGetSymbolAddress((void**)&Vh,   g_Vh);
    cudaGetSymbolAddress((void**)&Axh,  g_Axh);
    cudaGetSymbolAddress((void**)&W1h,  g_W1h);
    cudaGetSymbolAddress((void**)&W2h,  g_W2h);
    cudaGetSymbolAddress((void**)&W3hi, g_W3hi);  cudaGetSymbolAddress((void**)&W3lo, g_W3lo);
    cudaGetSymbolAddress((void**)&Y1, g_Y1);
    cudaGetSymbolAddress((void**)&Y2, g_Y2);
    cudaGetSymbolAddress((void**)&Y3, g_Y3);
    cudaGetSymbolAddress((void**)&pS, g_pS);      cudaGetSymbolAddress((void**)&pS2, g_pS2);
    cudaGetSymbolAddress((void**)&scale, g_scale); cudaGetSymbolAddress((void**)&shift, g_shift);

    const int SMEM64  = (2*ASZ  + 4*BSZ ) * 4;   // 40960 B (A single + B pair)
    const int SMEMBIG = (2*ASZB + 2*BSZB) * 4;   // 61440 B (A single + B single)
    cudaFuncSetAttribute(vgemm_kernel,    cudaFuncAttributeMaxDynamicSharedMemorySize, SMEM64);
    cudaFuncSetAttribute(gemm_ps_kernel,  cudaFuncAttributeMaxDynamicSharedMemorySize, SMEM64);
    cudaFuncSetAttribute(gemm_big_kernel, cudaFuncAttributeMaxDynamicSharedMemorySize, SMEMBIG);

    // 1) prep (En/Xt + W converts + G build)
    prep_all_kernel<<<296, 256>>>(x, Q, En, Xthi, Xtlo,
                                  W1, W1h, W2, W2h, W3, W3hi, W3lo, Gh);

    // 2) V = En .* (G @ Xt^T) - pos  -> single fp16
    vgemm_kernel<<<dim3(4, 4, 16), 256, SMEM64>>>(Gh, Xthi, Xtlo, En, x, Vh);

    // 3) layer 1 (A,B single fp16; 32 stats partials)
    gemm_big_kernel<<<dim3(NH/128, MROWS/256), 512, SMEMBIG>>>(
        Vh, W1h, b1, Y1, pS, pS2, VDIM, NH);
    stats_final_kernel<<<NH/8, 256>>>(pS, pS2, g1, bt1, MROWS, NH, 32, scale, shift);
    bnconvert_h_kernel<<<MROWS*NH/4/256, 256>>>(Y1, scale, shift, Axh, NH/4);

    // 4) layer 2
    gemm_big_kernel<<<dim3(NH/128, MROWS/256), 512, SMEMBIG>>>(
        Axh, W2h, b2, Y2, pS, pS2, NH, NH);
    stats_final_kernel<<<NH/8, 256>>>(pS, pS2, g2, bt2, MROWS, NH, 32, scale, shift);
    bnconvert_h_kernel<<<MROWS*NH/4/256, 256>>>(Y2, scale, shift, Axh, NH/4);

    // 5) layer 3 (B pair, 64 partials)
    gemm_ps_kernel<<<dim3(NO/64, MROWS/128), 256, SMEM64>>>(
        Axh, W3hi, W3lo, b3, Y3, pS, pS2, NH, NO);

    // 6) stats finalize + BN apply -> out
    bnstats_apply_kernel<<<128, 256>>>(Y3, pS, pS2, g3, bt3, out);
}